// round 8
// baseline (speedup 1.0000x reference)
#include <cuda_runtime.h>
#include <cuda_bf16.h>
#include <math.h>
#include <stdint.h>

#define TB 4
#define TT 1024
#define TC 1024
#define TH 16
#define THD 64
#define MR (TB*TT)          // 4096 rows
#define N3C (3*TC)          // 3072

// ---------------- scratch (allocation-free rule: device globals) -----------
static __device__ __nv_bfloat16 g_qkvhi[(size_t)MR * N3C];   // 24 MB
static __device__ __nv_bfloat16 g_qkvlo[(size_t)MR * N3C];   // 24 MB
static __device__ __nv_bfloat16 g_xhi[(size_t)MR * TC];
static __device__ __nv_bfloat16 g_xlo[(size_t)MR * TC];
static __device__ __nv_bfloat16 g_wqkv_hi[(size_t)N3C * TC];   // W^T [3072,1024]
static __device__ __nv_bfloat16 g_wqkv_lo[(size_t)N3C * TC];
static __device__ __nv_bfloat16 g_wpr_hi[(size_t)TC * TC];     // W^T [1024,1024]
static __device__ __nv_bfloat16 g_wpr_lo[(size_t)TC * TC];
static __device__ __nv_bfloat16 g_yhi[(size_t)MR * TC];
static __device__ __nv_bfloat16 g_ylo[(size_t)MR * TC];

// ---------------- PTX helpers (baseline ISA only) ---------------------------
__device__ __forceinline__ uint32_t smem_u32(const void* p) {
    uint32_t a;
    asm("{ .reg .u64 t; cvta.to.shared.u64 t, %1; cvt.u32.u64 %0, t; }" : "=r"(a) : "l"(p));
    return a;
}
__device__ __forceinline__ void ldsm_x4(uint32_t (&r)[4], uint32_t addr) {
    asm volatile("ldmatrix.sync.aligned.m8n8.x4.shared.b16 {%0,%1,%2,%3}, [%4];"
        : "=r"(r[0]), "=r"(r[1]), "=r"(r[2]), "=r"(r[3]) : "r"(addr));
}
__device__ __forceinline__ void ldsm_x4t(uint32_t (&r)[4], uint32_t addr) {
    asm volatile("ldmatrix.sync.aligned.m8n8.x4.trans.shared.b16 {%0,%1,%2,%3}, [%4];"
        : "=r"(r[0]), "=r"(r[1]), "=r"(r[2]), "=r"(r[3]) : "r"(addr));
}
__device__ __forceinline__ void mma_bf16(float (&d)[4], const uint32_t (&a)[4],
                                         uint32_t b0, uint32_t b1) {
    asm volatile("mma.sync.aligned.m16n8k16.row.col.f32.bf16.bf16.f32 "
        "{%0,%1,%2,%3}, {%4,%5,%6,%7}, {%8,%9}, {%0,%1,%2,%3};"
        : "+f"(d[0]), "+f"(d[1]), "+f"(d[2]), "+f"(d[3])
        : "r"(a[0]), "r"(a[1]), "r"(a[2]), "r"(a[3]), "r"(b0), "r"(b1));
}
__device__ __forceinline__ void cp_async16(uint32_t dst, const void* src) {
    asm volatile("cp.async.cg.shared.global [%0], [%1], 16;" :: "r"(dst), "l"(src) : "memory");
}
#define CP_COMMIT() asm volatile("cp.async.commit_group;" ::: "memory")
#define CP_WAIT1()  asm volatile("cp.async.wait_group 1;" ::: "memory")
#define CP_WAIT0()  asm volatile("cp.async.wait_group 0;" ::: "memory")

// smem tile geometry for GEMM: 128 rows x 40 bf16 (32 data + 8 pad)
#define TROW 40
#define TILE_ELEMS (128*TROW)
#define STAGE_ELEMS (4*TILE_ELEMS)
#define GEMM_SMEM (2*STAGE_ELEMS*2)   // 2 stages, bytes

// ---------------------------------------------------------------------------
// Split-bf16 tensor-core GEMM. Same math as R7 but mma issue order breaks
// same-accumulator chains: B fragments loaded for PAIRS of 16-wide n-tiles,
// then products emitted prod -> pair -> half -> mt (same-acc distance 8).
// out_mode: 0 -> fp32 C, 1 -> bf16 hi/lo pair (Chi, Clo).
// ---------------------------------------------------------------------------
__global__ __launch_bounds__(256, 2) void gemm_mma(
    const __nv_bfloat16* __restrict__ Ahi, const __nv_bfloat16* __restrict__ Alo,
    const __nv_bfloat16* __restrict__ Bhi, const __nv_bfloat16* __restrict__ Blo,
    float* __restrict__ C, __nv_bfloat16* __restrict__ Chi,
    __nv_bfloat16* __restrict__ Clo, int out_mode, int M, int N, int K)
{
    extern __shared__ __nv_bfloat16 smem[];

    const int t = threadIdx.x, lane = t & 31, wid = t >> 5;
    const int wm = wid & 3, wn = wid >> 2;
    const int bm = blockIdx.y * 128, bn = blockIdx.x * 128;

    float acc[2][8][4];
    #pragma unroll
    for (int i = 0; i < 2; i++)
        #pragma unroll
        for (int j = 0; j < 8; j++)
            #pragma unroll
            for (int k = 0; k < 4; k++) acc[i][j][k] = 0.f;

    // staging: 512 16B chunks per tile, 2 ADJACENT per thread
    const int r0 = t >> 1;
    const int cc0 = (t & 1) * 16;           // two 8-elem chunks: cc0, cc0+8
    const __nv_bfloat16* g0[4];
    g0[0] = Ahi + (size_t)(bm + r0) * K + cc0;
    g0[1] = Alo + (size_t)(bm + r0) * K + cc0;
    g0[2] = Bhi + (size_t)(bn + r0) * K + cc0;
    g0[3] = Blo + (size_t)(bn + r0) * K + cc0;
    uint32_t s0[4];
    #pragma unroll
    for (int w = 0; w < 4; w++)
        s0[w] = smem_u32(smem + w * TILE_ELEMS + r0 * TROW + cc0);
    const uint32_t stage_bytes = STAGE_ELEMS * 2;

    const int a_row = wm * 32 + (lane & 15);
    const int a_coff = (lane >> 4) * 8;
    const int b_row = wn * 64 + (lane & 7) + ((lane >> 4) & 1) * 8;
    const int b_coff = ((lane >> 3) & 1) * 8;

    const int niter = K >> 5;

    #pragma unroll
    for (int w = 0; w < 4; w++) { cp_async16(s0[w], g0[w]); cp_async16(s0[w] + 16, g0[w] + 8); }
    CP_COMMIT();

    for (int it = 0; it < niter; it++) {
        if (it + 1 < niter) {
            const int kn = (it + 1) << 5;
            const uint32_t soff = ((it + 1) & 1) * stage_bytes;
            #pragma unroll
            for (int w = 0; w < 4; w++) {
                cp_async16(s0[w] + soff, g0[w] + kn);
                cp_async16(s0[w] + soff + 16, g0[w] + kn + 8);
            }
            CP_COMMIT();
            CP_WAIT1();
        } else {
            CP_WAIT0();
        }
        __syncthreads();

        const __nv_bfloat16* bs = smem + (it & 1) * STAGE_ELEMS;
        #pragma unroll
        for (int ks = 0; ks < 2; ks++) {
            uint32_t ah[2][4], al[2][4];
            #pragma unroll
            for (int mt = 0; mt < 2; mt++) {
                ldsm_x4(ah[mt], smem_u32(bs + (a_row + mt*16) * TROW + ks*16 + a_coff));
                ldsm_x4(al[mt], smem_u32(bs + TILE_ELEMS + (a_row + mt*16) * TROW + ks*16 + a_coff));
            }
            #pragma unroll
            for (int npp = 0; npp < 2; npp++) {       // pairs of 16-wide n tiles
                uint32_t bh2[2][4], bl2[2][4];
                #pragma unroll
                for (int j = 0; j < 2; j++) {
                    const int np = npp*2 + j;
                    ldsm_x4(bh2[j], smem_u32(bs + 2*TILE_ELEMS + (b_row + np*16) * TROW + ks*16 + b_coff));
                    ldsm_x4(bl2[j], smem_u32(bs + 3*TILE_ELEMS + (b_row + np*16) * TROW + ks*16 + b_coff));
                }
                // product-major order: same-acc distance = 8 mmas
                #pragma unroll
                for (int prod = 0; prod < 3; prod++) {
                    #pragma unroll
                    for (int j = 0; j < 2; j++) {
                        #pragma unroll
                        for (int half = 0; half < 2; half++) {
                            const int nt = (npp*2 + j)*2 + half;
                            #pragma unroll
                            for (int mt = 0; mt < 2; mt++) {
                                const uint32_t (&af)[4] = (prod == 2) ? al[mt] : ah[mt];
                                const uint32_t* bf = (prod == 1) ? bl2[j] : bh2[j];
                                mma_bf16(acc[mt][nt], af, bf[2*half], bf[2*half+1]);
                            }
                        }
                    }
                }
            }
        }
        __syncthreads();
    }

    const int g = lane >> 2, tq = lane & 3;
    #pragma unroll
    for (int mt = 0; mt < 2; mt++) {
        const int row = bm + wm*32 + mt*16 + g;
        #pragma unroll
        for (int nt = 0; nt < 8; nt++) {
            const int col = bn + wn*64 + nt*8 + 2*tq;
            if (out_mode == 0) {
                *(float2*)(C + (size_t)row * N + col) =
                    make_float2(acc[mt][nt][0], acc[mt][nt][1]);
                *(float2*)(C + (size_t)(row + 8) * N + col) =
                    make_float2(acc[mt][nt][2], acc[mt][nt][3]);
            } else {
                #pragma unroll
                for (int rr = 0; rr < 2; rr++) {
                    const float v0 = acc[mt][nt][2*rr], v1 = acc[mt][nt][2*rr+1];
                    const __nv_bfloat16 h0 = __float2bfloat16(v0);
                    const __nv_bfloat16 h1 = __float2bfloat16(v1);
                    const __nv_bfloat16 l0 = __float2bfloat16(v0 - __bfloat162float(h0));
                    const __nv_bfloat16 l1 = __float2bfloat16(v1 - __bfloat162float(h1));
                    const size_t off = (size_t)(row + 8*rr) * N + col;
                    *(__nv_bfloat162*)(Chi + off) = __halves2bfloat162(h0, h1);
                    *(__nv_bfloat162*)(Clo + off) = __halves2bfloat162(l0, l1);
                }
            }
        }
    }
}

// ---------------------------------------------------------------------------
// fp32 -> (hi, lo) bf16, elementwise.
// ---------------------------------------------------------------------------
__global__ void convert_hilo(const float4* __restrict__ in,
                             __nv_bfloat162* __restrict__ hi,
                             __nv_bfloat162* __restrict__ lo, int n4)
{
    int i = blockIdx.x * blockDim.x + threadIdx.x;
    if (i >= n4) return;
    float4 v = in[i];
    __nv_bfloat16 h0 = __float2bfloat16(v.x), h1 = __float2bfloat16(v.y);
    __nv_bfloat16 h2 = __float2bfloat16(v.z), h3 = __float2bfloat16(v.w);
    __nv_bfloat16 l0 = __float2bfloat16(v.x - __bfloat162float(h0));
    __nv_bfloat16 l1 = __float2bfloat16(v.y - __bfloat162float(h1));
    __nv_bfloat16 l2 = __float2bfloat16(v.z - __bfloat162float(h2));
    __nv_bfloat16 l3 = __float2bfloat16(v.w - __bfloat162float(h3));
    hi[2*i]   = __halves2bfloat162(h0, h1);
    hi[2*i+1] = __halves2bfloat162(h2, h3);
    lo[2*i]   = __halves2bfloat162(l0, l1);
    lo[2*i+1] = __halves2bfloat162(l2, l3);
}

// ---------------------------------------------------------------------------
// Both W transposes in ONE launch. blocks with x < 96 handle Wqkv (N=3072),
// else Wproj (N=1024). K=1024 for both.
// ---------------------------------------------------------------------------
__global__ void transpose_hilo2(const float* __restrict__ Wq,
                                __nv_bfloat16* __restrict__ Tqh,
                                __nv_bfloat16* __restrict__ Tql,
                                const float* __restrict__ Wp,
                                __nv_bfloat16* __restrict__ Tph,
                                __nv_bfloat16* __restrict__ Tpl)
{
    __shared__ float tile[32][33];
    const bool isq = blockIdx.x < (N3C/32);
    const int bx = isq ? blockIdx.x : blockIdx.x - (N3C/32);
    const int N = isq ? N3C : TC;
    const float* W = isq ? Wq : Wp;
    __nv_bfloat16* Thi = isq ? Tqh : Tph;
    __nv_bfloat16* Tlo = isq ? Tql : Tpl;
    const int n0 = bx * 32, k0 = blockIdx.y * 32;
    const int tx = threadIdx.x, ty = threadIdx.y;
    #pragma unroll
    for (int j = 0; j < 4; j++)
        tile[ty + 8*j][tx] = W[(size_t)(k0 + ty + 8*j) * N + n0 + tx];
    __syncthreads();
    #pragma unroll
    for (int j = 0; j < 4; j++) {
        float v = tile[tx][ty + 8*j];
        __nv_bfloat16 h = __float2bfloat16(v);
        size_t o = (size_t)(n0 + ty + 8*j) * TC + k0 + tx;
        Thi[o] = h;
        Tlo[o] = __float2bfloat16(v - __bfloat162float(h));
    }
}

// ---------------------------------------------------------------------------
// Tensor-core flash attention (R7) with chain-broken mma ordering.
// ---------------------------------------------------------------------------
#define ASQ 72
#define ATILE (64*ASQ)
#define ATTN_SMEM (6*ATILE*2)

__global__ __launch_bounds__(128) void attn_mma(
    const __nv_bfloat16* __restrict__ qkvhi, const __nv_bfloat16* __restrict__ qkvlo,
    const float* __restrict__ span_params, const float* __restrict__ stride_params,
    __nv_bfloat16* __restrict__ yhi, __nv_bfloat16* __restrict__ ylo)
{
    extern __shared__ __nv_bfloat16 sm[];
    __nv_bfloat16* Qh = sm;
    __nv_bfloat16* Ql = sm + ATILE;
    __nv_bfloat16* Kh = sm + 2*ATILE;
    __nv_bfloat16* Kl = sm + 3*ATILE;
    __nv_bfloat16* Vh = sm + 4*ATILE;
    __nv_bfloat16* Vl = sm + 5*ATILE;

    const int qt = blockIdx.x, h = blockIdx.y, b = blockIdx.z;
    const int t = threadIdx.x, lane = t & 31, w = t >> 5;
    const int i0 = qt * 64;

    const float sp = 1024.f / (1.f + __expf(-span_params[h]));
    const float p0 = stride_params[2*h], p1 = stride_params[2*h + 1];
    const float mxp = fmaxf(p0, p1);
    const float e0 = __expf(p0 - mxp), e1 = __expf(p1 - mxp);
    const float sw0 = e0 / (e0 + e1), sw1 = e1 / (e0 + e1);
    const float c1 = 32.f + sp;

    const int lr = t >> 1, lc = (t & 1) * 32;
    {
        const size_t gq = (size_t)(b*TT + i0 + lr) * N3C + h*THD + lc;
        #pragma unroll
        for (int i = 0; i < 4; i++) {
            *(uint4*)(Qh + lr*ASQ + lc + i*8) = *(const uint4*)(qkvhi + gq + i*8);
            *(uint4*)(Ql + lr*ASQ + lc + i*8) = *(const uint4*)(qkvlo + gq + i*8);
        }
    }
    __syncthreads();

    uint32_t qfh[4][4], qfl[4][4];
    {
        const int a_row = w*16 + (lane & 15);
        const int a_coff = (lane >> 4) * 8;
        #pragma unroll
        for (int ks = 0; ks < 4; ks++) {
            ldsm_x4(qfh[ks], smem_u32(Qh + a_row*ASQ + ks*16 + a_coff));
            ldsm_x4(qfl[ks], smem_u32(Ql + a_row*ASQ + ks*16 + a_coff));
        }
    }

    float accy[8][4];
    #pragma unroll
    for (int i = 0; i < 8; i++)
        #pragma unroll
        for (int j = 0; j < 4; j++) accy[i][j] = 0.f;
    float rs0 = 0.f, rs1 = 0.f;

    const int g = lane >> 2, tq2 = (lane & 3) * 2;
    const int q0 = i0 + w*16 + g;
    const int kb_row = (lane & 7) + ((lane >> 4) & 1) * 8;
    const int kb_coff = ((lane >> 3) & 1) * 8;
    const int vb_row = (lane & 7) + ((lane >> 3) & 1) * 8;
    const int vb_coff = (lane >> 4) * 8;

    int jt0 = (int)floorf(((float)i0 - 95.f - sp) * (1.f / 64.f)) + 1;
    if (jt0 < 0) jt0 = 0;

    for (int jt = jt0; jt <= qt; jt++) {
        __syncthreads();
        {
            const size_t gk = (size_t)(b*TT + jt*64 + lr) * N3C + TC   + h*THD + lc;
            const size_t gv = (size_t)(b*TT + jt*64 + lr) * N3C + 2*TC + h*THD + lc;
            #pragma unroll
            for (int i = 0; i < 4; i++) {
                *(uint4*)(Kh + lr*ASQ + lc + i*8) = *(const uint4*)(qkvhi + gk + i*8);
                *(uint4*)(Kl + lr*ASQ + lc + i*8) = *(const uint4*)(qkvlo + gk + i*8);
                *(uint4*)(Vh + lr*ASQ + lc + i*8) = *(const uint4*)(qkvhi + gv + i*8);
                *(uint4*)(Vl + lr*ASQ + lc + i*8) = *(const uint4*)(qkvlo + gv + i*8);
            }
        }
        __syncthreads();

        // ---- S = Q K^T, chain-broken: pairs of n-tiles, product-major ----
        float s[8][4];
        #pragma unroll
        for (int i = 0; i < 8; i++)
            #pragma unroll
            for (int j = 0; j < 4; j++) s[i][j] = 0.f;
        #pragma unroll
        for (int ks = 0; ks < 4; ks++) {
            #pragma unroll
            for (int npp = 0; npp < 2; npp++) {
                uint32_t bh2[2][4], bl2[2][4];
                #pragma unroll
                for (int j = 0; j < 2; j++) {
                    const int np = npp*2 + j;
                    ldsm_x4(bh2[j], smem_u32(Kh + (np*16 + kb_row)*ASQ + ks*16 + kb_coff));
                    ldsm_x4(bl2[j], smem_u32(Kl + (np*16 + kb_row)*ASQ + ks*16 + kb_coff));
                }
                #pragma unroll
                for (int prod = 0; prod < 3; prod++) {
                    #pragma unroll
                    for (int j = 0; j < 2; j++) {
                        #pragma unroll
                        for (int half = 0; half < 2; half++) {
                            const int nf = (npp*2 + j)*2 + half;
                            const uint32_t (&af)[4] = (prod == 2) ? qfl[ks] : qfh[ks];
                            const uint32_t* bf = (prod == 1) ? bl2[j] : bh2[j];
                            mma_bf16(s[nf], af, bf[2*half], bf[2*half+1]);
                        }
                    }
                }
            }
        }

        // ---- mask + exp + rowsum + pack P (hi/lo) ----
        uint32_t pfh[4][4], pfl[4][4];
        #pragma unroll
        for (int nf = 0; nf < 8; nf++) {
            const int kk = jt*64 + nf*8 + tq2;
            float pv[4];
            #pragma unroll
            for (int e = 0; e < 4; e++) {
                const int qq = q0 + (e >> 1) * 8;
                const int kc = kk + (e & 1);
                const int rel = qq - kc;
                float p = 0.f;
                if (rel >= 0) {
                    float clip = fminf(fmaxf((c1 - (float)rel) * 0.03125f, 0.f), 1.f);
                    float mk = clip * (sw0 + (((rel & 1) == 0) ? sw1 : 0.f));
                    p = __expf(s[nf][e] * 0.125f) * mk;
                }
                pv[e] = p;
            }
            rs0 += pv[0] + pv[1];
            rs1 += pv[2] + pv[3];
            __nv_bfloat16 hh[4], ll[4];
            #pragma unroll
            for (int e = 0; e < 4; e++) {
                hh[e] = __float2bfloat16(pv[e]);
                ll[e] = __float2bfloat16(pv[e] - __bfloat162float(hh[e]));
            }
            const int j = nf >> 1, odd = nf & 1;
            uint32_t ph01, ph23, pl01, pl23;
            memcpy(&ph01, &hh[0], 4); memcpy(&ph23, &hh[2], 4);
            memcpy(&pl01, &ll[0], 4); memcpy(&pl23, &ll[2], 4);
            pfh[j][2*odd]   = ph01;  pfh[j][2*odd+1] = ph23;
            pfl[j][2*odd]   = pl01;  pfl[j][2*odd+1] = pl23;
        }

        // ---- Y += P V, chain-broken: pairs of d-tiles, product-major ----
        #pragma unroll
        for (int ks = 0; ks < 4; ks++) {
            #pragma unroll
            for (int dpp = 0; dpp < 2; dpp++) {
                uint32_t vh2[2][4], vl2[2][4];
                #pragma unroll
                for (int j = 0; j < 2; j++) {
                    const int dnp = dpp*2 + j;
                    ldsm_x4t(vh2[j], smem_u32(Vh + (ks*16 + vb_row)*ASQ + dnp*16 + vb_coff));
                    ldsm_x4t(vl2[j], smem_u32(Vl + (ks*16 + vb_row)*ASQ + dnp*16 + vb_coff));
                }
                #pragma unroll
                for (int prod = 0; prod < 3; prod++) {
                    #pragma unroll
                    for (int j = 0; j < 2; j++) {
                        #pragma unroll
                        for (int half = 0; half < 2; half++) {
                            const int df = (dpp*2 + j)*2 + half;
                            const uint32_t (&af)[4] = (prod == 2) ? pfl[ks] : pfh[ks];
                            const uint32_t* bf = (prod == 1) ? vl2[j] : vh2[j];
                            mma_bf16(accy[df], af, bf[2*half], bf[2*half+1]);
                        }
                    }
                }
            }
        }
    }

    rs0 += __shfl_xor_sync(0xffffffffu, rs0, 1);
    rs0 += __shfl_xor_sync(0xffffffffu, rs0, 2);
    rs1 += __shfl_xor_sync(0xffffffffu, rs1, 1);
    rs1 += __shfl_xor_sync(0xffffffffu, rs1, 2);
    const float inv0 = 1.f / rs0, inv1 = 1.f / rs1;

    const size_t row0 = (size_t)(b*TT + i0 + w*16 + g);
    #pragma unroll
    for (int df = 0; df < 8; df++) {
        const int col = h*THD + df*8 + tq2;
        #pragma unroll
        for (int rr = 0; rr < 2; rr++) {
            const float inv = rr ? inv1 : inv0;
            const float v0 = accy[df][2*rr] * inv, v1 = accy[df][2*rr+1] * inv;
            const __nv_bfloat16 h0 = __float2bfloat16(v0);
            const __nv_bfloat16 h1 = __float2bfloat16(v1);
            const __nv_bfloat16 l0 = __float2bfloat16(v0 - __bfloat162float(h0));
            const __nv_bfloat16 l1 = __float2bfloat16(v1 - __bfloat162float(h1));
            const size_t off = (row0 + 8*rr) * TC + col;
            *(__nv_bfloat162*)(yhi + off) = __halves2bfloat162(h0, h1);
            *(__nv_bfloat162*)(ylo + off) = __halves2bfloat162(l0, l1);
        }
    }
}

// ---------------------------------------------------------------------------
__global__ void tail_kernel(const float* __restrict__ span_params,
                            float* __restrict__ out, int out_size)
{
    if (threadIdx.x == 0 && blockIdx.x == 0) {
        float s = 0.f;
        for (int i = 0; i < TH; i++)
            s += 1024.f / (1.f + expf(-span_params[i]));
        if (out_size > MR * TC)
            out[MR * TC] = 2e-6f * s / 16.f;
    }
}

extern "C" void kernel_launch(void* const* d_in, const int* in_sizes, int n_in,
                              void* d_out, int out_size)
{
    const float* x    = (const float*)d_in[0];
    const float* Wqkv = (const float*)d_in[1];
    const float* Wpr  = (const float*)d_in[2];
    const float* span = (const float*)d_in[3];
    const float* strd = (const float*)d_in[4];
    float* out = (float*)d_out;

    __nv_bfloat16 *qkvhi, *qkvlo, *xhi, *xlo, *wqh, *wql, *wph, *wpl, *yhi, *ylo;
    cudaGetSymbolAddress((void**)&qkvhi, g_qkvhi);
    cudaGetSymbolAddress((void**)&qkvlo, g_qkvlo);
    cudaGetSymbolAddress((void**)&xhi, g_xhi);
    cudaGetSymbolAddress((void**)&xlo, g_xlo);
    cudaGetSymbolAddress((void**)&wqh, g_wqkv_hi);
    cudaGetSymbolAddress((void**)&wql, g_wqkv_lo);
    cudaGetSymbolAddress((void**)&wph, g_wpr_hi);
    cudaGetSymbolAddress((void**)&wpl, g_wpr_lo);
    cudaGetSymbolAddress((void**)&yhi, g_yhi);
    cudaGetSymbolAddress((void**)&ylo, g_ylo);

    static bool attr_set = false;
    if (!attr_set) {
        cudaFuncSetAttribute(gemm_mma, cudaFuncAttributeMaxDynamicSharedMemorySize, GEMM_SMEM);
        cudaFuncSetAttribute(attn_mma, cudaFuncAttributeMaxDynamicSharedMemorySize, ATTN_SMEM);
        attr_set = true;
    }

    // 0) operand prep
    convert_hilo<<<(MR*TC/4 + 255)/256, 256>>>((const float4*)x,
        (__nv_bfloat162*)xhi, (__nv_bfloat162*)xlo, MR*TC/4);
    transpose_hilo2<<<dim3(N3C/32 + TC/32, TC/32), dim3(32, 8)>>>(
        Wqkv, wqh, wql, Wpr, wph, wpl);

    // 1) qkv = x @ Wqkv -> bf16 hi/lo directly
    gemm_mma<<<dim3(N3C/128, MR/128), 256, GEMM_SMEM>>>(xhi, xlo, wqh, wql,
        nullptr, qkvhi, qkvlo, 1, MR, N3C, TC);

    // 2) tensor-core flash attention -> yhi/ylo
    attn_mma<<<dim3(TT/64, TH, TB), 128, ATTN_SMEM>>>(qkvhi, qkvlo, span, strd, yhi, ylo);

    // 3) y = yatt @ Wproj -> d_out (fp32)
    gemm_mma<<<dim3(TC/128, MR/128), 256, GEMM_SMEM>>>(yhi, ylo, wph, wpl,
        out, nullptr, nullptr, 0, MR, TC, TC);

    // 4) span_loss scalar
    tail_kernel<<<1, 32>>>(span, out, out_size);
}

// round 9
// speedup vs baseline: 1.0194x; 1.0194x over previous
#include <cuda_runtime.h>
#include <cuda_fp16.h>
#include <math.h>
#include <stdint.h>

#define TB 4
#define TT 1024
#define TC 1024
#define TH 16
#define THD 64
#define MR (TB*TT)          // 4096 rows
#define N3C (3*TC)          // 3072

// ---------------- scratch (allocation-free rule: device globals) -----------
static __device__ __half g_qkvhi[(size_t)MR * N3C];
static __device__ __half g_qkvlo[(size_t)MR * N3C];
static __device__ __half g_xhi[(size_t)MR * TC];
static __device__ __half g_xlo[(size_t)MR * TC];
static __device__ __half g_wqkv_hi[(size_t)N3C * TC];   // W^T [3072,1024]
static __device__ __half g_wqkv_lo[(size_t)N3C * TC];
static __device__ __half g_wpr_hi[(size_t)TC * TC];     // W^T [1024,1024]
static __device__ __half g_wpr_lo[(size_t)TC * TC];
static __device__ __half g_yhi[(size_t)MR * TC];
static __device__ __half g_ylo[(size_t)MR * TC];

// ---------------- PTX helpers (baseline ISA only) ---------------------------
__device__ __forceinline__ uint32_t smem_u32(const void* p) {
    uint32_t a;
    asm("{ .reg .u64 t; cvta.to.shared.u64 t, %1; cvt.u32.u64 %0, t; }" : "=r"(a) : "l"(p));
    return a;
}
__device__ __forceinline__ void ldsm_x4(uint32_t (&r)[4], uint32_t addr) {
    asm volatile("ldmatrix.sync.aligned.m8n8.x4.shared.b16 {%0,%1,%2,%3}, [%4];"
        : "=r"(r[0]), "=r"(r[1]), "=r"(r[2]), "=r"(r[3]) : "r"(addr));
}
__device__ __forceinline__ void ldsm_x4t(uint32_t (&r)[4], uint32_t addr) {
    asm volatile("ldmatrix.sync.aligned.m8n8.x4.trans.shared.b16 {%0,%1,%2,%3}, [%4];"
        : "=r"(r[0]), "=r"(r[1]), "=r"(r[2]), "=r"(r[3]) : "r"(addr));
}
// fp16 inputs, fp32 accumulate (main product)
__device__ __forceinline__ void mma_f32acc(float (&d)[4], const uint32_t (&a)[4],
                                           uint32_t b0, uint32_t b1) {
    asm volatile("mma.sync.aligned.m16n8k16.row.col.f32.f16.f16.f32 "
        "{%0,%1,%2,%3}, {%4,%5,%6,%7}, {%8,%9}, {%0,%1,%2,%3};"
        : "+f"(d[0]), "+f"(d[1]), "+f"(d[2]), "+f"(d[3])
        : "r"(a[0]), "r"(a[1]), "r"(a[2]), "r"(a[3]), "r"(b0), "r"(b1));
}
// fp16 inputs, fp16 accumulate (correction products — 2x rate)
__device__ __forceinline__ void mma_f16acc(uint32_t (&d)[2], const uint32_t (&a)[4],
                                           uint32_t b0, uint32_t b1) {
    asm volatile("mma.sync.aligned.m16n8k16.row.col.f16.f16.f16.f16 "
        "{%0,%1}, {%2,%3,%4,%5}, {%6,%7}, {%0,%1};"
        : "+r"(d[0]), "+r"(d[1])
        : "r"(a[0]), "r"(a[1]), "r"(a[2]), "r"(a[3]), "r"(b0), "r"(b1));
}
__device__ __forceinline__ void cp_async16(uint32_t dst, const void* src) {
    asm volatile("cp.async.cg.shared.global [%0], [%1], 16;" :: "r"(dst), "l"(src) : "memory");
}
#define CP_COMMIT() asm volatile("cp.async.commit_group;" ::: "memory")
#define CP_WAIT1()  asm volatile("cp.async.wait_group 1;" ::: "memory")
#define CP_WAIT0()  asm volatile("cp.async.wait_group 0;" ::: "memory")

// GEMM smem geometry: rows of 32 fp16 data + 8 pad = 40
#define TROWG 40
#define AT_ELEMS (128*TROWG)      // 5120
#define BT_ELEMS (64*TROWG)       // 2560
#define STAGE_ELEMS (2*AT_ELEMS + 2*BT_ELEMS)   // 15360
#define GEMM_SMEM (2*STAGE_ELEMS*2)             // 61440 bytes

// ---------------------------------------------------------------------------
// Split-fp16 mixed-accumulation GEMM:
//   C = (Ahi+Alo)(Bhi+Blo)^T ; hh -> f32 acc, (hl + lh) -> shared f16 acc.
// CTA 128x64, BK=32, 8 warps (4m x 2n), warp tile 32x32, mma.m16n8k16.
// out_mode: 0 -> fp32 C, 1 -> fp16 hi/lo (Chi, Clo).
// ---------------------------------------------------------------------------
__global__ __launch_bounds__(256, 2) void gemm_mma(
    const __half* __restrict__ Ahi, const __half* __restrict__ Alo,
    const __half* __restrict__ Bhi, const __half* __restrict__ Blo,
    float* __restrict__ C, __half* __restrict__ Chi,
    __half* __restrict__ Clo, int out_mode, int M, int N, int K)
{
    extern __shared__ __half smem[];

    const int t = threadIdx.x, lane = t & 31, wid = t >> 5;
    const int wm = wid & 3, wn = wid >> 2;
    const int bm = blockIdx.y * 128, bn = blockIdx.x * 64;

    float acc32[2][4][4];
    uint32_t acc16[2][4][2];
    #pragma unroll
    for (int i = 0; i < 2; i++)
        #pragma unroll
        for (int j = 0; j < 4; j++) {
            #pragma unroll
            for (int k = 0; k < 4; k++) acc32[i][j][k] = 0.f;
            acc16[i][j][0] = 0u; acc16[i][j][1] = 0u;
        }

    // staging: A 512 chunks/tile (2 per thread), B 256 chunks/tile (1 per thread)
    const int rA = t >> 2, cA = (t & 3) * 8;   // A rows rA and rA+64
    const __half* gAh = Ahi + (size_t)(bm + rA) * K + cA;
    const __half* gAl = Alo + (size_t)(bm + rA) * K + cA;
    const __half* gBh = Bhi + (size_t)(bn + rA) * K + cA;   // rA<64 valid for B
    const __half* gBl = Blo + (size_t)(bn + rA) * K + cA;
    const uint32_t sAh = smem_u32(smem + rA * TROWG + cA);
    const uint32_t sAl = sAh + AT_ELEMS * 2;
    const uint32_t sBh = smem_u32(smem + 2*AT_ELEMS + rA * TROWG + cA);
    const uint32_t sBl = sBh + BT_ELEMS * 2;
    const uint32_t rowskip = 64 * TROWG * 2;   // bytes for +64 rows
    const uint32_t stage_bytes = STAGE_ELEMS * 2;

    const int a_row = wm * 32 + (lane & 15);
    const int a_coff = (lane >> 4) * 8;
    const int b_rbase = wn * 32 + (lane & 7) + ((lane >> 4) & 1) * 8;
    const int b_coff = ((lane >> 3) & 1) * 8;

    const int niter = K >> 5;

    // prologue stage 0
    cp_async16(sAh, gAh);  cp_async16(sAh + rowskip, gAh + (size_t)64 * K);
    cp_async16(sAl, gAl);  cp_async16(sAl + rowskip, gAl + (size_t)64 * K);
    cp_async16(sBh, gBh);  cp_async16(sBl, gBl);
    CP_COMMIT();

    for (int it = 0; it < niter; it++) {
        if (it + 1 < niter) {
            const int kn = (it + 1) << 5;
            const uint32_t so = ((it + 1) & 1) * stage_bytes;
            cp_async16(sAh + so, gAh + kn);  cp_async16(sAh + so + rowskip, gAh + (size_t)64 * K + kn);
            cp_async16(sAl + so, gAl + kn);  cp_async16(sAl + so + rowskip, gAl + (size_t)64 * K + kn);
            cp_async16(sBh + so, gBh + kn);  cp_async16(sBl + so, gBl + kn);
            CP_COMMIT();
            CP_WAIT1();
        } else {
            CP_WAIT0();
        }
        __syncthreads();

        const __half* bs = smem + (it & 1) * STAGE_ELEMS;
        #pragma unroll
        for (int ks = 0; ks < 2; ks++) {
            uint32_t ah[2][4], al[2][4];
            #pragma unroll
            for (int mt = 0; mt < 2; mt++) {
                ldsm_x4(ah[mt], smem_u32(bs + (a_row + mt*16) * TROWG + ks*16 + a_coff));
                ldsm_x4(al[mt], smem_u32(bs + AT_ELEMS + (a_row + mt*16) * TROWG + ks*16 + a_coff));
            }
            #pragma unroll
            for (int np = 0; np < 2; np++) {
                uint32_t bh[4], bl[4];
                ldsm_x4(bh, smem_u32(bs + 2*AT_ELEMS + (b_rbase + np*16) * TROWG + ks*16 + b_coff));
                ldsm_x4(bl, smem_u32(bs + 2*AT_ELEMS + BT_ELEMS + (b_rbase + np*16) * TROWG + ks*16 + b_coff));
                #pragma unroll
                for (int half = 0; half < 2; half++) {
                    const int nt = np*2 + half;
                    #pragma unroll
                    for (int mt = 0; mt < 2; mt++) {
                        mma_f32acc(acc32[mt][nt], ah[mt], bh[2*half], bh[2*half+1]);
                        mma_f16acc(acc16[mt][nt], ah[mt], bl[2*half], bl[2*half+1]);
                        mma_f16acc(acc16[mt][nt], al[mt], bh[2*half], bh[2*half+1]);
                    }
                }
            }
        }
        __syncthreads();
    }

    // epilogue: c = acc32 + float(acc16)
    const int g = lane >> 2, tq = lane & 3;
    #pragma unroll
    for (int mt = 0; mt < 2; mt++) {
        const int row = bm + wm*32 + mt*16 + g;
        #pragma unroll
        for (int nt = 0; nt < 4; nt++) {
            const int col = bn + wn*32 + nt*8 + 2*tq;
            __half2 c0, c1;
            memcpy(&c0, &acc16[mt][nt][0], 4);
            memcpy(&c1, &acc16[mt][nt][1], 4);
            const float v00 = acc32[mt][nt][0] + __low2float(c0);
            const float v01 = acc32[mt][nt][1] + __high2float(c0);
            const float v10 = acc32[mt][nt][2] + __low2float(c1);
            const float v11 = acc32[mt][nt][3] + __high2float(c1);
            if (out_mode == 0) {
                *(float2*)(C + (size_t)row * N + col)       = make_float2(v00, v01);
                *(float2*)(C + (size_t)(row + 8) * N + col) = make_float2(v10, v11);
            } else {
                const __half h00 = __float2half_rn(v00), h01 = __float2half_rn(v01);
                const __half h10 = __float2half_rn(v10), h11 = __float2half_rn(v11);
                const __half l00 = __float2half_rn(v00 - __half2float(h00));
                const __half l01 = __float2half_rn(v01 - __half2float(h01));
                const __half l10 = __float2half_rn(v10 - __half2float(h10));
                const __half l11 = __float2half_rn(v11 - __half2float(h11));
                const size_t o0 = (size_t)row * N + col, o1 = (size_t)(row + 8) * N + col;
                *(__half2*)(Chi + o0) = __halves2half2(h00, h01);
                *(__half2*)(Chi + o1) = __halves2half2(h10, h11);
                *(__half2*)(Clo + o0) = __halves2half2(l00, l01);
                *(__half2*)(Clo + o1) = __halves2half2(l10, l11);
            }
        }
    }
}

// ---------------------------------------------------------------------------
// fp32 -> (hi, lo) fp16, elementwise.
// ---------------------------------------------------------------------------
__global__ void convert_hilo(const float4* __restrict__ in,
                             __half2* __restrict__ hi,
                             __half2* __restrict__ lo, int n4)
{
    int i = blockIdx.x * blockDim.x + threadIdx.x;
    if (i >= n4) return;
    float4 v = in[i];
    __half h0 = __float2half_rn(v.x), h1 = __float2half_rn(v.y);
    __half h2 = __float2half_rn(v.z), h3 = __float2half_rn(v.w);
    __half l0 = __float2half_rn(v.x - __half2float(h0));
    __half l1 = __float2half_rn(v.y - __half2float(h1));
    __half l2 = __float2half_rn(v.z - __half2float(h2));
    __half l3 = __float2half_rn(v.w - __half2float(h3));
    hi[2*i]   = __halves2half2(h0, h1);
    hi[2*i+1] = __halves2half2(h2, h3);
    lo[2*i]   = __halves2half2(l0, l1);
    lo[2*i+1] = __halves2half2(l2, l3);
}

// ---------------------------------------------------------------------------
// Both W transposes in ONE launch (fp16 hi/lo).
// ---------------------------------------------------------------------------
__global__ void transpose_hilo2(const float* __restrict__ Wq,
                                __half* __restrict__ Tqh,
                                __half* __restrict__ Tql,
                                const float* __restrict__ Wp,
                                __half* __restrict__ Tph,
                                __half* __restrict__ Tpl)
{
    __shared__ float tile[32][33];
    const bool isq = blockIdx.x < (N3C/32);
    const int bx = isq ? blockIdx.x : blockIdx.x - (N3C/32);
    const int N = isq ? N3C : TC;
    const float* W = isq ? Wq : Wp;
    __half* Thi = isq ? Tqh : Tph;
    __half* Tlo = isq ? Tql : Tpl;
    const int n0 = bx * 32, k0 = blockIdx.y * 32;
    const int tx = threadIdx.x, ty = threadIdx.y;
    #pragma unroll
    for (int j = 0; j < 4; j++)
        tile[ty + 8*j][tx] = W[(size_t)(k0 + ty + 8*j) * N + n0 + tx];
    __syncthreads();
    #pragma unroll
    for (int j = 0; j < 4; j++) {
        float v = tile[tx][ty + 8*j];
        __half h = __float2half_rn(v);
        size_t o = (size_t)(n0 + ty + 8*j) * TC + k0 + tx;
        Thi[o] = h;
        Tlo[o] = __float2half_rn(v - __half2float(h));
    }
}

// ---------------------------------------------------------------------------
// Tensor-core flash attention, fp16 operands (same structure as R8).
// ---------------------------------------------------------------------------
#define ASQ 72
#define ATILE (64*ASQ)
#define ATTN_SMEM (6*ATILE*2)

__global__ __launch_bounds__(128) void attn_mma(
    const __half* __restrict__ qkvhi, const __half* __restrict__ qkvlo,
    const float* __restrict__ span_params, const float* __restrict__ stride_params,
    __half* __restrict__ yhi, __half* __restrict__ ylo)
{
    extern __shared__ __half sm[];
    __half* Qh = sm;
    __half* Ql = sm + ATILE;
    __half* Kh = sm + 2*ATILE;
    __half* Kl = sm + 3*ATILE;
    __half* Vh = sm + 4*ATILE;
    __half* Vl = sm + 5*ATILE;

    const int qt = blockIdx.x, h = blockIdx.y, b = blockIdx.z;
    const int t = threadIdx.x, lane = t & 31, w = t >> 5;
    const int i0 = qt * 64;

    const float sp = 1024.f / (1.f + __expf(-span_params[h]));
    const float p0 = stride_params[2*h], p1 = stride_params[2*h + 1];
    const float mxp = fmaxf(p0, p1);
    const float e0 = __expf(p0 - mxp), e1 = __expf(p1 - mxp);
    const float sw0 = e0 / (e0 + e1), sw1 = e1 / (e0 + e1);
    const float c1 = 32.f + sp;

    const int lr = t >> 1, lc = (t & 1) * 32;
    {
        const size_t gq = (size_t)(b*TT + i0 + lr) * N3C + h*THD + lc;
        #pragma unroll
        for (int i = 0; i < 4; i++) {
            *(uint4*)(Qh + lr*ASQ + lc + i*8) = *(const uint4*)(qkvhi + gq + i*8);
            *(uint4*)(Ql + lr*ASQ + lc + i*8) = *(const uint4*)(qkvlo + gq + i*8);
        }
    }
    __syncthreads();

    uint32_t qfh[4][4], qfl[4][4];
    {
        const int a_row = w*16 + (lane & 15);
        const int a_coff = (lane >> 4) * 8;
        #pragma unroll
        for (int ks = 0; ks < 4; ks++) {
            ldsm_x4(qfh[ks], smem_u32(Qh + a_row*ASQ + ks*16 + a_coff));
            ldsm_x4(qfl[ks], smem_u32(Ql + a_row*ASQ + ks*16 + a_coff));
        }
    }

    float accy[8][4];
    #pragma unroll
    for (int i = 0; i < 8; i++)
        #pragma unroll
        for (int j = 0; j < 4; j++) accy[i][j] = 0.f;
    float rs0 = 0.f, rs1 = 0.f;

    const int g = lane >> 2, tq2 = (lane & 3) * 2;
    const int q0 = i0 + w*16 + g;
    const int kb_row = (lane & 7) + ((lane >> 4) & 1) * 8;
    const int kb_coff = ((lane >> 3) & 1) * 8;
    const int vb_row = (lane & 7) + ((lane >> 3) & 1) * 8;
    const int vb_coff = (lane >> 4) * 8;

    int jt0 = (int)floorf(((float)i0 - 95.f - sp) * (1.f / 64.f)) + 1;
    if (jt0 < 0) jt0 = 0;

    for (int jt = jt0; jt <= qt; jt++) {
        __syncthreads();
        {
            const size_t gk = (size_t)(b*TT + jt*64 + lr) * N3C + TC   + h*THD + lc;
            const size_t gv = (size_t)(b*TT + jt*64 + lr) * N3C + 2*TC + h*THD + lc;
            #pragma unroll
            for (int i = 0; i < 4; i++) {
                *(uint4*)(Kh + lr*ASQ + lc + i*8) = *(const uint4*)(qkvhi + gk + i*8);
                *(uint4*)(Kl + lr*ASQ + lc + i*8) = *(const uint4*)(qkvlo + gk + i*8);
                *(uint4*)(Vh + lr*ASQ + lc + i*8) = *(const uint4*)(qkvhi + gv + i*8);
                *(uint4*)(Vl + lr*ASQ + lc + i*8) = *(const uint4*)(qkvlo + gv + i*8);
            }
        }
        __syncthreads();

        // ---- S = Q K^T (3-product, f32 acc) ----
        float s[8][4];
        #pragma unroll
        for (int i = 0; i < 8; i++)
            #pragma unroll
            for (int j = 0; j < 4; j++) s[i][j] = 0.f;
        #pragma unroll
        for (int ks = 0; ks < 4; ks++) {
            #pragma unroll
            for (int np = 0; np < 4; np++) {
                uint32_t bh[4], bl[4];
                ldsm_x4(bh, smem_u32(Kh + (np*16 + kb_row)*ASQ + ks*16 + kb_coff));
                ldsm_x4(bl, smem_u32(Kl + (np*16 + kb_row)*ASQ + ks*16 + kb_coff));
                #pragma unroll
                for (int half = 0; half < 2; half++) {
                    const int nf = np*2 + half;
                    mma_f32acc(s[nf], qfh[ks], bh[2*half], bh[2*half+1]);
                    mma_f32acc(s[nf], qfh[ks], bl[2*half], bl[2*half+1]);
                    mma_f32acc(s[nf], qfl[ks], bh[2*half], bh[2*half+1]);
                }
            }
        }

        // ---- mask + exp + rowsum + pack P (fp16 hi/lo) ----
        uint32_t pfh[4][4], pfl[4][4];
        #pragma unroll
        for (int nf = 0; nf < 8; nf++) {
            const int kk = jt*64 + nf*8 + tq2;
            float pv[4];
            #pragma unroll
            for (int e = 0; e < 4; e++) {
                const int qq = q0 + (e >> 1) * 8;
                const int kc = kk + (e & 1);
                const int rel = qq - kc;
                float p = 0.f;
                if (rel >= 0) {
                    float clip = fminf(fmaxf((c1 - (float)rel) * 0.03125f, 0.f), 1.f);
                    float mk = clip * (sw0 + (((rel & 1) == 0) ? sw1 : 0.f));
                    p = __expf(s[nf][e] * 0.125f) * mk;
                }
                pv[e] = p;
            }
            rs0 += pv[0] + pv[1];
            rs1 += pv[2] + pv[3];
            __half hh[4], ll[4];
            #pragma unroll
            for (int e = 0; e < 4; e++) {
                hh[e] = __float2half_rn(pv[e]);
                ll[e] = __float2half_rn(pv[e] - __half2float(hh[e]));
            }
            const int j = nf >> 1, odd = nf & 1;
            uint32_t ph01, ph23, pl01, pl23;
            memcpy(&ph01, &hh[0], 4); memcpy(&ph23, &hh[2], 4);
            memcpy(&pl01, &ll[0], 4); memcpy(&pl23, &ll[2], 4);
            pfh[j][2*odd]   = ph01;  pfh[j][2*odd+1] = ph23;
            pfl[j][2*odd]   = pl01;  pfl[j][2*odd+1] = pl23;
        }

        // ---- Y += P V (3-product, f32 acc) ----
        #pragma unroll
        for (int ks = 0; ks < 4; ks++) {
            #pragma unroll
            for (int dnp = 0; dnp < 4; dnp++) {
                uint32_t vh[4], vl[4];
                ldsm_x4t(vh, smem_u32(Vh + (ks*16 + vb_row)*ASQ + dnp*16 + vb_coff));
                ldsm_x4t(vl, smem_u32(Vl + (ks*16 + vb_row)*ASQ + dnp*16 + vb_coff));
                #pragma unroll
                for (int half = 0; half < 2; half++) {
                    const int df = dnp*2 + half;
                    mma_f32acc(accy[df], pfh[ks], vh[2*half], vh[2*half+1]);
                    mma_f32acc(accy[df], pfh[ks], vl[2*half], vl[2*half+1]);
                    mma_f32acc(accy[df], pfl[ks], vh[2*half], vh[2*half+1]);
                }
            }
        }
    }

    rs0 += __shfl_xor_sync(0xffffffffu, rs0, 1);
    rs0 += __shfl_xor_sync(0xffffffffu, rs0, 2);
    rs1 += __shfl_xor_sync(0xffffffffu, rs1, 1);
    rs1 += __shfl_xor_sync(0xffffffffu, rs1, 2);
    const float inv0 = 1.f / rs0, inv1 = 1.f / rs1;

    const size_t row0 = (size_t)(b*TT + i0 + w*16 + g);
    #pragma unroll
    for (int df = 0; df < 8; df++) {
        const int col = h*THD + df*8 + tq2;
        #pragma unroll
        for (int rr = 0; rr < 2; rr++) {
            const float inv = rr ? inv1 : inv0;
            const float v0 = accy[df][2*rr] * inv, v1 = accy[df][2*rr+1] * inv;
            const __half h0 = __float2half_rn(v0);
            const __half h1 = __float2half_rn(v1);
            const __half l0 = __float2half_rn(v0 - __half2float(h0));
            const __half l1 = __float2half_rn(v1 - __half2float(h1));
            const size_t off = (row0 + 8*rr) * TC + col;
            *(__half2*)(yhi + off) = __halves2half2(h0, h1);
            *(__half2*)(ylo + off) = __halves2half2(l0, l1);
        }
    }
}

// ---------------------------------------------------------------------------
__global__ void tail_kernel(const float* __restrict__ span_params,
                            float* __restrict__ out, int out_size)
{
    if (threadIdx.x == 0 && blockIdx.x == 0) {
        float s = 0.f;
        for (int i = 0; i < TH; i++)
            s += 1024.f / (1.f + expf(-span_params[i]));
        if (out_size > MR * TC)
            out[MR * TC] = 2e-6f * s / 16.f;
    }
}

extern "C" void kernel_launch(void* const* d_in, const int* in_sizes, int n_in,
                              void* d_out, int out_size)
{
    const float* x    = (const float*)d_in[0];
    const float* Wqkv = (const float*)d_in[1];
    const float* Wpr  = (const float*)d_in[2];
    const float* span = (const float*)d_in[3];
    const float* strd = (const float*)d_in[4];
    float* out = (float*)d_out;

    __half *qkvhi, *qkvlo, *xhi, *xlo, *wqh, *wql, *wph, *wpl, *yhi, *ylo;
    cudaGetSymbolAddress((void**)&qkvhi, g_qkvhi);
    cudaGetSymbolAddress((void**)&qkvlo, g_qkvlo);
    cudaGetSymbolAddress((void**)&xhi, g_xhi);
    cudaGetSymbolAddress((void**)&xlo, g_xlo);
    cudaGetSymbolAddress((void**)&wqh, g_wqkv_hi);
    cudaGetSymbolAddress((void**)&wql, g_wqkv_lo);
    cudaGetSymbolAddress((void**)&wph, g_wpr_hi);
    cudaGetSymbolAddress((void**)&wpl, g_wpr_lo);
    cudaGetSymbolAddress((void**)&yhi, g_yhi);
    cudaGetSymbolAddress((void**)&ylo, g_ylo);

    static bool attr_set = false;
    if (!attr_set) {
        cudaFuncSetAttribute(gemm_mma, cudaFuncAttributeMaxDynamicSharedMemorySize, GEMM_SMEM);
        cudaFuncSetAttribute(attn_mma, cudaFuncAttributeMaxDynamicSharedMemorySize, ATTN_SMEM);
        attr_set = true;
    }

    // 0) operand prep (fp16 hi/lo)
    convert_hilo<<<(MR*TC/4 + 255)/256, 256>>>((const float4*)x,
        (__half2*)xhi, (__half2*)xlo, MR*TC/4);
    transpose_hilo2<<<dim3(N3C/32 + TC/32, TC/32), dim3(32, 8)>>>(
        Wqkv, wqh, wql, Wpr, wph, wpl);

    // 1) qkv = x @ Wqkv -> fp16 hi/lo
    gemm_mma<<<dim3(N3C/64, MR/128), 256, GEMM_SMEM>>>(xhi, xlo, wqh, wql,
        nullptr, qkvhi, qkvlo, 1, MR, N3C, TC);

    // 2) tensor-core flash attention -> yhi/ylo
    attn_mma<<<dim3(TT/64, TH, TB), 128, ATTN_SMEM>>>(qkvhi, qkvlo, span, strd, yhi, ylo);

    // 3) y = yatt @ Wproj -> d_out (fp32)
    gemm_mma<<<dim3(TC/64, MR/128), 256, GEMM_SMEM>>>(yhi, ylo, wph, wpl,
        out, nullptr, nullptr, 0, MR, TC, TC);

    // 4) span_loss scalar
    tail_kernel<<<1, 32>>>(span, out, out_size);
}

// round 10
// speedup vs baseline: 1.0437x; 1.0238x over previous
#include <cuda_runtime.h>
#include <cuda_fp16.h>
#include <math.h>
#include <stdint.h>

#define TB 4
#define TT 1024
#define TC 1024
#define TH 16
#define THD 64
#define MR (TB*TT)          // 4096 rows
#define N3C (3*TC)          // 3072

// ---------------- scratch (allocation-free rule: device globals) -----------
static __device__ __half g_qkvhi[(size_t)MR * N3C];
static __device__ __half g_qkvlo[(size_t)MR * N3C];
static __device__ __half g_xhi[(size_t)MR * TC];
static __device__ __half g_xlo[(size_t)MR * TC];
static __device__ __half g_wqkv_hi[(size_t)N3C * TC];   // W^T [3072,1024]
static __device__ __half g_wqkv_lo[(size_t)N3C * TC];
static __device__ __half g_wpr_hi[(size_t)TC * TC];     // W^T [1024,1024]
static __device__ __half g_wpr_lo[(size_t)TC * TC];
static __device__ __half g_yhi[(size_t)MR * TC];
static __device__ __half g_ylo[(size_t)MR * TC];

// ---------------- PTX helpers (baseline ISA only) ---------------------------
__device__ __forceinline__ uint32_t smem_u32(const void* p) {
    uint32_t a;
    asm("{ .reg .u64 t; cvta.to.shared.u64 t, %1; cvt.u32.u64 %0, t; }" : "=r"(a) : "l"(p));
    return a;
}
__device__ __forceinline__ void ldsm_x4(uint32_t (&r)[4], uint32_t addr) {
    asm volatile("ldmatrix.sync.aligned.m8n8.x4.shared.b16 {%0,%1,%2,%3}, [%4];"
        : "=r"(r[0]), "=r"(r[1]), "=r"(r[2]), "=r"(r[3]) : "r"(addr));
}
__device__ __forceinline__ void ldsm_x4t(uint32_t (&r)[4], uint32_t addr) {
    asm volatile("ldmatrix.sync.aligned.m8n8.x4.trans.shared.b16 {%0,%1,%2,%3}, [%4];"
        : "=r"(r[0]), "=r"(r[1]), "=r"(r[2]), "=r"(r[3]) : "r"(addr));
}
// fp16 inputs, fp32 accumulate (main product)
__device__ __forceinline__ void mma_f32acc(float (&d)[4], const uint32_t (&a)[4],
                                           uint32_t b0, uint32_t b1) {
    asm volatile("mma.sync.aligned.m16n8k16.row.col.f32.f16.f16.f32 "
        "{%0,%1,%2,%3}, {%4,%5,%6,%7}, {%8,%9}, {%0,%1,%2,%3};"
        : "+f"(d[0]), "+f"(d[1]), "+f"(d[2]), "+f"(d[3])
        : "r"(a[0]), "r"(a[1]), "r"(a[2]), "r"(a[3]), "r"(b0), "r"(b1));
}
// fp16 inputs, fp16 accumulate (correction products)
__device__ __forceinline__ void mma_f16acc(uint32_t (&d)[2], const uint32_t (&a)[4],
                                           uint32_t b0, uint32_t b1) {
    asm volatile("mma.sync.aligned.m16n8k16.row.col.f16.f16.f16.f16 "
        "{%0,%1}, {%2,%3,%4,%5}, {%6,%7}, {%0,%1};"
        : "+r"(d[0]), "+r"(d[1])
        : "r"(a[0]), "r"(a[1]), "r"(a[2]), "r"(a[3]), "r"(b0), "r"(b1));
}
__device__ __forceinline__ void cp_async16(uint32_t dst, const void* src) {
    asm volatile("cp.async.cg.shared.global [%0], [%1], 16;" :: "r"(dst), "l"(src) : "memory");
}
#define CP_COMMIT() asm volatile("cp.async.commit_group;" ::: "memory")
#define CP_WAIT1()  asm volatile("cp.async.wait_group 1;" ::: "memory")
#define CP_WAIT0()  asm volatile("cp.async.wait_group 0;" ::: "memory")

// GEMM smem geometry: rows of 32 fp16 data + 8 pad = 40
#define TROWG 40
#define AT_ELEMS (128*TROWG)      // 5120
#define BT_ELEMS (64*TROWG)       // 2560
#define STAGE_ELEMS (2*AT_ELEMS + 2*BT_ELEMS)   // 15360
#define GEMM_SMEM (2*STAGE_ELEMS*2)             // 61440 bytes

// ---------------------------------------------------------------------------
// Split-fp16 mixed-accumulation GEMM (unchanged from R9):
//   C = (Ahi+Alo)(Bhi+Blo)^T ; hh -> f32 acc, (hl + lh) -> shared f16 acc.
// CTA 128x64, BK=32, 8 warps (4m x 2n), warp tile 32x32, mma.m16n8k16.
// out_mode: 0 -> fp32 C, 1 -> fp16 hi/lo (Chi, Clo).
// ---------------------------------------------------------------------------
__global__ __launch_bounds__(256, 2) void gemm_mma(
    const __half* __restrict__ Ahi, const __half* __restrict__ Alo,
    const __half* __restrict__ Bhi, const __half* __restrict__ Blo,
    float* __restrict__ C, __half* __restrict__ Chi,
    __half* __restrict__ Clo, int out_mode, int M, int N, int K)
{
    extern __shared__ __half smem[];

    const int t = threadIdx.x, lane = t & 31, wid = t >> 5;
    const int wm = wid & 3, wn = wid >> 2;
    const int bm = blockIdx.y * 128, bn = blockIdx.x * 64;

    float acc32[2][4][4];
    uint32_t acc16[2][4][2];
    #pragma unroll
    for (int i = 0; i < 2; i++)
        #pragma unroll
        for (int j = 0; j < 4; j++) {
            #pragma unroll
            for (int k = 0; k < 4; k++) acc32[i][j][k] = 0.f;
            acc16[i][j][0] = 0u; acc16[i][j][1] = 0u;
        }

    const int rA = t >> 2, cA = (t & 3) * 8;
    const __half* gAh = Ahi + (size_t)(bm + rA) * K + cA;
    const __half* gAl = Alo + (size_t)(bm + rA) * K + cA;
    const __half* gBh = Bhi + (size_t)(bn + rA) * K + cA;
    const __half* gBl = Blo + (size_t)(bn + rA) * K + cA;
    const uint32_t sAh = smem_u32(smem + rA * TROWG + cA);
    const uint32_t sAl = sAh + AT_ELEMS * 2;
    const uint32_t sBh = smem_u32(smem + 2*AT_ELEMS + rA * TROWG + cA);
    const uint32_t sBl = sBh + BT_ELEMS * 2;
    const uint32_t rowskip = 64 * TROWG * 2;
    const uint32_t stage_bytes = STAGE_ELEMS * 2;

    const int a_row = wm * 32 + (lane & 15);
    const int a_coff = (lane >> 4) * 8;
    const int b_rbase = wn * 32 + (lane & 7) + ((lane >> 4) & 1) * 8;
    const int b_coff = ((lane >> 3) & 1) * 8;

    const int niter = K >> 5;

    cp_async16(sAh, gAh);  cp_async16(sAh + rowskip, gAh + (size_t)64 * K);
    cp_async16(sAl, gAl);  cp_async16(sAl + rowskip, gAl + (size_t)64 * K);
    cp_async16(sBh, gBh);  cp_async16(sBl, gBl);
    CP_COMMIT();

    for (int it = 0; it < niter; it++) {
        if (it + 1 < niter) {
            const int kn = (it + 1) << 5;
            const uint32_t so = ((it + 1) & 1) * stage_bytes;
            cp_async16(sAh + so, gAh + kn);  cp_async16(sAh + so + rowskip, gAh + (size_t)64 * K + kn);
            cp_async16(sAl + so, gAl + kn);  cp_async16(sAl + so + rowskip, gAl + (size_t)64 * K + kn);
            cp_async16(sBh + so, gBh + kn);  cp_async16(sBl + so, gBl + kn);
            CP_COMMIT();
            CP_WAIT1();
        } else {
            CP_WAIT0();
        }
        __syncthreads();

        const __half* bs = smem + (it & 1) * STAGE_ELEMS;
        #pragma unroll
        for (int ks = 0; ks < 2; ks++) {
            uint32_t ah[2][4], al[2][4];
            #pragma unroll
            for (int mt = 0; mt < 2; mt++) {
                ldsm_x4(ah[mt], smem_u32(bs + (a_row + mt*16) * TROWG + ks*16 + a_coff));
                ldsm_x4(al[mt], smem_u32(bs + AT_ELEMS + (a_row + mt*16) * TROWG + ks*16 + a_coff));
            }
            #pragma unroll
            for (int np = 0; np < 2; np++) {
                uint32_t bh[4], bl[4];
                ldsm_x4(bh, smem_u32(bs + 2*AT_ELEMS + (b_rbase + np*16) * TROWG + ks*16 + b_coff));
                ldsm_x4(bl, smem_u32(bs + 2*AT_ELEMS + BT_ELEMS + (b_rbase + np*16) * TROWG + ks*16 + b_coff));
                #pragma unroll
                for (int half = 0; half < 2; half++) {
                    const int nt = np*2 + half;
                    #pragma unroll
                    for (int mt = 0; mt < 2; mt++) {
                        mma_f32acc(acc32[mt][nt], ah[mt], bh[2*half], bh[2*half+1]);
                        mma_f16acc(acc16[mt][nt], ah[mt], bl[2*half], bl[2*half+1]);
                        mma_f16acc(acc16[mt][nt], al[mt], bh[2*half], bh[2*half+1]);
                    }
                }
            }
        }
        __syncthreads();
    }

    const int g = lane >> 2, tq = lane & 3;
    #pragma unroll
    for (int mt = 0; mt < 2; mt++) {
        const int row = bm + wm*32 + mt*16 + g;
        #pragma unroll
        for (int nt = 0; nt < 4; nt++) {
            const int col = bn + wn*32 + nt*8 + 2*tq;
            __half2 c0, c1;
            memcpy(&c0, &acc16[mt][nt][0], 4);
            memcpy(&c1, &acc16[mt][nt][1], 4);
            const float v00 = acc32[mt][nt][0] + __low2float(c0);
            const float v01 = acc32[mt][nt][1] + __high2float(c0);
            const float v10 = acc32[mt][nt][2] + __low2float(c1);
            const float v11 = acc32[mt][nt][3] + __high2float(c1);
            if (out_mode == 0) {
                *(float2*)(C + (size_t)row * N + col)       = make_float2(v00, v01);
                *(float2*)(C + (size_t)(row + 8) * N + col) = make_float2(v10, v11);
            } else {
                const __half h00 = __float2half_rn(v00), h01 = __float2half_rn(v01);
                const __half h10 = __float2half_rn(v10), h11 = __float2half_rn(v11);
                const __half l00 = __float2half_rn(v00 - __half2float(h00));
                const __half l01 = __float2half_rn(v01 - __half2float(h01));
                const __half l10 = __float2half_rn(v10 - __half2float(h10));
                const __half l11 = __float2half_rn(v11 - __half2float(h11));
                const size_t o0 = (size_t)row * N + col, o1 = (size_t)(row + 8) * N + col;
                *(__half2*)(Chi + o0) = __halves2half2(h00, h01);
                *(__half2*)(Chi + o1) = __halves2half2(h10, h11);
                *(__half2*)(Clo + o0) = __halves2half2(l00, l01);
                *(__half2*)(Clo + o1) = __halves2half2(l10, l11);
            }
        }
    }
}

// ---------------------------------------------------------------------------
// fp32 -> (hi, lo) fp16, elementwise.
// ---------------------------------------------------------------------------
__global__ void convert_hilo(const float4* __restrict__ in,
                             __half2* __restrict__ hi,
                             __half2* __restrict__ lo, int n4)
{
    int i = blockIdx.x * blockDim.x + threadIdx.x;
    if (i >= n4) return;
    float4 v = in[i];
    __half h0 = __float2half_rn(v.x), h1 = __float2half_rn(v.y);
    __half h2 = __float2half_rn(v.z), h3 = __float2half_rn(v.w);
    __half l0 = __float2half_rn(v.x - __half2float(h0));
    __half l1 = __float2half_rn(v.y - __half2float(h1));
    __half l2 = __float2half_rn(v.z - __half2float(h2));
    __half l3 = __float2half_rn(v.w - __half2float(h3));
    hi[2*i]   = __halves2half2(h0, h1);
    hi[2*i+1] = __halves2half2(h2, h3);
    lo[2*i]   = __halves2half2(l0, l1);
    lo[2*i+1] = __halves2half2(l2, l3);
}

// ---------------------------------------------------------------------------
// Both W transposes in ONE launch (fp16 hi/lo).
// ---------------------------------------------------------------------------
__global__ void transpose_hilo2(const float* __restrict__ Wq,
                                __half* __restrict__ Tqh,
                                __half* __restrict__ Tql,
                                const float* __restrict__ Wp,
                                __half* __restrict__ Tph,
                                __half* __restrict__ Tpl)
{
    __shared__ float tile[32][33];
    const bool isq = blockIdx.x < (N3C/32);
    const int bx = isq ? blockIdx.x : blockIdx.x - (N3C/32);
    const int N = isq ? N3C : TC;
    const float* W = isq ? Wq : Wp;
    __half* Thi = isq ? Tqh : Tph;
    __half* Tlo = isq ? Tql : Tpl;
    const int n0 = bx * 32, k0 = blockIdx.y * 32;
    const int tx = threadIdx.x, ty = threadIdx.y;
    #pragma unroll
    for (int j = 0; j < 4; j++)
        tile[ty + 8*j][tx] = W[(size_t)(k0 + ty + 8*j) * N + n0 + tx];
    __syncthreads();
    #pragma unroll
    for (int j = 0; j < 4; j++) {
        float v = tile[tx][ty + 8*j];
        __half h = __float2half_rn(v);
        size_t o = (size_t)(n0 + ty + 8*j) * TC + k0 + tx;
        Thi[o] = h;
        Tlo[o] = __float2half_rn(v - __half2float(h));
    }
}

// ---------------------------------------------------------------------------
// Tensor-core flash attention, restructured:
//  - 2-product S (qh*kh + qh*kl) and PV (ph*vh + ph*vl): A-side lo dropped
//  - cp.async double-buffered K/V tiles (prefetch jt+1 during compute jt)
//  - Q-lo tile removed; 9 smem tiles total (Qh + 2 stages x {Kh,Kl,Vh,Vl})
// ---------------------------------------------------------------------------
#define ASQ 72
#define ATILE (64*ASQ)              // elems per tile (64 rows x 72)
#define AST_ELEMS (4*ATILE)         // one K/V stage: Kh,Kl,Vh,Vl
#define ATTN_SMEM ((ATILE + 2*AST_ELEMS)*2)   // 82944 bytes

__global__ __launch_bounds__(128) void attn_mma(
    const __half* __restrict__ qkvhi, const __half* __restrict__ qkvlo,
    const float* __restrict__ span_params, const float* __restrict__ stride_params,
    __half* __restrict__ yhi, __half* __restrict__ ylo)
{
    extern __shared__ __half sm[];
    __half* Qh = sm;

    const int qt = blockIdx.x, h = blockIdx.y, b = blockIdx.z;
    const int t = threadIdx.x, lane = t & 31, w = t >> 5;
    const int i0 = qt * 64;

    const float sp = 1024.f / (1.f + __expf(-span_params[h]));
    const float p0 = stride_params[2*h], p1 = stride_params[2*h + 1];
    const float mxp = fmaxf(p0, p1);
    const float e0 = __expf(p0 - mxp), e1 = __expf(p1 - mxp);
    const float sw0 = e0 / (e0 + e1), sw1 = e1 / (e0 + e1);
    const float c1 = 32.f + sp;

    const int lr = t >> 1, lc = (t & 1) * 32;

    int jt0 = (int)floorf(((float)i0 - 95.f - sp) * (1.f / 64.f)) + 1;
    if (jt0 < 0) jt0 = 0;

    // gmem row base for this thread's staging row
    const size_t grow = (size_t)(b*TT) * N3C + h*THD + lc;

    // ---- issue prefetch of first K/V stage, then load Q ----
    {
        const size_t gk = grow + (size_t)(jt0*64 + lr) * N3C + TC;
        const size_t gv = gk + TC;
        const uint32_t dst = smem_u32(sm + ATILE + (jt0 & 1) * AST_ELEMS + lr*ASQ + lc);
        #pragma unroll
        for (int i = 0; i < 4; i++) {
            cp_async16(dst + i*16,               qkvhi + gk + i*8);
            cp_async16(dst + ATILE*2 + i*16,     qkvlo + gk + i*8);
            cp_async16(dst + 2*ATILE*2 + i*16,   qkvhi + gv + i*8);
            cp_async16(dst + 3*ATILE*2 + i*16,   qkvlo + gv + i*8);
        }
        CP_COMMIT();
    }
    {
        const size_t gq = grow + (size_t)(i0 + lr) * N3C;
        #pragma unroll
        for (int i = 0; i < 4; i++)
            *(uint4*)(Qh + lr*ASQ + lc + i*8) = *(const uint4*)(qkvhi + gq + i*8);
    }
    __syncthreads();

    // ---- Q fragments (hi only) ----
    uint32_t qfh[4][4];
    {
        const int a_row = w*16 + (lane & 15);
        const int a_coff = (lane >> 4) * 8;
        #pragma unroll
        for (int ks = 0; ks < 4; ks++)
            ldsm_x4(qfh[ks], smem_u32(Qh + a_row*ASQ + ks*16 + a_coff));
    }

    float accy[8][4];
    #pragma unroll
    for (int i = 0; i < 8; i++)
        #pragma unroll
        for (int j = 0; j < 4; j++) accy[i][j] = 0.f;
    float rs0 = 0.f, rs1 = 0.f;

    const int g = lane >> 2, tq2 = (lane & 3) * 2;
    const int q0 = i0 + w*16 + g;
    const int kb_row = (lane & 7) + ((lane >> 4) & 1) * 8;
    const int kb_coff = ((lane >> 3) & 1) * 8;
    const int vb_row = (lane & 7) + ((lane >> 3) & 1) * 8;
    const int vb_coff = (lane >> 4) * 8;

    for (int jt = jt0; jt <= qt; jt++) {
        CP_WAIT0();          // stage (jt&1) data landed
        __syncthreads();     // all warps done reading stage ((jt+1)&1) from iter jt-1

        // prefetch next stage while computing this one
        if (jt + 1 <= qt) {
            const size_t gk = grow + (size_t)((jt+1)*64 + lr) * N3C + TC;
            const size_t gv = gk + TC;
            const uint32_t dst = smem_u32(sm + ATILE + ((jt+1) & 1) * AST_ELEMS + lr*ASQ + lc);
            #pragma unroll
            for (int i = 0; i < 4; i++) {
                cp_async16(dst + i*16,               qkvhi + gk + i*8);
                cp_async16(dst + ATILE*2 + i*16,     qkvlo + gk + i*8);
                cp_async16(dst + 2*ATILE*2 + i*16,   qkvhi + gv + i*8);
                cp_async16(dst + 3*ATILE*2 + i*16,   qkvlo + gv + i*8);
            }
            CP_COMMIT();
        }

        const __half* Kh = sm + ATILE + (jt & 1) * AST_ELEMS;
        const __half* Kl = Kh + ATILE;
        const __half* Vh = Kh + 2*ATILE;
        const __half* Vl = Kh + 3*ATILE;

        // ---- S = Q K^T (2-product: qh*kh + qh*kl) ----
        float s[8][4];
        #pragma unroll
        for (int i = 0; i < 8; i++)
            #pragma unroll
            for (int j = 0; j < 4; j++) s[i][j] = 0.f;
        #pragma unroll
        for (int ks = 0; ks < 4; ks++) {
            #pragma unroll
            for (int np = 0; np < 4; np++) {
                uint32_t bh[4], bl[4];
                ldsm_x4(bh, smem_u32(Kh + (np*16 + kb_row)*ASQ + ks*16 + kb_coff));
                ldsm_x4(bl, smem_u32(Kl + (np*16 + kb_row)*ASQ + ks*16 + kb_coff));
                #pragma unroll
                for (int half = 0; half < 2; half++) {
                    const int nf = np*2 + half;
                    mma_f32acc(s[nf], qfh[ks], bh[2*half], bh[2*half+1]);
                    mma_f32acc(s[nf], qfh[ks], bl[2*half], bl[2*half+1]);
                }
            }
        }

        // ---- mask + exp + rowsum + pack P (hi only) ----
        uint32_t pfh[4][4];
        #pragma unroll
        for (int nf = 0; nf < 8; nf++) {
            const int kk = jt*64 + nf*8 + tq2;
            float pv[4];
            #pragma unroll
            for (int e = 0; e < 4; e++) {
                const int qq = q0 + (e >> 1) * 8;
                const int kc = kk + (e & 1);
                const int rel = qq - kc;
                float p = 0.f;
                if (rel >= 0) {
                    float clip = fminf(fmaxf((c1 - (float)rel) * 0.03125f, 0.f), 1.f);
                    float mk = clip * (sw0 + (((rel & 1) == 0) ? sw1 : 0.f));
                    p = __expf(s[nf][e] * 0.125f) * mk;
                }
                pv[e] = p;
            }
            rs0 += pv[0] + pv[1];
            rs1 += pv[2] + pv[3];
            __half hh[4];
            #pragma unroll
            for (int e = 0; e < 4; e++) hh[e] = __float2half_rn(pv[e]);
            const int j = nf >> 1, odd = nf & 1;
            uint32_t ph01, ph23;
            memcpy(&ph01, &hh[0], 4); memcpy(&ph23, &hh[2], 4);
            pfh[j][2*odd]   = ph01;  pfh[j][2*odd+1] = ph23;
        }

        // ---- Y += P V (2-product: ph*vh + ph*vl) ----
        #pragma unroll
        for (int ks = 0; ks < 4; ks++) {
            #pragma unroll
            for (int dnp = 0; dnp < 4; dnp++) {
                uint32_t vh[4], vl[4];
                ldsm_x4t(vh, smem_u32(Vh + (ks*16 + vb_row)*ASQ + dnp*16 + vb_coff));
                ldsm_x4t(vl, smem_u32(Vl + (ks*16 + vb_row)*ASQ + dnp*16 + vb_coff));
                #pragma unroll
                for (int half = 0; half < 2; half++) {
                    const int df = dnp*2 + half;
                    mma_f32acc(accy[df], pfh[ks], vh[2*half], vh[2*half+1]);
                    mma_f32acc(accy[df], pfh[ks], vl[2*half], vl[2*half+1]);
                }
            }
        }
    }

    rs0 += __shfl_xor_sync(0xffffffffu, rs0, 1);
    rs0 += __shfl_xor_sync(0xffffffffu, rs0, 2);
    rs1 += __shfl_xor_sync(0xffffffffu, rs1, 1);
    rs1 += __shfl_xor_sync(0xffffffffu, rs1, 2);
    const float inv0 = 1.f / rs0, inv1 = 1.f / rs1;

    const size_t row0 = (size_t)(b*TT + i0 + w*16 + g);
    #pragma unroll
    for (int df = 0; df < 8; df++) {
        const int col = h*THD + df*8 + tq2;
        #pragma unroll
        for (int rr = 0; rr < 2; rr++) {
            const float inv = rr ? inv1 : inv0;
            const float v0 = accy[df][2*rr] * inv, v1 = accy[df][2*rr+1] * inv;
            const __half h0 = __float2half_rn(v0);
            const __half h1 = __float2half_rn(v1);
            const __half l0 = __float2half_rn(v0 - __half2float(h0));
            const __half l1 = __float2half_rn(v1 - __half2float(h1));
            const size_t off = (row0 + 8*rr) * TC + col;
            *(__half2*)(yhi + off) = __halves2half2(h0, h1);
            *(__half2*)(ylo + off) = __halves2half2(l0, l1);
        }
    }
}

// ---------------------------------------------------------------------------
__global__ void tail_kernel(const float* __restrict__ span_params,
                            float* __restrict__ out, int out_size)
{
    if (threadIdx.x == 0 && blockIdx.x == 0) {
        float s = 0.f;
        for (int i = 0; i < TH; i++)
            s += 1024.f / (1.f + expf(-span_params[i]));
        if (out_size > MR * TC)
            out[MR * TC] = 2e-6f * s / 16.f;
    }
}

extern "C" void kernel_launch(void* const* d_in, const int* in_sizes, int n_in,
                              void* d_out, int out_size)
{
    const float* x    = (const float*)d_in[0];
    const float* Wqkv = (const float*)d_in[1];
    const float* Wpr  = (const float*)d_in[2];
    const float* span = (const float*)d_in[3];
    const float* strd = (const float*)d_in[4];
    float* out = (float*)d_out;

    __half *qkvhi, *qkvlo, *xhi, *xlo, *wqh, *wql, *wph, *wpl, *yhi, *ylo;
    cudaGetSymbolAddress((void**)&qkvhi, g_qkvhi);
    cudaGetSymbolAddress((void**)&qkvlo, g_qkvlo);
    cudaGetSymbolAddress((void**)&xhi, g_xhi);
    cudaGetSymbolAddress((void**)&xlo, g_xlo);
    cudaGetSymbolAddress((void**)&wqh, g_wqkv_hi);
    cudaGetSymbolAddress((void**)&wql, g_wqkv_lo);
    cudaGetSymbolAddress((void**)&wph, g_wpr_hi);
    cudaGetSymbolAddress((void**)&wpl, g_wpr_lo);
    cudaGetSymbolAddress((void**)&yhi, g_yhi);
    cudaGetSymbolAddress((void**)&ylo, g_ylo);

    static bool attr_set = false;
    if (!attr_set) {
        cudaFuncSetAttribute(gemm_mma, cudaFuncAttributeMaxDynamicSharedMemorySize, GEMM_SMEM);
        cudaFuncSetAttribute(attn_mma, cudaFuncAttributeMaxDynamicSharedMemorySize, ATTN_SMEM);
        attr_set = true;
    }

    // 0) operand prep (fp16 hi/lo)
    convert_hilo<<<(MR*TC/4 + 255)/256, 256>>>((const float4*)x,
        (__half2*)xhi, (__half2*)xlo, MR*TC/4);
    transpose_hilo2<<<dim3(N3C/32 + TC/32, TC/32), dim3(32, 8)>>>(
        Wqkv, wqh, wql, Wpr, wph, wpl);

    // 1) qkv = x @ Wqkv -> fp16 hi/lo
    gemm_mma<<<dim3(N3C/64, MR/128), 256, GEMM_SMEM>>>(xhi, xlo, wqh, wql,
        nullptr, qkvhi, qkvlo, 1, MR, N3C, TC);

    // 2) tensor-core flash attention -> yhi/ylo
    attn_mma<<<dim3(TT/64, TH, TB), 128, ATTN_SMEM>>>(qkvhi, qkvlo, span, strd, yhi, ylo);

    // 3) y = yatt @ Wproj -> d_out (fp32)
    gemm_mma<<<dim3(TC/64, MR/128), 256, GEMM_SMEM>>>(yhi, ylo, wph, wpl,
        out, nullptr, nullptr, 0, MR, TC, TC);

    // 4) span_loss scalar
    tail_kernel<<<1, 32>>>(span, out, out_size);
}

// round 11
// speedup vs baseline: 1.5516x; 1.4867x over previous
#include <cuda_runtime.h>
#include <cuda_fp16.h>
#include <math.h>
#include <stdint.h>

#define TB 4
#define TT 1024
#define TC 1024
#define TH 16
#define THD 64
#define MR (TB*TT)          // 4096 rows
#define N3C (3*TC)          // 3072

// ---------------- scratch (allocation-free rule: device globals) -----------
static __device__ __half g_qkvhi[(size_t)MR * N3C];
static __device__ __half g_qkvlo[(size_t)MR * N3C];
static __device__ __half g_xhi[(size_t)MR * TC];
static __device__ __half g_wqkv_hi[(size_t)N3C * TC];   // W^T [3072,1024]
static __device__ __half g_wqkv_lo[(size_t)N3C * TC];
static __device__ __half g_wpr_hi[(size_t)TC * TC];     // W^T [1024,1024]
static __device__ __half g_wpr_lo[(size_t)TC * TC];
static __device__ __half g_yhi[(size_t)MR * TC];

// ---------------- PTX helpers (baseline ISA only) ---------------------------
__device__ __forceinline__ uint32_t smem_u32(const void* p) {
    uint32_t a;
    asm("{ .reg .u64 t; cvta.to.shared.u64 t, %1; cvt.u32.u64 %0, t; }" : "=r"(a) : "l"(p));
    return a;
}
__device__ __forceinline__ void ldsm_x4(uint32_t (&r)[4], uint32_t addr) {
    asm volatile("ldmatrix.sync.aligned.m8n8.x4.shared.b16 {%0,%1,%2,%3}, [%4];"
        : "=r"(r[0]), "=r"(r[1]), "=r"(r[2]), "=r"(r[3]) : "r"(addr));
}
__device__ __forceinline__ void ldsm_x4t(uint32_t (&r)[4], uint32_t addr) {
    asm volatile("ldmatrix.sync.aligned.m8n8.x4.trans.shared.b16 {%0,%1,%2,%3}, [%4];"
        : "=r"(r[0]), "=r"(r[1]), "=r"(r[2]), "=r"(r[3]) : "r"(addr));
}
// fp16 inputs, fp32 accumulate (main product)
__device__ __forceinline__ void mma_f32acc(float (&d)[4], const uint32_t (&a)[4],
                                           uint32_t b0, uint32_t b1) {
    asm volatile("mma.sync.aligned.m16n8k16.row.col.f32.f16.f16.f32 "
        "{%0,%1,%2,%3}, {%4,%5,%6,%7}, {%8,%9}, {%0,%1,%2,%3};"
        : "+f"(d[0]), "+f"(d[1]), "+f"(d[2]), "+f"(d[3])
        : "r"(a[0]), "r"(a[1]), "r"(a[2]), "r"(a[3]), "r"(b0), "r"(b1));
}
// fp16 inputs, fp16 accumulate (correction product)
__device__ __forceinline__ void mma_f16acc(uint32_t (&d)[2], const uint32_t (&a)[4],
                                           uint32_t b0, uint32_t b1) {
    asm volatile("mma.sync.aligned.m16n8k16.row.col.f16.f16.f16.f16 "
        "{%0,%1}, {%2,%3,%4,%5}, {%6,%7}, {%0,%1};"
        : "+r"(d[0]), "+r"(d[1])
        : "r"(a[0]), "r"(a[1]), "r"(a[2]), "r"(a[3]), "r"(b0), "r"(b1));
}
__device__ __forceinline__ void cp_async16(uint32_t dst, const void* src) {
    asm volatile("cp.async.cg.shared.global [%0], [%1], 16;" :: "r"(dst), "l"(src) : "memory");
}
#define CP_COMMIT() asm volatile("cp.async.commit_group;" ::: "memory")
#define CP_WAIT1()  asm volatile("cp.async.wait_group 1;" ::: "memory")
#define CP_WAIT0()  asm volatile("cp.async.wait_group 0;" ::: "memory")

// GEMM smem geometry: rows of 32 fp16 data + 8 pad = 40
#define TROWG 40
#define AT_ELEMS (128*TROWG)      // 5120
#define BT_ELEMS (64*TROWG)       // 2560
#define STAGE_ELEMS (AT_ELEMS + 2*BT_ELEMS)   // 10240
#define GEMM_SMEM (2*STAGE_ELEMS*2)           // 40960 bytes

// ---------------------------------------------------------------------------
// 2-product split-fp16 GEMM:  C ~= Ahi*(Bhi+Blo)^T
//   (A-side lo dropped: rel err ~2^-12). hh -> f32 acc, hl -> f16 acc.
// CTA 128x64, BK=32, 8 warps (4m x 2n), warp tile 32x32, mma.m16n8k16.
// out_mode: 0 -> fp32 C, 1 -> fp16 hi/lo (Chi, Clo).
// ---------------------------------------------------------------------------
__global__ __launch_bounds__(256, 2) void gemm_mma(
    const __half* __restrict__ Ahi,
    const __half* __restrict__ Bhi, const __half* __restrict__ Blo,
    float* __restrict__ C, __half* __restrict__ Chi,
    __half* __restrict__ Clo, int out_mode, int M, int N, int K)
{
    extern __shared__ __half smem[];

    const int t = threadIdx.x, lane = t & 31, wid = t >> 5;
    const int wm = wid & 3, wn = wid >> 2;
    const int bm = blockIdx.y * 128, bn = blockIdx.x * 64;

    float acc32[2][4][4];
    uint32_t acc16[2][4][2];
    #pragma unroll
    for (int i = 0; i < 2; i++)
        #pragma unroll
        for (int j = 0; j < 4; j++) {
            #pragma unroll
            for (int k = 0; k < 4; k++) acc32[i][j][k] = 0.f;
            acc16[i][j][0] = 0u; acc16[i][j][1] = 0u;
        }

    const int rA = t >> 2, cA = (t & 3) * 8;
    const __half* gAh = Ahi + (size_t)(bm + rA) * K + cA;
    const __half* gBh = Bhi + (size_t)(bn + rA) * K + cA;   // rA<64 valid for B
    const __half* gBl = Blo + (size_t)(bn + rA) * K + cA;
    const uint32_t sAh = smem_u32(smem + rA * TROWG + cA);
    const uint32_t sBh = smem_u32(smem + AT_ELEMS + rA * TROWG + cA);
    const uint32_t sBl = sBh + BT_ELEMS * 2;
    const uint32_t rowskip = 64 * TROWG * 2;
    const uint32_t stage_bytes = STAGE_ELEMS * 2;

    const int a_row = wm * 32 + (lane & 15);
    const int a_coff = (lane >> 4) * 8;
    const int b_rbase = wn * 32 + (lane & 7) + ((lane >> 4) & 1) * 8;
    const int b_coff = ((lane >> 3) & 1) * 8;

    const int niter = K >> 5;

    cp_async16(sAh, gAh);  cp_async16(sAh + rowskip, gAh + (size_t)64 * K);
    cp_async16(sBh, gBh);  cp_async16(sBl, gBl);
    CP_COMMIT();

    for (int it = 0; it < niter; it++) {
        if (it + 1 < niter) {
            const int kn = (it + 1) << 5;
            const uint32_t so = ((it + 1) & 1) * stage_bytes;
            cp_async16(sAh + so, gAh + kn);
            cp_async16(sAh + so + rowskip, gAh + (size_t)64 * K + kn);
            cp_async16(sBh + so, gBh + kn);
            cp_async16(sBl + so, gBl + kn);
            CP_COMMIT();
            CP_WAIT1();
        } else {
            CP_WAIT0();
        }
        __syncthreads();

        const __half* bs = smem + (it & 1) * STAGE_ELEMS;
        #pragma unroll
        for (int ks = 0; ks < 2; ks++) {
            uint32_t ah[2][4];
            #pragma unroll
            for (int mt = 0; mt < 2; mt++)
                ldsm_x4(ah[mt], smem_u32(bs + (a_row + mt*16) * TROWG + ks*16 + a_coff));
            #pragma unroll
            for (int np = 0; np < 2; np++) {
                uint32_t bh[4], bl[4];
                ldsm_x4(bh, smem_u32(bs + AT_ELEMS + (b_rbase + np*16) * TROWG + ks*16 + b_coff));
                ldsm_x4(bl, smem_u32(bs + AT_ELEMS + BT_ELEMS + (b_rbase + np*16) * TROWG + ks*16 + b_coff));
                #pragma unroll
                for (int half = 0; half < 2; half++) {
                    const int nt = np*2 + half;
                    #pragma unroll
                    for (int mt = 0; mt < 2; mt++) {
                        mma_f32acc(acc32[mt][nt], ah[mt], bh[2*half], bh[2*half+1]);
                        mma_f16acc(acc16[mt][nt], ah[mt], bl[2*half], bl[2*half+1]);
                    }
                }
            }
        }
        __syncthreads();
    }

    const int g = lane >> 2, tq = lane & 3;
    #pragma unroll
    for (int mt = 0; mt < 2; mt++) {
        const int row = bm + wm*32 + mt*16 + g;
        #pragma unroll
        for (int nt = 0; nt < 4; nt++) {
            const int col = bn + wn*32 + nt*8 + 2*tq;
            __half2 c0, c1;
            memcpy(&c0, &acc16[mt][nt][0], 4);
            memcpy(&c1, &acc16[mt][nt][1], 4);
            const float v00 = acc32[mt][nt][0] + __low2float(c0);
            const float v01 = acc32[mt][nt][1] + __high2float(c0);
            const float v10 = acc32[mt][nt][2] + __low2float(c1);
            const float v11 = acc32[mt][nt][3] + __high2float(c1);
            if (out_mode == 0) {
                *(float2*)(C + (size_t)row * N + col)       = make_float2(v00, v01);
                *(float2*)(C + (size_t)(row + 8) * N + col) = make_float2(v10, v11);
            } else {
                const __half h00 = __float2half_rn(v00), h01 = __float2half_rn(v01);
                const __half h10 = __float2half_rn(v10), h11 = __float2half_rn(v11);
                const __half l00 = __float2half_rn(v00 - __half2float(h00));
                const __half l01 = __float2half_rn(v01 - __half2float(h01));
                const __half l10 = __float2half_rn(v10 - __half2float(h10));
                const __half l11 = __float2half_rn(v11 - __half2float(h11));
                const size_t o0 = (size_t)row * N + col, o1 = (size_t)(row + 8) * N + col;
                *(__half2*)(Chi + o0) = __halves2half2(h00, h01);
                *(__half2*)(Chi + o1) = __halves2half2(h10, h11);
                *(__half2*)(Clo + o0) = __halves2half2(l00, l01);
                *(__half2*)(Clo + o1) = __halves2half2(l10, l11);
            }
        }
    }
}

// ---------------------------------------------------------------------------
// fp32 -> hi fp16, elementwise (A-side operands need hi only).
// ---------------------------------------------------------------------------
__global__ void convert_hi(const float4* __restrict__ in,
                           __half2* __restrict__ hi, int n4)
{
    int i = blockIdx.x * blockDim.x + threadIdx.x;
    if (i >= n4) return;
    float4 v = in[i];
    hi[2*i]   = __halves2half2(__float2half_rn(v.x), __float2half_rn(v.y));
    hi[2*i+1] = __halves2half2(__float2half_rn(v.z), __float2half_rn(v.w));
}

// ---------------------------------------------------------------------------
// Both W transposes in ONE launch (fp16 hi/lo).
// ---------------------------------------------------------------------------
__global__ void transpose_hilo2(const float* __restrict__ Wq,
                                __half* __restrict__ Tqh,
                                __half* __restrict__ Tql,
                                const float* __restrict__ Wp,
                                __half* __restrict__ Tph,
                                __half* __restrict__ Tpl)
{
    __shared__ float tile[32][33];
    const bool isq = blockIdx.x < (N3C/32);
    const int bx = isq ? blockIdx.x : blockIdx.x - (N3C/32);
    const int N = isq ? N3C : TC;
    const float* W = isq ? Wq : Wp;
    __half* Thi = isq ? Tqh : Tph;
    __half* Tlo = isq ? Tql : Tpl;
    const int n0 = bx * 32, k0 = blockIdx.y * 32;
    const int tx = threadIdx.x, ty = threadIdx.y;
    #pragma unroll
    for (int j = 0; j < 4; j++)
        tile[ty + 8*j][tx] = W[(size_t)(k0 + ty + 8*j) * N + n0 + tx];
    __syncthreads();
    #pragma unroll
    for (int j = 0; j < 4; j++) {
        float v = tile[tx][ty + 8*j];
        __half h = __float2half_rn(v);
        size_t o = (size_t)(n0 + ty + 8*j) * TC + k0 + tx;
        Thi[o] = h;
        Tlo[o] = __float2half_rn(v - __half2float(h));
    }
}

// ---------------------------------------------------------------------------
// Tensor-core flash attention:
//  - S = qh*kh only (k-lo logit correction ~1e-4 absolute, dropped)
//  - PV = ph*vh + ph*vl (v-lo kept: it is the error-dominant term)
//  - cp.async double-buffered K/V (7 smem tiles -> 3 CTAs/SM)
//  - epilogue emits y-hi only (proj GEMM drops its A-side lo)
// ---------------------------------------------------------------------------
#define ASQ 72
#define ATILE (64*ASQ)              // elems per tile (64 rows x 72)
#define AST_ELEMS (3*ATILE)         // one K/V stage: Kh,Vh,Vl
#define ATTN_SMEM ((ATILE + 2*AST_ELEMS)*2)   // 64512 bytes

__global__ __launch_bounds__(128) void attn_mma(
    const __half* __restrict__ qkvhi, const __half* __restrict__ qkvlo,
    const float* __restrict__ span_params, const float* __restrict__ stride_params,
    __half* __restrict__ yhi)
{
    extern __shared__ __half sm[];
    __half* Qh = sm;

    const int qt = blockIdx.x, h = blockIdx.y, b = blockIdx.z;
    const int t = threadIdx.x, lane = t & 31, w = t >> 5;
    const int i0 = qt * 64;

    const float sp = 1024.f / (1.f + __expf(-span_params[h]));
    const float p0 = stride_params[2*h], p1 = stride_params[2*h + 1];
    const float mxp = fmaxf(p0, p1);
    const float e0 = __expf(p0 - mxp), e1 = __expf(p1 - mxp);
    const float sw0 = e0 / (e0 + e1), sw1 = e1 / (e0 + e1);
    const float c1 = 32.f + sp;

    const int lr = t >> 1, lc = (t & 1) * 32;

    int jt0 = (int)floorf(((float)i0 - 95.f - sp) * (1.f / 64.f)) + 1;
    if (jt0 < 0) jt0 = 0;

    const size_t grow = (size_t)(b*TT) * N3C + h*THD + lc;

    // ---- prefetch first K/V stage, then load Q ----
    {
        const size_t gk = grow + (size_t)(jt0*64 + lr) * N3C + TC;
        const size_t gv = gk + TC;
        const uint32_t dst = smem_u32(sm + ATILE + (jt0 & 1) * AST_ELEMS + lr*ASQ + lc);
        #pragma unroll
        for (int i = 0; i < 4; i++) {
            cp_async16(dst + i*16,             qkvhi + gk + i*8);
            cp_async16(dst + ATILE*2 + i*16,   qkvhi + gv + i*8);
            cp_async16(dst + 2*ATILE*2 + i*16, qkvlo + gv + i*8);
        }
        CP_COMMIT();
    }
    {
        const size_t gq = grow + (size_t)(i0 + lr) * N3C;
        #pragma unroll
        for (int i = 0; i < 4; i++)
            *(uint4*)(Qh + lr*ASQ + lc + i*8) = *(const uint4*)(qkvhi + gq + i*8);
    }
    __syncthreads();

    // ---- Q fragments (hi only) ----
    uint32_t qfh[4][4];
    {
        const int a_row = w*16 + (lane & 15);
        const int a_coff = (lane >> 4) * 8;
        #pragma unroll
        for (int ks = 0; ks < 4; ks++)
            ldsm_x4(qfh[ks], smem_u32(Qh + a_row*ASQ + ks*16 + a_coff));
    }

    float accy[8][4];
    #pragma unroll
    for (int i = 0; i < 8; i++)
        #pragma unroll
        for (int j = 0; j < 4; j++) accy[i][j] = 0.f;
    float rs0 = 0.f, rs1 = 0.f;

    const int g = lane >> 2, tq2 = (lane & 3) * 2;
    const int q0 = i0 + w*16 + g;
    const int kb_row = (lane & 7) + ((lane >> 4) & 1) * 8;
    const int kb_coff = ((lane >> 3) & 1) * 8;
    const int vb_row = (lane & 7) + ((lane >> 3) & 1) * 8;
    const int vb_coff = (lane >> 4) * 8;

    for (int jt = jt0; jt <= qt; jt++) {
        CP_WAIT0();
        __syncthreads();

        if (jt + 1 <= qt) {
            const size_t gk = grow + (size_t)((jt+1)*64 + lr) * N3C + TC;
            const size_t gv = gk + TC;
            const uint32_t dst = smem_u32(sm + ATILE + ((jt+1) & 1) * AST_ELEMS + lr*ASQ + lc);
            #pragma unroll
            for (int i = 0; i < 4; i++) {
                cp_async16(dst + i*16,             qkvhi + gk + i*8);
                cp_async16(dst + ATILE*2 + i*16,   qkvhi + gv + i*8);
                cp_async16(dst + 2*ATILE*2 + i*16, qkvlo + gv + i*8);
            }
            CP_COMMIT();
        }

        const __half* Kh = sm + ATILE + (jt & 1) * AST_ELEMS;
        const __half* Vh = Kh + ATILE;
        const __half* Vl = Kh + 2*ATILE;

        // ---- S = Q K^T (single product qh*kh) ----
        float s[8][4];
        #pragma unroll
        for (int i = 0; i < 8; i++)
            #pragma unroll
            for (int j = 0; j < 4; j++) s[i][j] = 0.f;
        #pragma unroll
        for (int ks = 0; ks < 4; ks++) {
            #pragma unroll
            for (int np = 0; np < 4; np++) {
                uint32_t bh[4];
                ldsm_x4(bh, smem_u32(Kh + (np*16 + kb_row)*ASQ + ks*16 + kb_coff));
                #pragma unroll
                for (int half = 0; half < 2; half++)
                    mma_f32acc(s[np*2 + half], qfh[ks], bh[2*half], bh[2*half+1]);
            }
        }

        // ---- mask + exp + rowsum + pack P (hi only) ----
        uint32_t pfh[4][4];
        #pragma unroll
        for (int nf = 0; nf < 8; nf++) {
            const int kk = jt*64 + nf*8 + tq2;
            float pv[4];
            #pragma unroll
            for (int e = 0; e < 4; e++) {
                const int qq = q0 + (e >> 1) * 8;
                const int kc = kk + (e & 1);
                const int rel = qq - kc;
                float p = 0.f;
                if (rel >= 0) {
                    float clip = fminf(fmaxf((c1 - (float)rel) * 0.03125f, 0.f), 1.f);
                    float mk = clip * (sw0 + (((rel & 1) == 0) ? sw1 : 0.f));
                    p = __expf(s[nf][e] * 0.125f) * mk;
                }
                pv[e] = p;
            }
            rs0 += pv[0] + pv[1];
            rs1 += pv[2] + pv[3];
            __half hh[4];
            #pragma unroll
            for (int e = 0; e < 4; e++) hh[e] = __float2half_rn(pv[e]);
            const int j = nf >> 1, odd = nf & 1;
            uint32_t ph01, ph23;
            memcpy(&ph01, &hh[0], 4); memcpy(&ph23, &hh[2], 4);
            pfh[j][2*odd]   = ph01;  pfh[j][2*odd+1] = ph23;
        }

        // ---- Y += P V (2-product: ph*vh + ph*vl) ----
        #pragma unroll
        for (int ks = 0; ks < 4; ks++) {
            #pragma unroll
            for (int dnp = 0; dnp < 4; dnp++) {
                uint32_t vh[4], vl[4];
                ldsm_x4t(vh, smem_u32(Vh + (ks*16 + vb_row)*ASQ + dnp*16 + vb_coff));
                ldsm_x4t(vl, smem_u32(Vl + (ks*16 + vb_row)*ASQ + dnp*16 + vb_coff));
                #pragma unroll
                for (int half = 0; half < 2; half++) {
                    const int df = dnp*2 + half;
                    mma_f32acc(accy[df], pfh[ks], vh[2*half], vh[2*half+1]);
                    mma_f32acc(accy[df], pfh[ks], vl[2*half], vl[2*half+1]);
                }
            }
        }
    }

    rs0 += __shfl_xor_sync(0xffffffffu, rs0, 1);
    rs0 += __shfl_xor_sync(0xffffffffu, rs0, 2);
    rs1 += __shfl_xor_sync(0xffffffffu, rs1, 1);
    rs1 += __shfl_xor_sync(0xffffffffu, rs1, 2);
    const float inv0 = 1.f / rs0, inv1 = 1.f / rs1;

    const size_t row0 = (size_t)(b*TT + i0 + w*16 + g);
    #pragma unroll
    for (int df = 0; df < 8; df++) {
        const int col = h*THD + df*8 + tq2;
        #pragma unroll
        for (int rr = 0; rr < 2; rr++) {
            const float inv = rr ? inv1 : inv0;
            const float v0 = accy[df][2*rr] * inv, v1 = accy[df][2*rr+1] * inv;
            const size_t off = (row0 + 8*rr) * TC + col;
            *(__half2*)(yhi + off) =
                __halves2half2(__float2half_rn(v0), __float2half_rn(v1));
        }
    }
}

// ---------------------------------------------------------------------------
__global__ void tail_kernel(const float* __restrict__ span_params,
                            float* __restrict__ out, int out_size)
{
    if (threadIdx.x == 0 && blockIdx.x == 0) {
        float s = 0.f;
        for (int i = 0; i < TH; i++)
            s += 1024.f / (1.f + expf(-span_params[i]));
        if (out_size > MR * TC)
            out[MR * TC] = 2e-6f * s / 16.f;
    }
}

extern "C" void kernel_launch(void* const* d_in, const int* in_sizes, int n_in,
                              void* d_out, int out_size)
{
    const float* x    = (const float*)d_in[0];
    const float* Wqkv = (const float*)d_in[1];
    const float* Wpr  = (const float*)d_in[2];
    const float* span = (const float*)d_in[3];
    const float* strd = (const float*)d_in[4];
    float* out = (float*)d_out;

    __half *qkvhi, *qkvlo, *xhi, *wqh, *wql, *wph, *wpl, *yhi;
    cudaGetSymbolAddress((void**)&qkvhi, g_qkvhi);
    cudaGetSymbolAddress((void**)&qkvlo, g_qkvlo);
    cudaGetSymbolAddress((void**)&xhi, g_xhi);
    cudaGetSymbolAddress((void**)&wqh, g_wqkv_hi);
    cudaGetSymbolAddress((void**)&wql, g_wqkv_lo);
    cudaGetSymbolAddress((void**)&wph, g_wpr_hi);
    cudaGetSymbolAddress((void**)&wpl, g_wpr_lo);
    cudaGetSymbolAddress((void**)&yhi, g_yhi);

    static bool attr_set = false;
    if (!attr_set) {
        cudaFuncSetAttribute(gemm_mma, cudaFuncAttributeMaxDynamicSharedMemorySize, GEMM_SMEM);
        cudaFuncSetAttribute(attn_mma, cudaFuncAttributeMaxDynamicSharedMemorySize, ATTN_SMEM);
        attr_set = true;
    }

    // 0) operand prep (x hi; W hi/lo transposed)
    convert_hi<<<(MR*TC/4 + 255)/256, 256>>>((const float4*)x, (__half2*)xhi, MR*TC/4);
    transpose_hilo2<<<dim3(N3C/32 + TC/32, TC/32), dim3(32, 8)>>>(
        Wqkv, wqh, wql, Wpr, wph, wpl);

    // 1) qkv = x @ Wqkv -> fp16 hi/lo (2-product GEMM)
    gemm_mma<<<dim3(N3C/64, MR/128), 256, GEMM_SMEM>>>(xhi, wqh, wql,
        nullptr, qkvhi, qkvlo, 1, MR, N3C, TC);

    // 2) tensor-core flash attention -> yhi
    attn_mma<<<dim3(TT/64, TH, TB), 128, ATTN_SMEM>>>(qkvhi, qkvlo, span, strd, yhi);

    // 3) y = yatt @ Wproj -> d_out (fp32, 2-product GEMM)
    gemm_mma<<<dim3(TC/64, MR/128), 256, GEMM_SMEM>>>(yhi, wph, wpl,
        out, nullptr, nullptr, 0, MR, TC, TC);

    // 4) span_loss scalar
    tail_kernel<<<1, 32>>>(span, out, out_size);
}

// round 12
// speedup vs baseline: 1.9635x; 1.2654x over previous
#include <cuda_runtime.h>
#include <cuda_fp16.h>
#include <math.h>
#include <stdint.h>

#define TB 4
#define TT 1024
#define TC 1024
#define TH 16
#define THD 64
#define MR (TB*TT)          // 4096 rows
#define N3C (3*TC)          // 3072

// ---------------- scratch (allocation-free rule: device globals) -----------
static __device__ __half g_qkvhi[(size_t)MR * N3C];
static __device__ __half g_qkvlo[(size_t)MR * N3C];
static __device__ __half g_xhi[(size_t)MR * TC];
static __device__ __half g_wqkv_hi[(size_t)N3C * TC];   // W^T [3072,1024]
static __device__ __half g_wpr_hi[(size_t)TC * TC];     // W^T [1024,1024]
static __device__ __half g_yhi[(size_t)MR * TC];

// ---------------- PTX helpers (baseline ISA only) ---------------------------
__device__ __forceinline__ uint32_t smem_u32(const void* p) {
    uint32_t a;
    asm("{ .reg .u64 t; cvta.to.shared.u64 t, %1; cvt.u32.u64 %0, t; }" : "=r"(a) : "l"(p));
    return a;
}
__device__ __forceinline__ void ldsm_x4(uint32_t (&r)[4], uint32_t addr) {
    asm volatile("ldmatrix.sync.aligned.m8n8.x4.shared.b16 {%0,%1,%2,%3}, [%4];"
        : "=r"(r[0]), "=r"(r[1]), "=r"(r[2]), "=r"(r[3]) : "r"(addr));
}
__device__ __forceinline__ void ldsm_x4t(uint32_t (&r)[4], uint32_t addr) {
    asm volatile("ldmatrix.sync.aligned.m8n8.x4.trans.shared.b16 {%0,%1,%2,%3}, [%4];"
        : "=r"(r[0]), "=r"(r[1]), "=r"(r[2]), "=r"(r[3]) : "r"(addr));
}
// fp16 inputs, fp32 accumulate
__device__ __forceinline__ void mma_f32acc(float (&d)[4], const uint32_t (&a)[4],
                                           uint32_t b0, uint32_t b1) {
    asm volatile("mma.sync.aligned.m16n8k16.row.col.f32.f16.f16.f32 "
        "{%0,%1,%2,%3}, {%4,%5,%6,%7}, {%8,%9}, {%0,%1,%2,%3};"
        : "+f"(d[0]), "+f"(d[1]), "+f"(d[2]), "+f"(d[3])
        : "r"(a[0]), "r"(a[1]), "r"(a[2]), "r"(a[3]), "r"(b0), "r"(b1));
}
__device__ __forceinline__ void cp_async16(uint32_t dst, const void* src) {
    asm volatile("cp.async.cg.shared.global [%0], [%1], 16;" :: "r"(dst), "l"(src) : "memory");
}
#define CP_COMMIT() asm volatile("cp.async.commit_group;" ::: "memory")
#define CP_WAIT1()  asm volatile("cp.async.wait_group 1;" ::: "memory")
#define CP_WAIT0()  asm volatile("cp.async.wait_group 0;" ::: "memory")

// GEMM smem geometry: rows of 32 fp16 data + 8 pad = 40
#define TROWG 40
#define AT_ELEMS (128*TROWG)      // 5120
#define BT_ELEMS (64*TROWG)       // 2560
#define STAGE_ELEMS (AT_ELEMS + BT_ELEMS)   // 7680
#define GEMM_SMEM (2*STAGE_ELEMS*2)         // 30720 bytes

// ---------------------------------------------------------------------------
// Single-product fp16 GEMM:  C ~= Ahi * Bhi^T  (f32 accumulate).
// A-lo / B-lo corrections dropped (each ~2.4e-4 rel; validated error model).
// CTA 128x64, BK=32, 8 warps (4m x 2n), warp tile 32x32, mma.m16n8k16.
// out_mode: 0 -> fp32 C, 1 -> fp16 hi/lo (Chi, Clo).
// ---------------------------------------------------------------------------
__global__ __launch_bounds__(256, 2) void gemm_mma(
    const __half* __restrict__ Ahi, const __half* __restrict__ Bhi,
    float* __restrict__ C, __half* __restrict__ Chi,
    __half* __restrict__ Clo, int out_mode, int M, int N, int K)
{
    extern __shared__ __half smem[];

    const int t = threadIdx.x, lane = t & 31, wid = t >> 5;
    const int wm = wid & 3, wn = wid >> 2;
    const int bm = blockIdx.y * 128, bn = blockIdx.x * 64;

    float acc32[2][4][4];
    #pragma unroll
    for (int i = 0; i < 2; i++)
        #pragma unroll
        for (int j = 0; j < 4; j++)
            #pragma unroll
            for (int k = 0; k < 4; k++) acc32[i][j][k] = 0.f;

    const int rA = t >> 2, cA = (t & 3) * 8;
    const __half* gAh = Ahi + (size_t)(bm + rA) * K + cA;
    const __half* gBh = Bhi + (size_t)(bn + rA) * K + cA;   // rA<64 valid for B
    const uint32_t sAh = smem_u32(smem + rA * TROWG + cA);
    const uint32_t sBh = smem_u32(smem + AT_ELEMS + rA * TROWG + cA);
    const uint32_t rowskip = 64 * TROWG * 2;
    const uint32_t stage_bytes = STAGE_ELEMS * 2;

    const int a_row = wm * 32 + (lane & 15);
    const int a_coff = (lane >> 4) * 8;
    const int b_rbase = wn * 32 + (lane & 7) + ((lane >> 4) & 1) * 8;
    const int b_coff = ((lane >> 3) & 1) * 8;

    const int niter = K >> 5;

    cp_async16(sAh, gAh);  cp_async16(sAh + rowskip, gAh + (size_t)64 * K);
    cp_async16(sBh, gBh);
    CP_COMMIT();

    for (int it = 0; it < niter; it++) {
        if (it + 1 < niter) {
            const int kn = (it + 1) << 5;
            const uint32_t so = ((it + 1) & 1) * stage_bytes;
            cp_async16(sAh + so, gAh + kn);
            cp_async16(sAh + so + rowskip, gAh + (size_t)64 * K + kn);
            cp_async16(sBh + so, gBh + kn);
            CP_COMMIT();
            CP_WAIT1();
        } else {
            CP_WAIT0();
        }
        __syncthreads();

        const __half* bs = smem + (it & 1) * STAGE_ELEMS;
        #pragma unroll
        for (int ks = 0; ks < 2; ks++) {
            uint32_t ah[2][4];
            #pragma unroll
            for (int mt = 0; mt < 2; mt++)
                ldsm_x4(ah[mt], smem_u32(bs + (a_row + mt*16) * TROWG + ks*16 + a_coff));
            #pragma unroll
            for (int np = 0; np < 2; np++) {
                uint32_t bh[4];
                ldsm_x4(bh, smem_u32(bs + AT_ELEMS + (b_rbase + np*16) * TROWG + ks*16 + b_coff));
                #pragma unroll
                for (int half = 0; half < 2; half++) {
                    const int nt = np*2 + half;
                    #pragma unroll
                    for (int mt = 0; mt < 2; mt++)
                        mma_f32acc(acc32[mt][nt], ah[mt], bh[2*half], bh[2*half+1]);
                }
            }
        }
        __syncthreads();
    }

    const int g = lane >> 2, tq = lane & 3;
    #pragma unroll
    for (int mt = 0; mt < 2; mt++) {
        const int row = bm + wm*32 + mt*16 + g;
        #pragma unroll
        for (int nt = 0; nt < 4; nt++) {
            const int col = bn + wn*32 + nt*8 + 2*tq;
            const float v00 = acc32[mt][nt][0], v01 = acc32[mt][nt][1];
            const float v10 = acc32[mt][nt][2], v11 = acc32[mt][nt][3];
            if (out_mode == 0) {
                *(float2*)(C + (size_t)row * N + col)       = make_float2(v00, v01);
                *(float2*)(C + (size_t)(row + 8) * N + col) = make_float2(v10, v11);
            } else {
                const __half h00 = __float2half_rn(v00), h01 = __float2half_rn(v01);
                const __half h10 = __float2half_rn(v10), h11 = __float2half_rn(v11);
                const __half l00 = __float2half_rn(v00 - __half2float(h00));
                const __half l01 = __float2half_rn(v01 - __half2float(h01));
                const __half l10 = __float2half_rn(v10 - __half2float(h10));
                const __half l11 = __float2half_rn(v11 - __half2float(h11));
                const size_t o0 = (size_t)row * N + col, o1 = (size_t)(row + 8) * N + col;
                *(__half2*)(Chi + o0) = __halves2half2(h00, h01);
                *(__half2*)(Chi + o1) = __halves2half2(h10, h11);
                *(__half2*)(Clo + o0) = __halves2half2(l00, l01);
                *(__half2*)(Clo + o1) = __halves2half2(l10, l11);
            }
        }
    }
}

// ---------------------------------------------------------------------------
// fp32 -> hi fp16, elementwise.
// ---------------------------------------------------------------------------
__global__ void convert_hi(const float4* __restrict__ in,
                           __half2* __restrict__ hi, int n4)
{
    int i = blockIdx.x * blockDim.x + threadIdx.x;
    if (i >= n4) return;
    float4 v = in[i];
    hi[2*i]   = __halves2half2(__float2half_rn(v.x), __float2half_rn(v.y));
    hi[2*i+1] = __halves2half2(__float2half_rn(v.z), __float2half_rn(v.w));
}

// ---------------------------------------------------------------------------
// Both W transposes in ONE launch (fp16 hi only).
// ---------------------------------------------------------------------------
__global__ void transpose_hi2(const float* __restrict__ Wq,
                              __half* __restrict__ Tqh,
                              const float* __restrict__ Wp,
                              __half* __restrict__ Tph)
{
    __shared__ float tile[32][33];
    const bool isq = blockIdx.x < (N3C/32);
    const int bx = isq ? blockIdx.x : blockIdx.x - (N3C/32);
    const int N = isq ? N3C : TC;
    const float* W = isq ? Wq : Wp;
    __half* Thi = isq ? Tqh : Tph;
    const int n0 = bx * 32, k0 = blockIdx.y * 32;
    const int tx = threadIdx.x, ty = threadIdx.y;
    #pragma unroll
    for (int j = 0; j < 4; j++)
        tile[ty + 8*j][tx] = W[(size_t)(k0 + ty + 8*j) * N + n0 + tx];
    __syncthreads();
    #pragma unroll
    for (int j = 0; j < 4; j++) {
        float v = tile[tx][ty + 8*j];
        size_t o = (size_t)(n0 + ty + 8*j) * TC + k0 + tx;
        Thi[o] = __float2half_rn(v);
    }
}

// ---------------------------------------------------------------------------
// Tensor-core flash attention (unchanged from R11):
//  - S = qh*kh ; PV = ph*vh + ph*vl ; cp.async double-buffered K/V
// ---------------------------------------------------------------------------
#define ASQ 72
#define ATILE (64*ASQ)              // elems per tile (64 rows x 72)
#define AST_ELEMS (3*ATILE)         // one K/V stage: Kh,Vh,Vl
#define ATTN_SMEM ((ATILE + 2*AST_ELEMS)*2)   // 64512 bytes

__global__ __launch_bounds__(128) void attn_mma(
    const __half* __restrict__ qkvhi, const __half* __restrict__ qkvlo,
    const float* __restrict__ span_params, const float* __restrict__ stride_params,
    __half* __restrict__ yhi)
{
    extern __shared__ __half sm[];
    __half* Qh = sm;

    const int qt = blockIdx.x, h = blockIdx.y, b = blockIdx.z;
    const int t = threadIdx.x, lane = t & 31, w = t >> 5;
    const int i0 = qt * 64;

    const float sp = 1024.f / (1.f + __expf(-span_params[h]));
    const float p0 = stride_params[2*h], p1 = stride_params[2*h + 1];
    const float mxp = fmaxf(p0, p1);
    const float e0 = __expf(p0 - mxp), e1 = __expf(p1 - mxp);
    const float sw0 = e0 / (e0 + e1), sw1 = e1 / (e0 + e1);
    const float c1 = 32.f + sp;

    const int lr = t >> 1, lc = (t & 1) * 32;

    int jt0 = (int)floorf(((float)i0 - 95.f - sp) * (1.f / 64.f)) + 1;
    if (jt0 < 0) jt0 = 0;

    const size_t grow = (size_t)(b*TT) * N3C + h*THD + lc;

    {
        const size_t gk = grow + (size_t)(jt0*64 + lr) * N3C + TC;
        const size_t gv = gk + TC;
        const uint32_t dst = smem_u32(sm + ATILE + (jt0 & 1) * AST_ELEMS + lr*ASQ + lc);
        #pragma unroll
        for (int i = 0; i < 4; i++) {
            cp_async16(dst + i*16,             qkvhi + gk + i*8);
            cp_async16(dst + ATILE*2 + i*16,   qkvhi + gv + i*8);
            cp_async16(dst + 2*ATILE*2 + i*16, qkvlo + gv + i*8);
        }
        CP_COMMIT();
    }
    {
        const size_t gq = grow + (size_t)(i0 + lr) * N3C;
        #pragma unroll
        for (int i = 0; i < 4; i++)
            *(uint4*)(Qh + lr*ASQ + lc + i*8) = *(const uint4*)(qkvhi + gq + i*8);
    }
    __syncthreads();

    uint32_t qfh[4][4];
    {
        const int a_row = w*16 + (lane & 15);
        const int a_coff = (lane >> 4) * 8;
        #pragma unroll
        for (int ks = 0; ks < 4; ks++)
            ldsm_x4(qfh[ks], smem_u32(Qh + a_row*ASQ + ks*16 + a_coff));
    }

    float accy[8][4];
    #pragma unroll
    for (int i = 0; i < 8; i++)
        #pragma unroll
        for (int j = 0; j < 4; j++) accy[i][j] = 0.f;
    float rs0 = 0.f, rs1 = 0.f;

    const int g = lane >> 2, tq2 = (lane & 3) * 2;
    const int q0 = i0 + w*16 + g;
    const int kb_row = (lane & 7) + ((lane >> 4) & 1) * 8;
    const int kb_coff = ((lane >> 3) & 1) * 8;
    const int vb_row = (lane & 7) + ((lane >> 3) & 1) * 8;
    const int vb_coff = (lane >> 4) * 8;

    for (int jt = jt0; jt <= qt; jt++) {
        CP_WAIT0();
        __syncthreads();

        if (jt + 1 <= qt) {
            const size_t gk = grow + (size_t)((jt+1)*64 + lr) * N3C + TC;
            const size_t gv = gk + TC;
            const uint32_t dst = smem_u32(sm + ATILE + ((jt+1) & 1) * AST_ELEMS + lr*ASQ + lc);
            #pragma unroll
            for (int i = 0; i < 4; i++) {
                cp_async16(dst + i*16,             qkvhi + gk + i*8);
                cp_async16(dst + ATILE*2 + i*16,   qkvhi + gv + i*8);
                cp_async16(dst + 2*ATILE*2 + i*16, qkvlo + gv + i*8);
            }
            CP_COMMIT();
        }

        const __half* Kh = sm + ATILE + (jt & 1) * AST_ELEMS;
        const __half* Vh = Kh + ATILE;
        const __half* Vl = Kh + 2*ATILE;

        float s[8][4];
        #pragma unroll
        for (int i = 0; i < 8; i++)
            #pragma unroll
            for (int j = 0; j < 4; j++) s[i][j] = 0.f;
        #pragma unroll
        for (int ks = 0; ks < 4; ks++) {
            #pragma unroll
            for (int np = 0; np < 4; np++) {
                uint32_t bh[4];
                ldsm_x4(bh, smem_u32(Kh + (np*16 + kb_row)*ASQ + ks*16 + kb_coff));
                #pragma unroll
                for (int half = 0; half < 2; half++)
                    mma_f32acc(s[np*2 + half], qfh[ks], bh[2*half], bh[2*half+1]);
            }
        }

        uint32_t pfh[4][4];
        #pragma unroll
        for (int nf = 0; nf < 8; nf++) {
            const int kk = jt*64 + nf*8 + tq2;
            float pv[4];
            #pragma unroll
            for (int e = 0; e < 4; e++) {
                const int qq = q0 + (e >> 1) * 8;
                const int kc = kk + (e & 1);
                const int rel = qq - kc;
                float p = 0.f;
                if (rel >= 0) {
                    float clip = fminf(fmaxf((c1 - (float)rel) * 0.03125f, 0.f), 1.f);
                    float mk = clip * (sw0 + (((rel & 1) == 0) ? sw1 : 0.f));
                    p = __expf(s[nf][e] * 0.125f) * mk;
                }
                pv[e] = p;
            }
            rs0 += pv[0] + pv[1];
            rs1 += pv[2] + pv[3];
            __half hh[4];
            #pragma unroll
            for (int e = 0; e < 4; e++) hh[e] = __float2half_rn(pv[e]);
            const int j = nf >> 1, odd = nf & 1;
            uint32_t ph01, ph23;
            memcpy(&ph01, &hh[0], 4); memcpy(&ph23, &hh[2], 4);
            pfh[j][2*odd]   = ph01;  pfh[j][2*odd+1] = ph23;
        }

        #pragma unroll
        for (int ks = 0; ks < 4; ks++) {
            #pragma unroll
            for (int dnp = 0; dnp < 4; dnp++) {
                uint32_t vh[4], vl[4];
                ldsm_x4t(vh, smem_u32(Vh + (ks*16 + vb_row)*ASQ + dnp*16 + vb_coff));
                ldsm_x4t(vl, smem_u32(Vl + (ks*16 + vb_row)*ASQ + dnp*16 + vb_coff));
                #pragma unroll
                for (int half = 0; half < 2; half++) {
                    const int df = dnp*2 + half;
                    mma_f32acc(accy[df], pfh[ks], vh[2*half], vh[2*half+1]);
                    mma_f32acc(accy[df], pfh[ks], vl[2*half], vl[2*half+1]);
                }
            }
        }
    }

    rs0 += __shfl_xor_sync(0xffffffffu, rs0, 1);
    rs0 += __shfl_xor_sync(0xffffffffu, rs0, 2);
    rs1 += __shfl_xor_sync(0xffffffffu, rs1, 1);
    rs1 += __shfl_xor_sync(0xffffffffu, rs1, 2);
    const float inv0 = 1.f / rs0, inv1 = 1.f / rs1;

    const size_t row0 = (size_t)(b*TT + i0 + w*16 + g);
    #pragma unroll
    for (int df = 0; df < 8; df++) {
        const int col = h*THD + df*8 + tq2;
        #pragma unroll
        for (int rr = 0; rr < 2; rr++) {
            const float inv = rr ? inv1 : inv0;
            const float v0 = accy[df][2*rr] * inv, v1 = accy[df][2*rr+1] * inv;
            const size_t off = (row0 + 8*rr) * TC + col;
            *(__half2*)(yhi + off) =
                __halves2half2(__float2half_rn(v0), __float2half_rn(v1));
        }
    }
}

// ---------------------------------------------------------------------------
__global__ void tail_kernel(const float* __restrict__ span_params,
                            float* __restrict__ out, int out_size)
{
    if (threadIdx.x == 0 && blockIdx.x == 0) {
        float s = 0.f;
        for (int i = 0; i < TH; i++)
            s += 1024.f / (1.f + expf(-span_params[i]));
        if (out_size > MR * TC)
            out[MR * TC] = 2e-6f * s / 16.f;
    }
}

extern "C" void kernel_launch(void* const* d_in, const int* in_sizes, int n_in,
                              void* d_out, int out_size)
{
    const float* x    = (const float*)d_in[0];
    const float* Wqkv = (const float*)d_in[1];
    const float* Wpr  = (const float*)d_in[2];
    const float* span = (const float*)d_in[3];
    const float* strd = (const float*)d_in[4];
    float* out = (float*)d_out;

    __half *qkvhi, *qkvlo, *xhi, *wqh, *wph, *yhi;
    cudaGetSymbolAddress((void**)&qkvhi, g_qkvhi);
    cudaGetSymbolAddress((void**)&qkvlo, g_qkvlo);
    cudaGetSymbolAddress((void**)&xhi, g_xhi);
    cudaGetSymbolAddress((void**)&wqh, g_wqkv_hi);
    cudaGetSymbolAddress((void**)&wph, g_wpr_hi);
    cudaGetSymbolAddress((void**)&yhi, g_yhi);

    static bool attr_set = false;
    if (!attr_set) {
        cudaFuncSetAttribute(gemm_mma, cudaFuncAttributeMaxDynamicSharedMemorySize, GEMM_SMEM);
        cudaFuncSetAttribute(attn_mma, cudaFuncAttributeMaxDynamicSharedMemorySize, ATTN_SMEM);
        attr_set = true;
    }

    // 0) operand prep (x hi; W hi transposed)
    convert_hi<<<(MR*TC/4 + 255)/256, 256>>>((const float4*)x, (__half2*)xhi, MR*TC/4);
    transpose_hi2<<<dim3(N3C/32 + TC/32, TC/32), dim3(32, 8)>>>(Wqkv, wqh, Wpr, wph);

    // 1) qkv = x @ Wqkv -> fp16 hi/lo (single-product GEMM)
    gemm_mma<<<dim3(N3C/64, MR/128), 256, GEMM_SMEM>>>(xhi, wqh,
        nullptr, qkvhi, qkvlo, 1, MR, N3C, TC);

    // 2) tensor-core flash attention -> yhi
    attn_mma<<<dim3(TT/64, TH, TB), 128, ATTN_SMEM>>>(qkvhi, qkvlo, span, strd, yhi);

    // 3) y = yatt @ Wproj -> d_out (fp32, single-product GEMM)
    gemm_mma<<<dim3(TC/64, MR/128), 256, GEMM_SMEM>>>(yhi, wph,
        out, nullptr, nullptr, 0, MR, TC, TC);

    // 4) span_loss scalar
    tail_kernel<<<1, 32>>>(span, out, out_size);
}

// round 13
// speedup vs baseline: 2.2538x; 1.1478x over previous
#include <cuda_runtime.h>
#include <cuda_fp16.h>
#include <math.h>
#include <stdint.h>

#define TB 4
#define TT 1024
#define TC 1024
#define TH 16
#define THD 64
#define MR (TB*TT)          // 4096 rows
#define N3C (3*TC)          // 3072

// ---------------- scratch (allocation-free rule: device globals) -----------
static __device__ __half g_qkvhi[(size_t)MR * N3C];
static __device__ __half g_xhi[(size_t)MR * TC];
static __device__ __half g_wqkv_hi[(size_t)N3C * TC];   // W^T [3072,1024]
static __device__ __half g_wpr_hi[(size_t)TC * TC];     // W^T [1024,1024]
static __device__ __half g_yhi[(size_t)MR * TC];

// ---------------- PTX helpers (baseline ISA only) ---------------------------
__device__ __forceinline__ uint32_t smem_u32(const void* p) {
    uint32_t a;
    asm("{ .reg .u64 t; cvta.to.shared.u64 t, %1; cvt.u32.u64 %0, t; }" : "=r"(a) : "l"(p));
    return a;
}
__device__ __forceinline__ void ldsm_x4(uint32_t (&r)[4], uint32_t addr) {
    asm volatile("ldmatrix.sync.aligned.m8n8.x4.shared.b16 {%0,%1,%2,%3}, [%4];"
        : "=r"(r[0]), "=r"(r[1]), "=r"(r[2]), "=r"(r[3]) : "r"(addr));
}
__device__ __forceinline__ void ldsm_x4t(uint32_t (&r)[4], uint32_t addr) {
    asm volatile("ldmatrix.sync.aligned.m8n8.x4.trans.shared.b16 {%0,%1,%2,%3}, [%4];"
        : "=r"(r[0]), "=r"(r[1]), "=r"(r[2]), "=r"(r[3]) : "r"(addr));
}
// fp16 inputs, fp32 accumulate
__device__ __forceinline__ void mma_f32acc(float (&d)[4], const uint32_t (&a)[4],
                                           uint32_t b0, uint32_t b1) {
    asm volatile("mma.sync.aligned.m16n8k16.row.col.f32.f16.f16.f32 "
        "{%0,%1,%2,%3}, {%4,%5,%6,%7}, {%8,%9}, {%0,%1,%2,%3};"
        : "+f"(d[0]), "+f"(d[1]), "+f"(d[2]), "+f"(d[3])
        : "r"(a[0]), "r"(a[1]), "r"(a[2]), "r"(a[3]), "r"(b0), "r"(b1));
}
__device__ __forceinline__ void cp_async16(uint32_t dst, const void* src) {
    asm volatile("cp.async.cg.shared.global [%0], [%1], 16;" :: "r"(dst), "l"(src) : "memory");
}
#define CP_COMMIT() asm volatile("cp.async.commit_group;" ::: "memory")
#define CP_WAIT1()  asm volatile("cp.async.wait_group 1;" ::: "memory")
#define CP_WAIT0()  asm volatile("cp.async.wait_group 0;" ::: "memory")

// GEMM smem geometry: rows of 32 fp16 data + 8 pad = 40
#define TROWG 40
#define AT_ELEMS (128*TROWG)      // 5120
#define BT_ELEMS (64*TROWG)       // 2560
#define STAGE_ELEMS (AT_ELEMS + BT_ELEMS)   // 7680
#define GEMM_SMEM (2*STAGE_ELEMS*2)         // 30720 bytes

// ---------------------------------------------------------------------------
// Single-product fp16 GEMM:  C ~= Ahi * Bhi^T  (f32 accumulate).
// CTA 128x64, BK=32, 8 warps (4m x 2n), warp tile 32x32, mma.m16n8k16.
// out_mode: 0 -> fp32 C, 1 -> fp16 hi (Chi).
// ---------------------------------------------------------------------------
__global__ __launch_bounds__(256, 2) void gemm_mma(
    const __half* __restrict__ Ahi, const __half* __restrict__ Bhi,
    float* __restrict__ C, __half* __restrict__ Chi,
    int out_mode, int M, int N, int K)
{
    extern __shared__ __half smem[];

    const int t = threadIdx.x, lane = t & 31, wid = t >> 5;
    const int wm = wid & 3, wn = wid >> 2;
    const int bm = blockIdx.y * 128, bn = blockIdx.x * 64;

    float acc32[2][4][4];
    #pragma unroll
    for (int i = 0; i < 2; i++)
        #pragma unroll
        for (int j = 0; j < 4; j++)
            #pragma unroll
            for (int k = 0; k < 4; k++) acc32[i][j][k] = 0.f;

    const int rA = t >> 2, cA = (t & 3) * 8;
    const __half* gAh = Ahi + (size_t)(bm + rA) * K + cA;
    const __half* gBh = Bhi + (size_t)(bn + rA) * K + cA;   // rA<64 valid for B
    const uint32_t sAh = smem_u32(smem + rA * TROWG + cA);
    const uint32_t sBh = smem_u32(smem + AT_ELEMS + rA * TROWG + cA);
    const uint32_t rowskip = 64 * TROWG * 2;
    const uint32_t stage_bytes = STAGE_ELEMS * 2;

    const int a_row = wm * 32 + (lane & 15);
    const int a_coff = (lane >> 4) * 8;
    const int b_rbase = wn * 32 + (lane & 7) + ((lane >> 4) & 1) * 8;
    const int b_coff = ((lane >> 3) & 1) * 8;

    const int niter = K >> 5;

    cp_async16(sAh, gAh);  cp_async16(sAh + rowskip, gAh + (size_t)64 * K);
    cp_async16(sBh, gBh);
    CP_COMMIT();

    for (int it = 0; it < niter; it++) {
        if (it + 1 < niter) {
            const int kn = (it + 1) << 5;
            const uint32_t so = ((it + 1) & 1) * stage_bytes;
            cp_async16(sAh + so, gAh + kn);
            cp_async16(sAh + so + rowskip, gAh + (size_t)64 * K + kn);
            cp_async16(sBh + so, gBh + kn);
            CP_COMMIT();
            CP_WAIT1();
        } else {
            CP_WAIT0();
        }
        __syncthreads();

        const __half* bs = smem + (it & 1) * STAGE_ELEMS;
        #pragma unroll
        for (int ks = 0; ks < 2; ks++) {
            uint32_t ah[2][4];
            #pragma unroll
            for (int mt = 0; mt < 2; mt++)
                ldsm_x4(ah[mt], smem_u32(bs + (a_row + mt*16) * TROWG + ks*16 + a_coff));
            #pragma unroll
            for (int np = 0; np < 2; np++) {
                uint32_t bh[4];
                ldsm_x4(bh, smem_u32(bs + AT_ELEMS + (b_rbase + np*16) * TROWG + ks*16 + b_coff));
                #pragma unroll
                for (int half = 0; half < 2; half++) {
                    const int nt = np*2 + half;
                    #pragma unroll
                    for (int mt = 0; mt < 2; mt++)
                        mma_f32acc(acc32[mt][nt], ah[mt], bh[2*half], bh[2*half+1]);
                }
            }
        }
        __syncthreads();
    }

    const int g = lane >> 2, tq = lane & 3;
    #pragma unroll
    for (int mt = 0; mt < 2; mt++) {
        const int row = bm + wm*32 + mt*16 + g;
        #pragma unroll
        for (int nt = 0; nt < 4; nt++) {
            const int col = bn + wn*32 + nt*8 + 2*tq;
            const float v00 = acc32[mt][nt][0], v01 = acc32[mt][nt][1];
            const float v10 = acc32[mt][nt][2], v11 = acc32[mt][nt][3];
            if (out_mode == 0) {
                *(float2*)(C + (size_t)row * N + col)       = make_float2(v00, v01);
                *(float2*)(C + (size_t)(row + 8) * N + col) = make_float2(v10, v11);
            } else {
                const size_t o0 = (size_t)row * N + col, o1 = (size_t)(row + 8) * N + col;
                *(__half2*)(Chi + o0) =
                    __halves2half2(__float2half_rn(v00), __float2half_rn(v01));
                *(__half2*)(Chi + o1) =
                    __halves2half2(__float2half_rn(v10), __float2half_rn(v11));
            }
        }
    }
}

// ---------------------------------------------------------------------------
// fp32 -> hi fp16, elementwise.
// ---------------------------------------------------------------------------
__global__ void convert_hi(const float4* __restrict__ in,
                           __half2* __restrict__ hi, int n4)
{
    int i = blockIdx.x * blockDim.x + threadIdx.x;
    if (i >= n4) return;
    float4 v = in[i];
    hi[2*i]   = __halves2half2(__float2half_rn(v.x), __float2half_rn(v.y));
    hi[2*i+1] = __halves2half2(__float2half_rn(v.z), __float2half_rn(v.w));
}

// ---------------------------------------------------------------------------
// Both W transposes in ONE launch (fp16 hi only).
// ---------------------------------------------------------------------------
__global__ void transpose_hi2(const float* __restrict__ Wq,
                              __half* __restrict__ Tqh,
                              const float* __restrict__ Wp,
                              __half* __restrict__ Tph)
{
    __shared__ float tile[32][33];
    const bool isq = blockIdx.x < (N3C/32);
    const int bx = isq ? blockIdx.x : blockIdx.x - (N3C/32);
    const int N = isq ? N3C : TC;
    const float* W = isq ? Wq : Wp;
    __half* Thi = isq ? Tqh : Tph;
    const int n0 = bx * 32, k0 = blockIdx.y * 32;
    const int tx = threadIdx.x, ty = threadIdx.y;
    #pragma unroll
    for (int j = 0; j < 4; j++)
        tile[ty + 8*j][tx] = W[(size_t)(k0 + ty + 8*j) * N + n0 + tx];
    __syncthreads();
    #pragma unroll
    for (int j = 0; j < 4; j++) {
        float v = tile[tx][ty + 8*j];
        size_t o = (size_t)(n0 + ty + 8*j) * TC + k0 + tx;
        Thi[o] = __float2half_rn(v);
    }
}

// ---------------------------------------------------------------------------
// Tensor-core flash attention:
//  - S = qh*kh ; PV = ph*vh (v-lo dropped, validated error model)
//  - fast-path mask: for tiles with max rel <= sp, clip==1 and rel parity
//    is a per-thread constant -> p = expf(s/8) * c[e&1]
//  - cp.async double-buffered K/V, 5 smem tiles -> 4 CTAs/SM
// ---------------------------------------------------------------------------
#define ASQ 72
#define ATILE (64*ASQ)              // elems per tile (64 rows x 72)
#define AST_ELEMS (2*ATILE)         // one K/V stage: Kh,Vh
#define ATTN_SMEM ((ATILE + 2*AST_ELEMS)*2)   // 46080 bytes

__global__ __launch_bounds__(128, 4) void attn_mma(
    const __half* __restrict__ qkvhi,
    const float* __restrict__ span_params, const float* __restrict__ stride_params,
    __half* __restrict__ yhi)
{
    extern __shared__ __half sm[];
    __half* Qh = sm;

    const int qt = blockIdx.x, h = blockIdx.y, b = blockIdx.z;
    const int t = threadIdx.x, lane = t & 31, w = t >> 5;
    const int i0 = qt * 64;

    const float sp = 1024.f / (1.f + __expf(-span_params[h]));
    const float p0 = stride_params[2*h], p1 = stride_params[2*h + 1];
    const float mxp = fmaxf(p0, p1);
    const float e0 = __expf(p0 - mxp), e1 = __expf(p1 - mxp);
    const float sw0 = e0 / (e0 + e1), sw1 = e1 / (e0 + e1);
    const float c1 = 32.f + sp;

    const int lr = t >> 1, lc = (t & 1) * 32;

    int jt0 = (int)floorf(((float)i0 - 95.f - sp) * (1.f / 64.f)) + 1;
    if (jt0 < 0) jt0 = 0;
    // tiles jt in [jt_fast_lo, qt-1] have all rel in [1, sp] -> clip == 1
    const int jt_fast_lo = qt - (int)floorf((sp - 63.f) * (1.f / 64.f));

    const size_t grow = (size_t)(b*TT) * N3C + h*THD + lc;

    // ---- prefetch first K/V stage, then load Q ----
    {
        const size_t gk = grow + (size_t)(jt0*64 + lr) * N3C + TC;
        const size_t gv = gk + TC;
        const uint32_t dst = smem_u32(sm + ATILE + (jt0 & 1) * AST_ELEMS + lr*ASQ + lc);
        #pragma unroll
        for (int i = 0; i < 4; i++) {
            cp_async16(dst + i*16,           qkvhi + gk + i*8);
            cp_async16(dst + ATILE*2 + i*16, qkvhi + gv + i*8);
        }
        CP_COMMIT();
    }
    {
        const size_t gq = grow + (size_t)(i0 + lr) * N3C;
        #pragma unroll
        for (int i = 0; i < 4; i++)
            *(uint4*)(Qh + lr*ASQ + lc + i*8) = *(const uint4*)(qkvhi + gq + i*8);
    }
    __syncthreads();

    uint32_t qfh[4][4];
    {
        const int a_row = w*16 + (lane & 15);
        const int a_coff = (lane >> 4) * 8;
        #pragma unroll
        for (int ks = 0; ks < 4; ks++)
            ldsm_x4(qfh[ks], smem_u32(Qh + a_row*ASQ + ks*16 + a_coff));
    }

    float accy[8][4];
    #pragma unroll
    for (int i = 0; i < 8; i++)
        #pragma unroll
        for (int j = 0; j < 4; j++) accy[i][j] = 0.f;
    float rs0 = 0.f, rs1 = 0.f;

    const int g = lane >> 2, tq2 = (lane & 3) * 2;
    const int q0 = i0 + w*16 + g;
    const int kb_row = (lane & 7) + ((lane >> 4) & 1) * 8;
    const int kb_coff = ((lane >> 3) & 1) * 8;
    const int vb_row = (lane & 7) + ((lane >> 3) & 1) * 8;
    const int vb_coff = (lane >> 4) * 8;

    // per-thread parity constants: parity(rel) = (q0 + tq2 + (e&1)) & 1
    const int par0 = (q0 + tq2) & 1;
    float cpar[2];
    cpar[0] = sw0 + ((par0 == 0) ? sw1 : 0.f);
    cpar[1] = sw0 + ((par0 == 0) ? 0.f : sw1);

    for (int jt = jt0; jt <= qt; jt++) {
        CP_WAIT0();
        __syncthreads();

        if (jt + 1 <= qt) {
            const size_t gk = grow + (size_t)((jt+1)*64 + lr) * N3C + TC;
            const size_t gv = gk + TC;
            const uint32_t dst = smem_u32(sm + ATILE + ((jt+1) & 1) * AST_ELEMS + lr*ASQ + lc);
            #pragma unroll
            for (int i = 0; i < 4; i++) {
                cp_async16(dst + i*16,           qkvhi + gk + i*8);
                cp_async16(dst + ATILE*2 + i*16, qkvhi + gv + i*8);
            }
            CP_COMMIT();
        }

        const __half* Kh = sm + ATILE + (jt & 1) * AST_ELEMS;
        const __half* Vh = Kh + ATILE;

        // ---- S = Q K^T (single product) ----
        float s[8][4];
        #pragma unroll
        for (int i = 0; i < 8; i++)
            #pragma unroll
            for (int j = 0; j < 4; j++) s[i][j] = 0.f;
        #pragma unroll
        for (int ks = 0; ks < 4; ks++) {
            #pragma unroll
            for (int np = 0; np < 4; np++) {
                uint32_t bh[4];
                ldsm_x4(bh, smem_u32(Kh + (np*16 + kb_row)*ASQ + ks*16 + kb_coff));
                #pragma unroll
                for (int half = 0; half < 2; half++)
                    mma_f32acc(s[np*2 + half], qfh[ks], bh[2*half], bh[2*half+1]);
            }
        }

        // ---- mask + exp + rowsum + pack P ----
        uint32_t pfh[4][4];
        const bool fastpath = (jt < qt) && (jt >= jt_fast_lo);
        if (fastpath) {
            #pragma unroll
            for (int nf = 0; nf < 8; nf++) {
                float pv[4];
                #pragma unroll
                for (int e = 0; e < 4; e++)
                    pv[e] = __expf(s[nf][e] * 0.125f) * cpar[e & 1];
                rs0 += pv[0] + pv[1];
                rs1 += pv[2] + pv[3];
                __half hh[4];
                #pragma unroll
                for (int e = 0; e < 4; e++) hh[e] = __float2half_rn(pv[e]);
                const int j = nf >> 1, odd = nf & 1;
                uint32_t ph01, ph23;
                memcpy(&ph01, &hh[0], 4); memcpy(&ph23, &hh[2], 4);
                pfh[j][2*odd]   = ph01;  pfh[j][2*odd+1] = ph23;
            }
        } else {
            #pragma unroll
            for (int nf = 0; nf < 8; nf++) {
                const int kk = jt*64 + nf*8 + tq2;
                float pv[4];
                #pragma unroll
                for (int e = 0; e < 4; e++) {
                    const int qq = q0 + (e >> 1) * 8;
                    const int kc = kk + (e & 1);
                    const int rel = qq - kc;
                    float p = 0.f;
                    if (rel >= 0) {
                        float clip = fminf(fmaxf((c1 - (float)rel) * 0.03125f, 0.f), 1.f);
                        float mk = clip * (sw0 + (((rel & 1) == 0) ? sw1 : 0.f));
                        p = __expf(s[nf][e] * 0.125f) * mk;
                    }
                    pv[e] = p;
                }
                rs0 += pv[0] + pv[1];
                rs1 += pv[2] + pv[3];
                __half hh[4];
                #pragma unroll
                for (int e = 0; e < 4; e++) hh[e] = __float2half_rn(pv[e]);
                const int j = nf >> 1, odd = nf & 1;
                uint32_t ph01, ph23;
                memcpy(&ph01, &hh[0], 4); memcpy(&ph23, &hh[2], 4);
                pfh[j][2*odd]   = ph01;  pfh[j][2*odd+1] = ph23;
            }
        }

        // ---- Y += P V (single product) ----
        #pragma unroll
        for (int ks = 0; ks < 4; ks++) {
            #pragma unroll
            for (int dnp = 0; dnp < 4; dnp++) {
                uint32_t vh[4];
                ldsm_x4t(vh, smem_u32(Vh + (ks*16 + vb_row)*ASQ + dnp*16 + vb_coff));
                #pragma unroll
                for (int half = 0; half < 2; half++)
                    mma_f32acc(accy[dnp*2 + half], pfh[ks], vh[2*half], vh[2*half+1]);
            }
        }
    }

    rs0 += __shfl_xor_sync(0xffffffffu, rs0, 1);
    rs0 += __shfl_xor_sync(0xffffffffu, rs0, 2);
    rs1 += __shfl_xor_sync(0xffffffffu, rs1, 1);
    rs1 += __shfl_xor_sync(0xffffffffu, rs1, 2);
    const float inv0 = 1.f / rs0, inv1 = 1.f / rs1;

    const size_t row0 = (size_t)(b*TT + i0 + w*16 + g);
    #pragma unroll
    for (int df = 0; df < 8; df++) {
        const int col = h*THD + df*8 + tq2;
        #pragma unroll
        for (int rr = 0; rr < 2; rr++) {
            const float inv = rr ? inv1 : inv0;
            const float v0 = accy[df][2*rr] * inv, v1 = accy[df][2*rr+1] * inv;
            const size_t off = (row0 + 8*rr) * TC + col;
            *(__half2*)(yhi + off) =
                __halves2half2(__float2half_rn(v0), __float2half_rn(v1));
        }
    }
}

// ---------------------------------------------------------------------------
__global__ void tail_kernel(const float* __restrict__ span_params,
                            float* __restrict__ out, int out_size)
{
    if (threadIdx.x == 0 && blockIdx.x == 0) {
        float s = 0.f;
        for (int i = 0; i < TH; i++)
            s += 1024.f / (1.f + expf(-span_params[i]));
        if (out_size > MR * TC)
            out[MR * TC] = 2e-6f * s / 16.f;
    }
}

extern "C" void kernel_launch(void* const* d_in, const int* in_sizes, int n_in,
                              void* d_out, int out_size)
{
    const float* x    = (const float*)d_in[0];
    const float* Wqkv = (const float*)d_in[1];
    const float* Wpr  = (const float*)d_in[2];
    const float* span = (const float*)d_in[3];
    const float* strd = (const float*)d_in[4];
    float* out = (float*)d_out;

    __half *qkvhi, *xhi, *wqh, *wph, *yhi;
    cudaGetSymbolAddress((void**)&qkvhi, g_qkvhi);
    cudaGetSymbolAddress((void**)&xhi, g_xhi);
    cudaGetSymbolAddress((void**)&wqh, g_wqkv_hi);
    cudaGetSymbolAddress((void**)&wph, g_wpr_hi);
    cudaGetSymbolAddress((void**)&yhi, g_yhi);

    static bool attr_set = false;
    if (!attr_set) {
        cudaFuncSetAttribute(gemm_mma, cudaFuncAttributeMaxDynamicSharedMemorySize, GEMM_SMEM);
        cudaFuncSetAttribute(attn_mma, cudaFuncAttributeMaxDynamicSharedMemorySize, ATTN_SMEM);
        attr_set = true;
    }

    // 0) operand prep (x hi; W hi transposed)
    convert_hi<<<(MR*TC/4 + 255)/256, 256>>>((const float4*)x, (__half2*)xhi, MR*TC/4);
    transpose_hi2<<<dim3(N3C/32 + TC/32, TC/32), dim3(32, 8)>>>(Wqkv, wqh, Wpr, wph);

    // 1) qkv = x @ Wqkv -> fp16 hi
    gemm_mma<<<dim3(N3C/64, MR/128), 256, GEMM_SMEM>>>(xhi, wqh,
        nullptr, qkvhi, 1, MR, N3C, TC);

    // 2) tensor-core flash attention -> yhi
    attn_mma<<<dim3(TT/64, TH, TB), 128, ATTN_SMEM>>>(qkvhi, span, strd, yhi);

    // 3) y = yatt @ Wproj -> d_out (fp32)
    gemm_mma<<<dim3(TC/64, MR/128), 256, GEMM_SMEM>>>(yhi, wph,
        out, nullptr, 0, MR, TC, TC);

    // 4) span_loss scalar
    tail_kernel<<<1, 32>>>(span, out, out_size);
}

// round 14
// speedup vs baseline: 2.2599x; 1.0027x over previous
#include <cuda_runtime.h>
#include <cuda_fp16.h>
#include <math.h>
#include <stdint.h>

#define TB 4
#define TT 1024
#define TC 1024
#define TH 16
#define THD 64
#define MR (TB*TT)          // 4096 rows
#define N3C (3*TC)          // 3072

// ---------------- scratch (allocation-free rule: device globals) -----------
static __device__ __half g_qkvhi[(size_t)MR * N3C];
static __device__ __half g_xhi[(size_t)MR * TC];
static __device__ __half g_wqkv_hi[(size_t)N3C * TC];   // W^T [3072,1024]
static __device__ __half g_wpr_hi[(size_t)TC * TC];     // W^T [1024,1024]
static __device__ __half g_yhi[(size_t)MR * TC];

// ---------------- PTX helpers (baseline ISA only) ---------------------------
__device__ __forceinline__ uint32_t smem_u32(const void* p) {
    uint32_t a;
    asm("{ .reg .u64 t; cvta.to.shared.u64 t, %1; cvt.u32.u64 %0, t; }" : "=r"(a) : "l"(p));
    return a;
}
__device__ __forceinline__ void ldsm_x4(uint32_t (&r)[4], uint32_t addr) {
    asm volatile("ldmatrix.sync.aligned.m8n8.x4.shared.b16 {%0,%1,%2,%3}, [%4];"
        : "=r"(r[0]), "=r"(r[1]), "=r"(r[2]), "=r"(r[3]) : "r"(addr));
}
__device__ __forceinline__ void ldsm_x4t(uint32_t (&r)[4], uint32_t addr) {
    asm volatile("ldmatrix.sync.aligned.m8n8.x4.trans.shared.b16 {%0,%1,%2,%3}, [%4];"
        : "=r"(r[0]), "=r"(r[1]), "=r"(r[2]), "=r"(r[3]) : "r"(addr));
}
// fp16 inputs, fp32 accumulate
__device__ __forceinline__ void mma_f32acc(float (&d)[4], const uint32_t (&a)[4],
                                           uint32_t b0, uint32_t b1) {
    asm volatile("mma.sync.aligned.m16n8k16.row.col.f32.f16.f16.f32 "
        "{%0,%1,%2,%3}, {%4,%5,%6,%7}, {%8,%9}, {%0,%1,%2,%3};"
        : "+f"(d[0]), "+f"(d[1]), "+f"(d[2]), "+f"(d[3])
        : "r"(a[0]), "r"(a[1]), "r"(a[2]), "r"(a[3]), "r"(b0), "r"(b1));
}
__device__ __forceinline__ float ex2f(float x) {
    float r;
    asm("ex2.approx.f32 %0, %1;" : "=f"(r) : "f"(x));
    return r;
}
#define EXPC 0.18033688f   // 0.125 * log2(e)
__device__ __forceinline__ void cp_async16(uint32_t dst, const void* src) {
    asm volatile("cp.async.cg.shared.global [%0], [%1], 16;" :: "r"(dst), "l"(src) : "memory");
}
#define CP_COMMIT() asm volatile("cp.async.commit_group;" ::: "memory")
#define CP_WAIT1()  asm volatile("cp.async.wait_group 1;" ::: "memory")
#define CP_WAIT0()  asm volatile("cp.async.wait_group 0;" ::: "memory")

// GEMM smem geometry: rows of 32 fp16 data + 8 pad = 40
#define TROWG 40
#define AT_ELEMS (128*TROWG)      // 5120
#define BT_ELEMS (64*TROWG)       // 2560
#define STAGE_ELEMS (AT_ELEMS + BT_ELEMS)   // 7680
#define GEMM_SMEM (2*STAGE_ELEMS*2)         // 30720 bytes

// ---------------------------------------------------------------------------
// Single-product fp16 GEMM:  C ~= Ahi * Bhi^T  (f32 accumulate). Unchanged.
// ---------------------------------------------------------------------------
__global__ __launch_bounds__(256, 2) void gemm_mma(
    const __half* __restrict__ Ahi, const __half* __restrict__ Bhi,
    float* __restrict__ C, __half* __restrict__ Chi,
    int out_mode, int M, int N, int K)
{
    extern __shared__ __half smem[];

    const int t = threadIdx.x, lane = t & 31, wid = t >> 5;
    const int wm = wid & 3, wn = wid >> 2;
    const int bm = blockIdx.y * 128, bn = blockIdx.x * 64;

    float acc32[2][4][4];
    #pragma unroll
    for (int i = 0; i < 2; i++)
        #pragma unroll
        for (int j = 0; j < 4; j++)
            #pragma unroll
            for (int k = 0; k < 4; k++) acc32[i][j][k] = 0.f;

    const int rA = t >> 2, cA = (t & 3) * 8;
    const __half* gAh = Ahi + (size_t)(bm + rA) * K + cA;
    const __half* gBh = Bhi + (size_t)(bn + rA) * K + cA;
    const uint32_t sAh = smem_u32(smem + rA * TROWG + cA);
    const uint32_t sBh = smem_u32(smem + AT_ELEMS + rA * TROWG + cA);
    const uint32_t rowskip = 64 * TROWG * 2;
    const uint32_t stage_bytes = STAGE_ELEMS * 2;

    const int a_row = wm * 32 + (lane & 15);
    const int a_coff = (lane >> 4) * 8;
    const int b_rbase = wn * 32 + (lane & 7) + ((lane >> 4) & 1) * 8;
    const int b_coff = ((lane >> 3) & 1) * 8;

    const int niter = K >> 5;

    cp_async16(sAh, gAh);  cp_async16(sAh + rowskip, gAh + (size_t)64 * K);
    cp_async16(sBh, gBh);
    CP_COMMIT();

    for (int it = 0; it < niter; it++) {
        if (it + 1 < niter) {
            const int kn = (it + 1) << 5;
            const uint32_t so = ((it + 1) & 1) * stage_bytes;
            cp_async16(sAh + so, gAh + kn);
            cp_async16(sAh + so + rowskip, gAh + (size_t)64 * K + kn);
            cp_async16(sBh + so, gBh + kn);
            CP_COMMIT();
            CP_WAIT1();
        } else {
            CP_WAIT0();
        }
        __syncthreads();

        const __half* bs = smem + (it & 1) * STAGE_ELEMS;
        #pragma unroll
        for (int ks = 0; ks < 2; ks++) {
            uint32_t ah[2][4];
            #pragma unroll
            for (int mt = 0; mt < 2; mt++)
                ldsm_x4(ah[mt], smem_u32(bs + (a_row + mt*16) * TROWG + ks*16 + a_coff));
            #pragma unroll
            for (int np = 0; np < 2; np++) {
                uint32_t bh[4];
                ldsm_x4(bh, smem_u32(bs + AT_ELEMS + (b_rbase + np*16) * TROWG + ks*16 + b_coff));
                #pragma unroll
                for (int half = 0; half < 2; half++) {
                    const int nt = np*2 + half;
                    #pragma unroll
                    for (int mt = 0; mt < 2; mt++)
                        mma_f32acc(acc32[mt][nt], ah[mt], bh[2*half], bh[2*half+1]);
                }
            }
        }
        __syncthreads();
    }

    const int g = lane >> 2, tq = lane & 3;
    #pragma unroll
    for (int mt = 0; mt < 2; mt++) {
        const int row = bm + wm*32 + mt*16 + g;
        #pragma unroll
        for (int nt = 0; nt < 4; nt++) {
            const int col = bn + wn*32 + nt*8 + 2*tq;
            const float v00 = acc32[mt][nt][0], v01 = acc32[mt][nt][1];
            const float v10 = acc32[mt][nt][2], v11 = acc32[mt][nt][3];
            if (out_mode == 0) {
                *(float2*)(C + (size_t)row * N + col)       = make_float2(v00, v01);
                *(float2*)(C + (size_t)(row + 8) * N + col) = make_float2(v10, v11);
            } else {
                const size_t o0 = (size_t)row * N + col, o1 = (size_t)(row + 8) * N + col;
                *(__half2*)(Chi + o0) =
                    __halves2half2(__float2half_rn(v00), __float2half_rn(v01));
                *(__half2*)(Chi + o1) =
                    __halves2half2(__float2half_rn(v10), __float2half_rn(v11));
            }
        }
    }
}

// ---------------------------------------------------------------------------
// fp32 -> hi fp16, elementwise.
// ---------------------------------------------------------------------------
__global__ void convert_hi(const float4* __restrict__ in,
                           __half2* __restrict__ hi, int n4)
{
    int i = blockIdx.x * blockDim.x + threadIdx.x;
    if (i >= n4) return;
    float4 v = in[i];
    hi[2*i]   = __halves2half2(__float2half_rn(v.x), __float2half_rn(v.y));
    hi[2*i+1] = __halves2half2(__float2half_rn(v.z), __float2half_rn(v.w));
}

// ---------------------------------------------------------------------------
// Both W transposes in ONE launch (fp16 hi only).
// ---------------------------------------------------------------------------
__global__ void transpose_hi2(const float* __restrict__ Wq,
                              __half* __restrict__ Tqh,
                              const float* __restrict__ Wp,
                              __half* __restrict__ Tph)
{
    __shared__ float tile[32][33];
    const bool isq = blockIdx.x < (N3C/32);
    const int bx = isq ? blockIdx.x : blockIdx.x - (N3C/32);
    const int N = isq ? N3C : TC;
    const float* W = isq ? Wq : Wp;
    __half* Thi = isq ? Tqh : Tph;
    const int n0 = bx * 32, k0 = blockIdx.y * 32;
    const int tx = threadIdx.x, ty = threadIdx.y;
    #pragma unroll
    for (int j = 0; j < 4; j++)
        tile[ty + 8*j][tx] = W[(size_t)(k0 + ty + 8*j) * N + n0 + tx];
    __syncthreads();
    #pragma unroll
    for (int j = 0; j < 4; j++) {
        float v = tile[tx][ty + 8*j];
        size_t o = (size_t)(n0 + ty + 8*j) * TC + k0 + tx;
        Thi[o] = __float2half_rn(v);
    }
}

// ---------------------------------------------------------------------------
// Tensor-core flash attention, Q-tile 128 (256 threads, 8 warps):
//  - each K/V tile serves 128 queries -> K/V traffic & staging overhead halve
//  - per-warp fast-path mask (all rel in [1, sp] -> clip==1, parity constant)
//  - exp via raw ex2.approx with folded constant
// ---------------------------------------------------------------------------
#define ASQ 72
#define ATILE (64*ASQ)              // 4608 elems (64 rows x 72)
#define QTILE (2*ATILE)             // 128-row Q tile
#define AST_ELEMS (2*ATILE)         // one K/V stage: Kh,Vh
#define ATTN_SMEM ((QTILE + 2*AST_ELEMS)*2)   // 55296 bytes

__global__ __launch_bounds__(256, 2) void attn_mma(
    const __half* __restrict__ qkvhi,
    const float* __restrict__ span_params, const float* __restrict__ stride_params,
    __half* __restrict__ yhi)
{
    extern __shared__ __half sm[];
    __half* Qh = sm;

    const int qt = blockIdx.x, h = blockIdx.y, b = blockIdx.z;
    const int t = threadIdx.x, lane = t & 31, w = t >> 5;
    const int i0 = qt * 128;

    const float sp = 1024.f / (1.f + __expf(-span_params[h]));
    const float p0 = stride_params[2*h], p1 = stride_params[2*h + 1];
    const float mxp = fmaxf(p0, p1);
    const float e0 = __expf(p0 - mxp), e1 = __expf(p1 - mxp);
    const float sw0 = e0 / (e0 + e1), sw1 = e1 / (e0 + e1);
    const float c1 = 32.f + sp;

    // Q staging: 128 rows, each thread loads 32 cols of one row
    const int lrq = t >> 1, lcq = (t & 1) * 32;
    // K/V staging: 64 rows, each thread loads 16 cols of one row
    const int lrk = t >> 2, lck = (t & 3) * 16;

    int jt0 = (int)floorf(((float)i0 - 95.f - sp) * (1.f / 64.f)) + 1;
    if (jt0 < 0) jt0 = 0;
    const int jt_last = (i0 + 127) >> 6;

    const size_t growk = (size_t)(b*TT) * N3C + h*THD + lck;

    // ---- prefetch first K/V stage ----
    {
        const size_t gk = growk + (size_t)(jt0*64 + lrk) * N3C + TC;
        const size_t gv = gk + TC;
        const uint32_t dst = smem_u32(sm + QTILE + (jt0 & 1) * AST_ELEMS + lrk*ASQ + lck);
        cp_async16(dst,               qkvhi + gk);
        cp_async16(dst + 16,          qkvhi + gk + 8);
        cp_async16(dst + ATILE*2,     qkvhi + gv);
        cp_async16(dst + ATILE*2+16,  qkvhi + gv + 8);
        CP_COMMIT();
    }
    // ---- load Q tile ----
    {
        const size_t gq = (size_t)(b*TT) * N3C + h*THD + lcq + (size_t)(i0 + lrq) * N3C;
        #pragma unroll
        for (int i = 0; i < 4; i++)
            *(uint4*)(Qh + lrq*ASQ + lcq + i*8) = *(const uint4*)(qkvhi + gq + i*8);
    }
    __syncthreads();

    // ---- Q fragments ----
    uint32_t qfh[4][4];
    {
        const int a_row = w*16 + (lane & 15);
        const int a_coff = (lane >> 4) * 8;
        #pragma unroll
        for (int ks = 0; ks < 4; ks++)
            ldsm_x4(qfh[ks], smem_u32(Qh + a_row*ASQ + ks*16 + a_coff));
    }

    float accy[8][4];
    #pragma unroll
    for (int i = 0; i < 8; i++)
        #pragma unroll
        for (int j = 0; j < 4; j++) accy[i][j] = 0.f;
    float rs0 = 0.f, rs1 = 0.f;

    const int g = lane >> 2, tq2 = (lane & 3) * 2;
    const int wq_lo = i0 + w*16;          // warp's lowest q row
    const int q0 = wq_lo + g;
    const int kb_row = (lane & 7) + ((lane >> 4) & 1) * 8;
    const int kb_coff = ((lane >> 3) & 1) * 8;
    const int vb_row = (lane & 7) + ((lane >> 3) & 1) * 8;
    const int vb_coff = (lane >> 4) * 8;

    const int par0 = (q0 + tq2) & 1;
    float cpar[2];
    cpar[0] = sw0 + ((par0 == 0) ? sw1 : 0.f);
    cpar[1] = sw0 + ((par0 == 0) ? 0.f : sw1);

    for (int jt = jt0; jt <= jt_last; jt++) {
        CP_WAIT0();
        __syncthreads();

        if (jt + 1 <= jt_last) {
            const size_t gk = growk + (size_t)((jt+1)*64 + lrk) * N3C + TC;
            const size_t gv = gk + TC;
            const uint32_t dst = smem_u32(sm + QTILE + ((jt+1) & 1) * AST_ELEMS + lrk*ASQ + lck);
            cp_async16(dst,               qkvhi + gk);
            cp_async16(dst + 16,          qkvhi + gk + 8);
            cp_async16(dst + ATILE*2,     qkvhi + gv);
            cp_async16(dst + ATILE*2+16,  qkvhi + gv + 8);
            CP_COMMIT();
        }

        const __half* Kh = sm + QTILE + (jt & 1) * AST_ELEMS;
        const __half* Vh = Kh + ATILE;

        // ---- S = Q K^T ----
        float s[8][4];
        #pragma unroll
        for (int i = 0; i < 8; i++)
            #pragma unroll
            for (int j = 0; j < 4; j++) s[i][j] = 0.f;
        #pragma unroll
        for (int ks = 0; ks < 4; ks++) {
            #pragma unroll
            for (int np = 0; np < 4; np++) {
                uint32_t bh[4];
                ldsm_x4(bh, smem_u32(Kh + (np*16 + kb_row)*ASQ + ks*16 + kb_coff));
                #pragma unroll
                for (int half = 0; half < 2; half++)
                    mma_f32acc(s[np*2 + half], qfh[ks], bh[2*half], bh[2*half+1]);
            }
        }

        // ---- mask + exp + rowsum + pack P ----
        uint32_t pfh[4][4];
        // per-warp fast path: all rel in [1, sp]
        const int rel_min = wq_lo - (jt*64 + 63);
        const bool fastpath = (rel_min >= 1) && ((float)(wq_lo + 15 - jt*64) <= sp);
        if (fastpath) {
            #pragma unroll
            for (int nf = 0; nf < 8; nf++) {
                float pv[4];
                #pragma unroll
                for (int e = 0; e < 4; e++)
                    pv[e] = ex2f(s[nf][e] * EXPC) * cpar[e & 1];
                rs0 += pv[0] + pv[1];
                rs1 += pv[2] + pv[3];
                __half hh[4];
                #pragma unroll
                for (int e = 0; e < 4; e++) hh[e] = __float2half_rn(pv[e]);
                const int j = nf >> 1, odd = nf & 1;
                uint32_t ph01, ph23;
                memcpy(&ph01, &hh[0], 4); memcpy(&ph23, &hh[2], 4);
                pfh[j][2*odd]   = ph01;  pfh[j][2*odd+1] = ph23;
            }
        } else {
            #pragma unroll
            for (int nf = 0; nf < 8; nf++) {
                const int kk = jt*64 + nf*8 + tq2;
                float pv[4];
                #pragma unroll
                for (int e = 0; e < 4; e++) {
                    const int qq = q0 + (e >> 1) * 8;
                    const int kc = kk + (e & 1);
                    const int rel = qq - kc;
                    float p = 0.f;
                    if (rel >= 0) {
                        float clip = fminf(fmaxf((c1 - (float)rel) * 0.03125f, 0.f), 1.f);
                        float mk = clip * (sw0 + (((rel & 1) == 0) ? sw1 : 0.f));
                        p = ex2f(s[nf][e] * EXPC) * mk;
                    }
                    pv[e] = p;
                }
                rs0 += pv[0] + pv[1];
                rs1 += pv[2] + pv[3];
                __half hh[4];
                #pragma unroll
                for (int e = 0; e < 4; e++) hh[e] = __float2half_rn(pv[e]);
                const int j = nf >> 1, odd = nf & 1;
                uint32_t ph01, ph23;
                memcpy(&ph01, &hh[0], 4); memcpy(&ph23, &hh[2], 4);
                pfh[j][2*odd]   = ph01;  pfh[j][2*odd+1] = ph23;
            }
        }

        // ---- Y += P V ----
        #pragma unroll
        for (int ks = 0; ks < 4; ks++) {
            #pragma unroll
            for (int dnp = 0; dnp < 4; dnp++) {
                uint32_t vh[4];
                ldsm_x4t(vh, smem_u32(Vh + (ks*16 + vb_row)*ASQ + dnp*16 + vb_coff));
                #pragma unroll
                for (int half = 0; half < 2; half++)
                    mma_f32acc(accy[dnp*2 + half], pfh[ks], vh[2*half], vh[2*half+1]);
            }
        }
    }

    rs0 += __shfl_xor_sync(0xffffffffu, rs0, 1);
    rs0 += __shfl_xor_sync(0xffffffffu, rs0, 2);
    rs1 += __shfl_xor_sync(0xffffffffu, rs1, 1);
    rs1 += __shfl_xor_sync(0xffffffffu, rs1, 2);
    const float inv0 = 1.f / rs0, inv1 = 1.f / rs1;

    const size_t row0 = (size_t)(b*TT + q0);
    #pragma unroll
    for (int df = 0; df < 8; df++) {
        const int col = h*THD + df*8 + tq2;
        #pragma unroll
        for (int rr = 0; rr < 2; rr++) {
            const float inv = rr ? inv1 : inv0;
            const float v0 = accy[df][2*rr] * inv, v1 = accy[df][2*rr+1] * inv;
            const size_t off = (row0 + 8*rr) * TC + col;
            *(__half2*)(yhi + off) =
                __halves2half2(__float2half_rn(v0), __float2half_rn(v1));
        }
    }
}

// ---------------------------------------------------------------------------
__global__ void tail_kernel(const float* __restrict__ span_params,
                            float* __restrict__ out, int out_size)
{
    if (threadIdx.x == 0 && blockIdx.x == 0) {
        float s = 0.f;
        for (int i = 0; i < TH; i++)
            s += 1024.f / (1.f + expf(-span_params[i]));
        if (out_size > MR * TC)
            out[MR * TC] = 2e-6f * s / 16.f;
    }
}

extern "C" void kernel_launch(void* const* d_in, const int* in_sizes, int n_in,
                              void* d_out, int out_size)
{
    const float* x    = (const float*)d_in[0];
    const float* Wqkv = (const float*)d_in[1];
    const float* Wpr  = (const float*)d_in[2];
    const float* span = (const float*)d_in[3];
    const float* strd = (const float*)d_in[4];
    float* out = (float*)d_out;

    __half *qkvhi, *xhi, *wqh, *wph, *yhi;
    cudaGetSymbolAddress((void**)&qkvhi, g_qkvhi);
    cudaGetSymbolAddress((void**)&xhi, g_xhi);
    cudaGetSymbolAddress((void**)&wqh, g_wqkv_hi);
    cudaGetSymbolAddress((void**)&wph, g_wpr_hi);
    cudaGetSymbolAddress((void**)&yhi, g_yhi);

    static bool attr_set = false;
    if (!attr_set) {
        cudaFuncSetAttribute(gemm_mma, cudaFuncAttributeMaxDynamicSharedMemorySize, GEMM_SMEM);
        cudaFuncSetAttribute(attn_mma, cudaFuncAttributeMaxDynamicSharedMemorySize, ATTN_SMEM);
        attr_set = true;
    }

    // 0) operand prep (x hi; W hi transposed)
    convert_hi<<<(MR*TC/4 + 255)/256, 256>>>((const float4*)x, (__half2*)xhi, MR*TC/4);
    transpose_hi2<<<dim3(N3C/32 + TC/32, TC/32), dim3(32, 8)>>>(Wqkv, wqh, Wpr, wph);

    // 1) qkv = x @ Wqkv -> fp16 hi
    gemm_mma<<<dim3(N3C/64, MR/128), 256, GEMM_SMEM>>>(xhi, wqh,
        nullptr, qkvhi, 1, MR, N3C, TC);

    // 2) tensor-core flash attention (Q-tile 128) -> yhi
    attn_mma<<<dim3(TT/128, TH, TB), 256, ATTN_SMEM>>>(qkvhi, span, strd, yhi);

    // 3) y = yatt @ Wproj -> d_out (fp32)
    gemm_mma<<<dim3(TC/64, MR/128), 256, GEMM_SMEM>>>(yhi, wph,
        out, nullptr, 0, MR, TC, TC);

    // 4) span_loss scalar
    tail_kernel<<<1, 32>>>(span, out, out_size);
}

// round 15
// speedup vs baseline: 2.3383x; 1.0347x over previous
#include <cuda_runtime.h>
#include <cuda_fp16.h>
#include <math.h>
#include <stdint.h>

#define TB 4
#define TT 1024
#define TC 1024
#define TH 16
#define THD 64
#define MR (TB*TT)          // 4096 rows
#define N3C (3*TC)          // 3072

// ---------------- scratch (allocation-free rule: device globals) -----------
static __device__ __half g_qkvhi[(size_t)MR * N3C];
static __device__ __half g_xhi[(size_t)MR * TC];
static __device__ __half g_wqkv_hi[(size_t)N3C * TC];   // W^T [3072,1024]
static __device__ __half g_wpr_hi[(size_t)TC * TC];     // W^T [1024,1024]
static __device__ __half g_yhi[(size_t)MR * TC];

// ---------------- PTX helpers (baseline ISA only) ---------------------------
__device__ __forceinline__ uint32_t smem_u32(const void* p) {
    uint32_t a;
    asm("{ .reg .u64 t; cvta.to.shared.u64 t, %1; cvt.u32.u64 %0, t; }" : "=r"(a) : "l"(p));
    return a;
}
__device__ __forceinline__ void ldsm_x4(uint32_t (&r)[4], uint32_t addr) {
    asm volatile("ldmatrix.sync.aligned.m8n8.x4.shared.b16 {%0,%1,%2,%3}, [%4];"
        : "=r"(r[0]), "=r"(r[1]), "=r"(r[2]), "=r"(r[3]) : "r"(addr));
}
__device__ __forceinline__ void ldsm_x4t(uint32_t (&r)[4], uint32_t addr) {
    asm volatile("ldmatrix.sync.aligned.m8n8.x4.trans.shared.b16 {%0,%1,%2,%3}, [%4];"
        : "=r"(r[0]), "=r"(r[1]), "=r"(r[2]), "=r"(r[3]) : "r"(addr));
}
// fp16 inputs, fp32 accumulate
__device__ __forceinline__ void mma_f32acc(float (&d)[4], const uint32_t (&a)[4],
                                           uint32_t b0, uint32_t b1) {
    asm volatile("mma.sync.aligned.m16n8k16.row.col.f32.f16.f16.f32 "
        "{%0,%1,%2,%3}, {%4,%5,%6,%7}, {%8,%9}, {%0,%1,%2,%3};"
        : "+f"(d[0]), "+f"(d[1]), "+f"(d[2]), "+f"(d[3])
        : "r"(a[0]), "r"(a[1]), "r"(a[2]), "r"(a[3]), "r"(b0), "r"(b1));
}
__device__ __forceinline__ float ex2f(float x) {
    float r;
    asm("ex2.approx.f32 %0, %1;" : "=f"(r) : "f"(x));
    return r;
}
__device__ __forceinline__ uint32_t pack_h2(float a, float b) {
    __half2 h = __floats2half2_rn(a, b);
    uint32_t u;
    memcpy(&u, &h, 4);
    return u;
}
#define EXPC 0.18033688f   // 0.125 * log2(e)
__device__ __forceinline__ void cp_async16(uint32_t dst, const void* src) {
    asm volatile("cp.async.cg.shared.global [%0], [%1], 16;" :: "r"(dst), "l"(src) : "memory");
}
#define CP_COMMIT() asm volatile("cp.async.commit_group;" ::: "memory")
#define CP_WAIT1()  asm volatile("cp.async.wait_group 1;" ::: "memory")
#define CP_WAIT0()  asm volatile("cp.async.wait_group 0;" ::: "memory")

// GEMM smem geometry: rows of 32 fp16 data + 8 pad = 40
#define TROWG 40
#define AT_ELEMS (128*TROWG)      // 5120
#define BT_ELEMS (64*TROWG)       // 2560
#define STAGE_ELEMS (AT_ELEMS + BT_ELEMS)   // 7680
#define GEMM_SMEM (2*STAGE_ELEMS*2)         // 30720 bytes

// ---------------------------------------------------------------------------
// Single-product fp16 GEMM:  C ~= Ahi * Bhi^T  (f32 accumulate). Unchanged.
// ---------------------------------------------------------------------------
__global__ __launch_bounds__(256, 2) void gemm_mma(
    const __half* __restrict__ Ahi, const __half* __restrict__ Bhi,
    float* __restrict__ C, __half* __restrict__ Chi,
    int out_mode, int M, int N, int K)
{
    extern __shared__ __half smem[];

    const int t = threadIdx.x, lane = t & 31, wid = t >> 5;
    const int wm = wid & 3, wn = wid >> 2;
    const int bm = blockIdx.y * 128, bn = blockIdx.x * 64;

    float acc32[2][4][4];
    #pragma unroll
    for (int i = 0; i < 2; i++)
        #pragma unroll
        for (int j = 0; j < 4; j++)
            #pragma unroll
            for (int k = 0; k < 4; k++) acc32[i][j][k] = 0.f;

    const int rA = t >> 2, cA = (t & 3) * 8;
    const __half* gAh = Ahi + (size_t)(bm + rA) * K + cA;
    const __half* gBh = Bhi + (size_t)(bn + rA) * K + cA;
    const uint32_t sAh = smem_u32(smem + rA * TROWG + cA);
    const uint32_t sBh = smem_u32(smem + AT_ELEMS + rA * TROWG + cA);
    const uint32_t rowskip = 64 * TROWG * 2;
    const uint32_t stage_bytes = STAGE_ELEMS * 2;

    const int a_row = wm * 32 + (lane & 15);
    const int a_coff = (lane >> 4) * 8;
    const int b_rbase = wn * 32 + (lane & 7) + ((lane >> 4) & 1) * 8;
    const int b_coff = ((lane >> 3) & 1) * 8;

    const int niter = K >> 5;

    cp_async16(sAh, gAh);  cp_async16(sAh + rowskip, gAh + (size_t)64 * K);
    cp_async16(sBh, gBh);
    CP_COMMIT();

    for (int it = 0; it < niter; it++) {
        if (it + 1 < niter) {
            const int kn = (it + 1) << 5;
            const uint32_t so = ((it + 1) & 1) * stage_bytes;
            cp_async16(sAh + so, gAh + kn);
            cp_async16(sAh + so + rowskip, gAh + (size_t)64 * K + kn);
            cp_async16(sBh + so, gBh + kn);
            CP_COMMIT();
            CP_WAIT1();
        } else {
            CP_WAIT0();
        }
        __syncthreads();

        const __half* bs = smem + (it & 1) * STAGE_ELEMS;
        #pragma unroll
        for (int ks = 0; ks < 2; ks++) {
            uint32_t ah[2][4];
            #pragma unroll
            for (int mt = 0; mt < 2; mt++)
                ldsm_x4(ah[mt], smem_u32(bs + (a_row + mt*16) * TROWG + ks*16 + a_coff));
            #pragma unroll
            for (int np = 0; np < 2; np++) {
                uint32_t bh[4];
                ldsm_x4(bh, smem_u32(bs + AT_ELEMS + (b_rbase + np*16) * TROWG + ks*16 + b_coff));
                #pragma unroll
                for (int half = 0; half < 2; half++) {
                    const int nt = np*2 + half;
                    #pragma unroll
                    for (int mt = 0; mt < 2; mt++)
                        mma_f32acc(acc32[mt][nt], ah[mt], bh[2*half], bh[2*half+1]);
                }
            }
        }
        __syncthreads();
    }

    const int g = lane >> 2, tq = lane & 3;
    #pragma unroll
    for (int mt = 0; mt < 2; mt++) {
        const int row = bm + wm*32 + mt*16 + g;
        #pragma unroll
        for (int nt = 0; nt < 4; nt++) {
            const int col = bn + wn*32 + nt*8 + 2*tq;
            const float v00 = acc32[mt][nt][0], v01 = acc32[mt][nt][1];
            const float v10 = acc32[mt][nt][2], v11 = acc32[mt][nt][3];
            if (out_mode == 0) {
                *(float2*)(C + (size_t)row * N + col)       = make_float2(v00, v01);
                *(float2*)(C + (size_t)(row + 8) * N + col) = make_float2(v10, v11);
            } else {
                const size_t o0 = (size_t)row * N + col, o1 = (size_t)(row + 8) * N + col;
                *(uint32_t*)(Chi + o0) = pack_h2(v00, v01);
                *(uint32_t*)(Chi + o1) = pack_h2(v10, v11);
            }
        }
    }
}

// ---------------------------------------------------------------------------
// Fused prep: blocks [0, NCONV) convert x -> fp16 hi; blocks [NCONV, ...)
// transpose W matrices to fp16 hi; block NCONV thread 0 also writes span_loss.
// ---------------------------------------------------------------------------
#define NCONV (MR*TC/4/256)            // 4096 convert blocks
#define NTRX  (N3C/32 + TC/32)         // 128 transpose x-blocks
__global__ void prep_kernel(const float4* __restrict__ x4,
                            __half2* __restrict__ xhi,
                            const float* __restrict__ Wq,
                            __half* __restrict__ Tqh,
                            const float* __restrict__ Wp,
                            __half* __restrict__ Tph,
                            const float* __restrict__ span_params,
                            float* __restrict__ out, int out_size)
{
    const int bid = blockIdx.x;
    const int t = threadIdx.x;
    if (bid < NCONV) {
        const int i = bid * 256 + t;
        float4 v = x4[i];
        xhi[2*i]   = __floats2half2_rn(v.x, v.y);
        xhi[2*i+1] = __floats2half2_rn(v.z, v.w);
        return;
    }
    if (bid == NCONV && t == 0 && out_size > MR * TC) {
        float s = 0.f;
        for (int i = 0; i < TH; i++)
            s += 1024.f / (1.f + expf(-span_params[i]));
        out[MR * TC] = 2e-6f * s / 16.f;
    }
    // transpose region
    __shared__ float tile[32][33];
    const int idx = bid - NCONV;
    const int bxx = idx % NTRX, by = idx / NTRX;
    const bool isq = bxx < (N3C/32);
    const int bx = isq ? bxx : bxx - (N3C/32);
    const int N = isq ? N3C : TC;
    const float* W = isq ? Wq : Wp;
    __half* Thi = isq ? Tqh : Tph;
    const int n0 = bx * 32, k0 = by * 32;
    const int tx = t & 31, ty = t >> 5;
    #pragma unroll
    for (int j = 0; j < 4; j++)
        tile[ty + 8*j][tx] = W[(size_t)(k0 + ty + 8*j) * N + n0 + tx];
    __syncthreads();
    #pragma unroll
    for (int j = 0; j < 4; j++) {
        float v = tile[tx][ty + 8*j];
        size_t o = (size_t)(n0 + ty + 8*j) * TC + k0 + tx;
        Thi[o] = __float2half_rn(v);
    }
}

// ---------------------------------------------------------------------------
// Tensor-core flash attention, Q-tile 128 (256 threads, 8 warps):
//  - fast-path mask folded into exponent: p = ex2(fma(s, C, log2(cpar)))
//  - packed f32->f16x2 conversions everywhere
// ---------------------------------------------------------------------------
#define ASQ 72
#define ATILE (64*ASQ)              // 4608 elems (64 rows x 72)
#define QTILE (2*ATILE)             // 128-row Q tile
#define AST_ELEMS (2*ATILE)         // one K/V stage: Kh,Vh
#define ATTN_SMEM ((QTILE + 2*AST_ELEMS)*2)   // 55296 bytes

__global__ __launch_bounds__(256, 2) void attn_mma(
    const __half* __restrict__ qkvhi,
    const float* __restrict__ span_params, const float* __restrict__ stride_params,
    __half* __restrict__ yhi)
{
    extern __shared__ __half sm[];
    __half* Qh = sm;

    const int qt = blockIdx.x, h = blockIdx.y, b = blockIdx.z;
    const int t = threadIdx.x, lane = t & 31, w = t >> 5;
    const int i0 = qt * 128;

    const float sp = 1024.f / (1.f + __expf(-span_params[h]));
    const float p0 = stride_params[2*h], p1 = stride_params[2*h + 1];
    const float mxp = fmaxf(p0, p1);
    const float e0 = __expf(p0 - mxp), e1 = __expf(p1 - mxp);
    const float sw0 = e0 / (e0 + e1), sw1 = e1 / (e0 + e1);
    const float c1 = 32.f + sp;

    const int lrq = t >> 1, lcq = (t & 1) * 32;
    const int lrk = t >> 2, lck = (t & 3) * 16;

    int jt0 = (int)floorf(((float)i0 - 95.f - sp) * (1.f / 64.f)) + 1;
    if (jt0 < 0) jt0 = 0;
    const int jt_last = (i0 + 127) >> 6;

    const size_t growk = (size_t)(b*TT) * N3C + h*THD + lck;

    {
        const size_t gk = growk + (size_t)(jt0*64 + lrk) * N3C + TC;
        const size_t gv = gk + TC;
        const uint32_t dst = smem_u32(sm + QTILE + (jt0 & 1) * AST_ELEMS + lrk*ASQ + lck);
        cp_async16(dst,               qkvhi + gk);
        cp_async16(dst + 16,          qkvhi + gk + 8);
        cp_async16(dst + ATILE*2,     qkvhi + gv);
        cp_async16(dst + ATILE*2+16,  qkvhi + gv + 8);
        CP_COMMIT();
    }
    {
        const size_t gq = (size_t)(b*TT) * N3C + h*THD + lcq + (size_t)(i0 + lrq) * N3C;
        #pragma unroll
        for (int i = 0; i < 4; i++)
            *(uint4*)(Qh + lrq*ASQ + lcq + i*8) = *(const uint4*)(qkvhi + gq + i*8);
    }
    __syncthreads();

    uint32_t qfh[4][4];
    {
        const int a_row = w*16 + (lane & 15);
        const int a_coff = (lane >> 4) * 8;
        #pragma unroll
        for (int ks = 0; ks < 4; ks++)
            ldsm_x4(qfh[ks], smem_u32(Qh + a_row*ASQ + ks*16 + a_coff));
    }

    float accy[8][4];
    #pragma unroll
    for (int i = 0; i < 8; i++)
        #pragma unroll
        for (int j = 0; j < 4; j++) accy[i][j] = 0.f;
    float rs0 = 0.f, rs1 = 0.f;

    const int g = lane >> 2, tq2 = (lane & 3) * 2;
    const int wq_lo = i0 + w*16;
    const int q0 = wq_lo + g;
    const int kb_row = (lane & 7) + ((lane >> 4) & 1) * 8;
    const int kb_coff = ((lane >> 3) & 1) * 8;
    const int vb_row = (lane & 7) + ((lane >> 3) & 1) * 8;
    const int vb_coff = (lane >> 4) * 8;

    const int par0 = (q0 + tq2) & 1;
    float cpar[2];
    cpar[0] = sw0 + ((par0 == 0) ? sw1 : 0.f);
    cpar[1] = sw0 + ((par0 == 0) ? 0.f : sw1);
    // log2 of mask constants, folded into ex2 argument on the fast path
    const float lc[2] = { __log2f(cpar[0]), __log2f(cpar[1]) };

    for (int jt = jt0; jt <= jt_last; jt++) {
        CP_WAIT0();
        __syncthreads();

        if (jt + 1 <= jt_last) {
            const size_t gk = growk + (size_t)((jt+1)*64 + lrk) * N3C + TC;
            const size_t gv = gk + TC;
            const uint32_t dst = smem_u32(sm + QTILE + ((jt+1) & 1) * AST_ELEMS + lrk*ASQ + lck);
            cp_async16(dst,               qkvhi + gk);
            cp_async16(dst + 16,          qkvhi + gk + 8);
            cp_async16(dst + ATILE*2,     qkvhi + gv);
            cp_async16(dst + ATILE*2+16,  qkvhi + gv + 8);
            CP_COMMIT();
        }

        const __half* Kh = sm + QTILE + (jt & 1) * AST_ELEMS;
        const __half* Vh = Kh + ATILE;

        // ---- S = Q K^T ----
        float s[8][4];
        #pragma unroll
        for (int i = 0; i < 8; i++)
            #pragma unroll
            for (int j = 0; j < 4; j++) s[i][j] = 0.f;
        #pragma unroll
        for (int ks = 0; ks < 4; ks++) {
            #pragma unroll
            for (int np = 0; np < 4; np++) {
                uint32_t bh[4];
                ldsm_x4(bh, smem_u32(Kh + (np*16 + kb_row)*ASQ + ks*16 + kb_coff));
                #pragma unroll
                for (int half = 0; half < 2; half++)
                    mma_f32acc(s[np*2 + half], qfh[ks], bh[2*half], bh[2*half+1]);
            }
        }

        // ---- mask + exp + rowsum + pack P ----
        uint32_t pfh[4][4];
        const int rel_min = wq_lo - (jt*64 + 63);
        const bool fastpath = (rel_min >= 1) && ((float)(wq_lo + 15 - jt*64) <= sp);
        if (fastpath) {
            #pragma unroll
            for (int nf = 0; nf < 8; nf++) {
                float pv[4];
                #pragma unroll
                for (int e = 0; e < 4; e++)
                    pv[e] = ex2f(fmaf(s[nf][e], EXPC, lc[e & 1]));
                rs0 += pv[0] + pv[1];
                rs1 += pv[2] + pv[3];
                const int j = nf >> 1, odd = nf & 1;
                pfh[j][2*odd]   = pack_h2(pv[0], pv[1]);
                pfh[j][2*odd+1] = pack_h2(pv[2], pv[3]);
            }
        } else {
            #pragma unroll
            for (int nf = 0; nf < 8; nf++) {
                const int kk = jt*64 + nf*8 + tq2;
                float pv[4];
                #pragma unroll
                for (int e = 0; e < 4; e++) {
                    const int qq = q0 + (e >> 1) * 8;
                    const int kc = kk + (e & 1);
                    const int rel = qq - kc;
                    float p = 0.f;
                    if (rel >= 0) {
                        float clip = fminf(fmaxf((c1 - (float)rel) * 0.03125f, 0.f), 1.f);
                        float mk = clip * (sw0 + (((rel & 1) == 0) ? sw1 : 0.f));
                        p = ex2f(s[nf][e] * EXPC) * mk;
                    }
                    pv[e] = p;
                }
                rs0 += pv[0] + pv[1];
                rs1 += pv[2] + pv[3];
                const int j = nf >> 1, odd = nf & 1;
                pfh[j][2*odd]   = pack_h2(pv[0], pv[1]);
                pfh[j][2*odd+1] = pack_h2(pv[2], pv[3]);
            }
        }

        // ---- Y += P V ----
        #pragma unroll
        for (int ks = 0; ks < 4; ks++) {
            #pragma unroll
            for (int dnp = 0; dnp < 4; dnp++) {
                uint32_t vh[4];
                ldsm_x4t(vh, smem_u32(Vh + (ks*16 + vb_row)*ASQ + dnp*16 + vb_coff));
                #pragma unroll
                for (int half = 0; half < 2; half++)
                    mma_f32acc(accy[dnp*2 + half], pfh[ks], vh[2*half], vh[2*half+1]);
            }
        }
    }

    rs0 += __shfl_xor_sync(0xffffffffu, rs0, 1);
    rs0 += __shfl_xor_sync(0xffffffffu, rs0, 2);
    rs1 += __shfl_xor_sync(0xffffffffu, rs1, 1);
    rs1 += __shfl_xor_sync(0xffffffffu, rs1, 2);
    const float inv0 = 1.f / rs0, inv1 = 1.f / rs1;

    const size_t row0 = (size_t)(b*TT + q0);
    #pragma unroll
    for (int df = 0; df < 8; df++) {
        const int col = h*THD + df*8 + tq2;
        #pragma unroll
        for (int rr = 0; rr < 2; rr++) {
            const float inv = rr ? inv1 : inv0;
            const size_t off = (row0 + 8*rr) * TC + col;
            *(uint32_t*)(yhi + off) =
                pack_h2(accy[df][2*rr] * inv, accy[df][2*rr+1] * inv);
        }
    }
}

extern "C" void kernel_launch(void* const* d_in, const int* in_sizes, int n_in,
                              void* d_out, int out_size)
{
    const float* x    = (const float*)d_in[0];
    const float* Wqkv = (const float*)d_in[1];
    const float* Wpr  = (const float*)d_in[2];
    const float* span = (const float*)d_in[3];
    const float* strd = (const float*)d_in[4];
    float* out = (float*)d_out;

    __half *qkvhi, *xhi, *wqh, *wph, *yhi;
    cudaGetSymbolAddress((void**)&qkvhi, g_qkvhi);
    cudaGetSymbolAddress((void**)&xhi, g_xhi);
    cudaGetSymbolAddress((void**)&wqh, g_wqkv_hi);
    cudaGetSymbolAddress((void**)&wph, g_wpr_hi);
    cudaGetSymbolAddress((void**)&yhi, g_yhi);

    static bool attr_set = false;
    if (!attr_set) {
        cudaFuncSetAttribute(gemm_mma, cudaFuncAttributeMaxDynamicSharedMemorySize, GEMM_SMEM);
        cudaFuncSetAttribute(attn_mma, cudaFuncAttributeMaxDynamicSharedMemorySize, ATTN_SMEM);
        attr_set = true;
    }

    // 0) fused prep: x -> fp16 hi, W transposes, span_loss scalar
    prep_kernel<<<NCONV + NTRX * (TC/32), 256>>>(
        (const float4*)x, (__half2*)xhi, Wqkv, wqh, Wpr, wph, span, out, out_size);

    // 1) qkv = x @ Wqkv -> fp16 hi
    gemm_mma<<<dim3(N3C/64, MR/128), 256, GEMM_SMEM>>>(xhi, wqh,
        nullptr, qkvhi, 1, MR, N3C, TC);

    // 2) tensor-core flash attention (Q-tile 128) -> yhi
    attn_mma<<<dim3(TT/128, TH, TB), 256, ATTN_SMEM>>>(qkvhi, span, strd, yhi);

    // 3) y = yatt @ Wproj -> d_out (fp32)
    gemm_mma<<<dim3(TC/64, MR/128), 256, GEMM_SMEM>>>(yhi, wph,
        out, nullptr, 0, MR, TC, TC);
}

// round 16
// speedup vs baseline: 2.4046x; 1.0284x over previous
#include <cuda_runtime.h>
#include <cuda_fp16.h>
#include <math.h>
#include <stdint.h>

#define TB 4
#define TT 1024
#define TC 1024
#define TH 16
#define THD 64
#define MR (TB*TT)          // 4096 rows
#define N3C (3*TC)          // 3072

// ---------------- scratch (allocation-free rule: device globals) -----------
static __device__ __half g_qkvhi[(size_t)MR * N3C];
static __device__ __half g_xhi[(size_t)MR * TC];
static __device__ __half g_wqkv_hi[(size_t)N3C * TC];   // W^T [3072,1024]
static __device__ __half g_wpr_hi[(size_t)TC * TC];     // W^T [1024,1024]
static __device__ __half g_yhi[(size_t)MR * TC];

// ---------------- PTX helpers (baseline ISA only) ---------------------------
__device__ __forceinline__ uint32_t smem_u32(const void* p) {
    uint32_t a;
    asm("{ .reg .u64 t; cvta.to.shared.u64 t, %1; cvt.u32.u64 %0, t; }" : "=r"(a) : "l"(p));
    return a;
}
__device__ __forceinline__ void ldsm_x4(uint32_t (&r)[4], uint32_t addr) {
    asm volatile("ldmatrix.sync.aligned.m8n8.x4.shared.b16 {%0,%1,%2,%3}, [%4];"
        : "=r"(r[0]), "=r"(r[1]), "=r"(r[2]), "=r"(r[3]) : "r"(addr));
}
__device__ __forceinline__ void ldsm_x4t(uint32_t (&r)[4], uint32_t addr) {
    asm volatile("ldmatrix.sync.aligned.m8n8.x4.trans.shared.b16 {%0,%1,%2,%3}, [%4];"
        : "=r"(r[0]), "=r"(r[1]), "=r"(r[2]), "=r"(r[3]) : "r"(addr));
}
// fp16 inputs, fp32 accumulate
__device__ __forceinline__ void mma_f32acc(float (&d)[4], const uint32_t (&a)[4],
                                           uint32_t b0, uint32_t b1) {
    asm volatile("mma.sync.aligned.m16n8k16.row.col.f32.f16.f16.f32 "
        "{%0,%1,%2,%3}, {%4,%5,%6,%7}, {%8,%9}, {%0,%1,%2,%3};"
        : "+f"(d[0]), "+f"(d[1]), "+f"(d[2]), "+f"(d[3])
        : "r"(a[0]), "r"(a[1]), "r"(a[2]), "r"(a[3]), "r"(b0), "r"(b1));
}
__device__ __forceinline__ uint32_t pack_h2(float a, float b) {
    __half2 h = __floats2half2_rn(a, b);
    uint32_t u;
    memcpy(&u, &h, 4);
    return u;
}
__device__ __forceinline__ uint32_t ex2_h2(uint32_t a) {
    uint32_t r;
    asm("ex2.approx.f16x2 %0, %1;" : "=r"(r) : "r"(a));
    return r;
}
__device__ __forceinline__ uint32_t hmul2(uint32_t a, uint32_t b) {
    uint32_t r;
    asm("mul.f16x2 %0, %1, %2;" : "=r"(r) : "r"(a), "r"(b));
    return r;
}
#define EXPC 0.18033688f   // 0.125 * log2(e)
#define ONES2 0x3C003C00u  // half2(1.0, 1.0)
__device__ __forceinline__ void cp_async16(uint32_t dst, const void* src) {
    asm volatile("cp.async.cg.shared.global [%0], [%1], 16;" :: "r"(dst), "l"(src) : "memory");
}
#define CP_COMMIT() asm volatile("cp.async.commit_group;" ::: "memory")
#define CP_WAIT1()  asm volatile("cp.async.wait_group 1;" ::: "memory")
#define CP_WAIT0()  asm volatile("cp.async.wait_group 0;" ::: "memory")

// GEMM smem geometry: rows of 32 fp16 data + 8 pad = 40
#define TROWG 40
#define AT_ELEMS (128*TROWG)      // 5120
#define BT_ELEMS (64*TROWG)       // 2560
#define STAGE_ELEMS (AT_ELEMS + BT_ELEMS)   // 7680
#define GEMM_SMEM (2*STAGE_ELEMS*2)         // 30720 bytes

// ---------------------------------------------------------------------------
// Single-product fp16 GEMM:  C ~= Ahi * Bhi^T  (f32 accumulate). Unchanged.
// ---------------------------------------------------------------------------
__global__ __launch_bounds__(256, 2) void gemm_mma(
    const __half* __restrict__ Ahi, const __half* __restrict__ Bhi,
    float* __restrict__ C, __half* __restrict__ Chi,
    int out_mode, int M, int N, int K)
{
    extern __shared__ __half smem[];

    const int t = threadIdx.x, lane = t & 31, wid = t >> 5;
    const int wm = wid & 3, wn = wid >> 2;
    const int bm = blockIdx.y * 128, bn = blockIdx.x * 64;

    float acc32[2][4][4];
    #pragma unroll
    for (int i = 0; i < 2; i++)
        #pragma unroll
        for (int j = 0; j < 4; j++)
            #pragma unroll
            for (int k = 0; k < 4; k++) acc32[i][j][k] = 0.f;

    const int rA = t >> 2, cA = (t & 3) * 8;
    const __half* gAh = Ahi + (size_t)(bm + rA) * K + cA;
    const __half* gBh = Bhi + (size_t)(bn + rA) * K + cA;
    const uint32_t sAh = smem_u32(smem + rA * TROWG + cA);
    const uint32_t sBh = smem_u32(smem + AT_ELEMS + rA * TROWG + cA);
    const uint32_t rowskip = 64 * TROWG * 2;
    const uint32_t stage_bytes = STAGE_ELEMS * 2;

    const int a_row = wm * 32 + (lane & 15);
    const int a_coff = (lane >> 4) * 8;
    const int b_rbase = wn * 32 + (lane & 7) + ((lane >> 4) & 1) * 8;
    const int b_coff = ((lane >> 3) & 1) * 8;

    const int niter = K >> 5;

    cp_async16(sAh, gAh);  cp_async16(sAh + rowskip, gAh + (size_t)64 * K);
    cp_async16(sBh, gBh);
    CP_COMMIT();

    for (int it = 0; it < niter; it++) {
        if (it + 1 < niter) {
            const int kn = (it + 1) << 5;
            const uint32_t so = ((it + 1) & 1) * stage_bytes;
            cp_async16(sAh + so, gAh + kn);
            cp_async16(sAh + so + rowskip, gAh + (size_t)64 * K + kn);
            cp_async16(sBh + so, gBh + kn);
            CP_COMMIT();
            CP_WAIT1();
        } else {
            CP_WAIT0();
        }
        __syncthreads();

        const __half* bs = smem + (it & 1) * STAGE_ELEMS;
        #pragma unroll
        for (int ks = 0; ks < 2; ks++) {
            uint32_t ah[2][4];
            #pragma unroll
            for (int mt = 0; mt < 2; mt++)
                ldsm_x4(ah[mt], smem_u32(bs + (a_row + mt*16) * TROWG + ks*16 + a_coff));
            #pragma unroll
            for (int np = 0; np < 2; np++) {
                uint32_t bh[4];
                ldsm_x4(bh, smem_u32(bs + AT_ELEMS + (b_rbase + np*16) * TROWG + ks*16 + b_coff));
                #pragma unroll
                for (int half = 0; half < 2; half++) {
                    const int nt = np*2 + half;
                    #pragma unroll
                    for (int mt = 0; mt < 2; mt++)
                        mma_f32acc(acc32[mt][nt], ah[mt], bh[2*half], bh[2*half+1]);
                }
            }
        }
        __syncthreads();
    }

    const int g = lane >> 2, tq = lane & 3;
    #pragma unroll
    for (int mt = 0; mt < 2; mt++) {
        const int row = bm + wm*32 + mt*16 + g;
        #pragma unroll
        for (int nt = 0; nt < 4; nt++) {
            const int col = bn + wn*32 + nt*8 + 2*tq;
            const float v00 = acc32[mt][nt][0], v01 = acc32[mt][nt][1];
            const float v10 = acc32[mt][nt][2], v11 = acc32[mt][nt][3];
            if (out_mode == 0) {
                *(float2*)(C + (size_t)row * N + col)       = make_float2(v00, v01);
                *(float2*)(C + (size_t)(row + 8) * N + col) = make_float2(v10, v11);
            } else {
                const size_t o0 = (size_t)row * N + col, o1 = (size_t)(row + 8) * N + col;
                *(uint32_t*)(Chi + o0) = pack_h2(v00, v01);
                *(uint32_t*)(Chi + o1) = pack_h2(v10, v11);
            }
        }
    }
}

// ---------------------------------------------------------------------------
// Fused prep: convert x -> fp16 hi; transpose W to fp16 hi; span_loss scalar.
// ---------------------------------------------------------------------------
#define NCONV (MR*TC/4/256)            // 4096 convert blocks
#define NTRX  (N3C/32 + TC/32)         // 128 transpose x-blocks
__global__ void prep_kernel(const float4* __restrict__ x4,
                            __half2* __restrict__ xhi,
                            const float* __restrict__ Wq,
                            __half* __restrict__ Tqh,
                            const float* __restrict__ Wp,
                            __half* __restrict__ Tph,
                            const float* __restrict__ span_params,
                            float* __restrict__ out, int out_size)
{
    const int bid = blockIdx.x;
    const int t = threadIdx.x;
    if (bid < NCONV) {
        const int i = bid * 256 + t;
        float4 v = x4[i];
        xhi[2*i]   = __floats2half2_rn(v.x, v.y);
        xhi[2*i+1] = __floats2half2_rn(v.z, v.w);
        return;
    }
    if (bid == NCONV && t == 0 && out_size > MR * TC) {
        float s = 0.f;
        for (int i = 0; i < TH; i++)
            s += 1024.f / (1.f + expf(-span_params[i]));
        out[MR * TC] = 2e-6f * s / 16.f;
    }
    __shared__ float tile[32][33];
    const int idx = bid - NCONV;
    const int bxx = idx % NTRX, by = idx / NTRX;
    const bool isq = bxx < (N3C/32);
    const int bx = isq ? bxx : bxx - (N3C/32);
    const int N = isq ? N3C : TC;
    const float* W = isq ? Wq : Wp;
    __half* Thi = isq ? Tqh : Tph;
    const int n0 = bx * 32, k0 = by * 32;
    const int tx = t & 31, ty = t >> 5;
    #pragma unroll
    for (int j = 0; j < 4; j++)
        tile[ty + 8*j][tx] = W[(size_t)(k0 + ty + 8*j) * N + n0 + tx];
    __syncthreads();
    #pragma unroll
    for (int j = 0; j < 4; j++) {
        float v = tile[tx][ty + 8*j];
        size_t o = (size_t)(n0 + ty + 8*j) * TC + k0 + tx;
        Thi[o] = __float2half_rn(v);
    }
}

// ---------------------------------------------------------------------------
// Tensor-core flash attention, Q-tile 128 (256 threads, 8 warps):
//  - exp via ex2.approx.f16x2 (one MUFU per 2 elements; arg computed in f32)
//  - row sums via extra mma with ones-B (no FADDs, no final shuffle)
// ---------------------------------------------------------------------------
#define ASQ 72
#define ATILE (64*ASQ)              // 4608 elems (64 rows x 72)
#define QTILE (2*ATILE)             // 128-row Q tile
#define AST_ELEMS (2*ATILE)         // one K/V stage: Kh,Vh
#define ATTN_SMEM ((QTILE + 2*AST_ELEMS)*2)   // 55296 bytes

__global__ __launch_bounds__(256, 2) void attn_mma(
    const __half* __restrict__ qkvhi,
    const float* __restrict__ span_params, const float* __restrict__ stride_params,
    __half* __restrict__ yhi)
{
    extern __shared__ __half sm[];
    __half* Qh = sm;

    const int qt = blockIdx.x, h = blockIdx.y, b = blockIdx.z;
    const int t = threadIdx.x, lane = t & 31, w = t >> 5;
    const int i0 = qt * 128;

    const float sp = 1024.f / (1.f + __expf(-span_params[h]));
    const float p0 = stride_params[2*h], p1 = stride_params[2*h + 1];
    const float mxp = fmaxf(p0, p1);
    const float e0 = __expf(p0 - mxp), e1 = __expf(p1 - mxp);
    const float sw0 = e0 / (e0 + e1), sw1 = e1 / (e0 + e1);
    const float c1 = 32.f + sp;

    const int lrq = t >> 1, lcq = (t & 1) * 32;
    const int lrk = t >> 2, lck = (t & 3) * 16;

    int jt0 = (int)floorf(((float)i0 - 95.f - sp) * (1.f / 64.f)) + 1;
    if (jt0 < 0) jt0 = 0;
    const int jt_last = (i0 + 127) >> 6;

    const size_t growk = (size_t)(b*TT) * N3C + h*THD + lck;

    {
        const size_t gk = growk + (size_t)(jt0*64 + lrk) * N3C + TC;
        const size_t gv = gk + TC;
        const uint32_t dst = smem_u32(sm + QTILE + (jt0 & 1) * AST_ELEMS + lrk*ASQ + lck);
        cp_async16(dst,               qkvhi + gk);
        cp_async16(dst + 16,          qkvhi + gk + 8);
        cp_async16(dst + ATILE*2,     qkvhi + gv);
        cp_async16(dst + ATILE*2+16,  qkvhi + gv + 8);
        CP_COMMIT();
    }
    {
        const size_t gq = (size_t)(b*TT) * N3C + h*THD + lcq + (size_t)(i0 + lrq) * N3C;
        #pragma unroll
        for (int i = 0; i < 4; i++)
            *(uint4*)(Qh + lrq*ASQ + lcq + i*8) = *(const uint4*)(qkvhi + gq + i*8);
    }
    __syncthreads();

    uint32_t qfh[4][4];
    {
        const int a_row = w*16 + (lane & 15);
        const int a_coff = (lane >> 4) * 8;
        #pragma unroll
        for (int ks = 0; ks < 4; ks++)
            ldsm_x4(qfh[ks], smem_u32(Qh + a_row*ASQ + ks*16 + a_coff));
    }

    float accy[8][4];
    #pragma unroll
    for (int i = 0; i < 8; i++)
        #pragma unroll
        for (int j = 0; j < 4; j++) accy[i][j] = 0.f;
    float rsacc[4] = {0.f, 0.f, 0.f, 0.f};   // rowsums via ones-mma

    const int g = lane >> 2, tq2 = (lane & 3) * 2;
    const int wq_lo = i0 + w*16;
    const int q0 = wq_lo + g;
    const int kb_row = (lane & 7) + ((lane >> 4) & 1) * 8;
    const int kb_coff = ((lane >> 3) & 1) * 8;
    const int vb_row = (lane & 7) + ((lane >> 3) & 1) * 8;
    const int vb_coff = (lane >> 4) * 8;

    const int par0 = (q0 + tq2) & 1;
    const float cp0 = sw0 + ((par0 == 0) ? sw1 : 0.f);
    const float cp1 = sw0 + ((par0 == 0) ? 0.f : sw1);
    const float lc[2] = { __log2f(cp0), __log2f(cp1) };

    for (int jt = jt0; jt <= jt_last; jt++) {
        CP_WAIT0();
        __syncthreads();

        if (jt + 1 <= jt_last) {
            const size_t gk = growk + (size_t)((jt+1)*64 + lrk) * N3C + TC;
            const size_t gv = gk + TC;
            const uint32_t dst = smem_u32(sm + QTILE + ((jt+1) & 1) * AST_ELEMS + lrk*ASQ + lck);
            cp_async16(dst,               qkvhi + gk);
            cp_async16(dst + 16,          qkvhi + gk + 8);
            cp_async16(dst + ATILE*2,     qkvhi + gv);
            cp_async16(dst + ATILE*2+16,  qkvhi + gv + 8);
            CP_COMMIT();
        }

        const __half* Kh = sm + QTILE + (jt & 1) * AST_ELEMS;
        const __half* Vh = Kh + ATILE;

        // ---- S = Q K^T ----
        float s[8][4];
        #pragma unroll
        for (int i = 0; i < 8; i++)
            #pragma unroll
            for (int j = 0; j < 4; j++) s[i][j] = 0.f;
        #pragma unroll
        for (int ks = 0; ks < 4; ks++) {
            #pragma unroll
            for (int np = 0; np < 4; np++) {
                uint32_t bh[4];
                ldsm_x4(bh, smem_u32(Kh + (np*16 + kb_row)*ASQ + ks*16 + kb_coff));
                #pragma unroll
                for (int half = 0; half < 2; half++)
                    mma_f32acc(s[np*2 + half], qfh[ks], bh[2*half], bh[2*half+1]);
            }
        }

        // ---- mask + exp (f16x2) + pack P ----
        uint32_t pfh[4][4];
        const int rel_min = wq_lo - (jt*64 + 63);
        const bool fastpath = (rel_min >= 1) && ((float)(wq_lo + 15 - jt*64) <= sp);
        if (fastpath) {
            #pragma unroll
            for (int nf = 0; nf < 8; nf++) {
                const float a0 = fmaf(s[nf][0], EXPC, lc[0]);
                const float a1 = fmaf(s[nf][1], EXPC, lc[1]);
                const float a2 = fmaf(s[nf][2], EXPC, lc[0]);
                const float a3 = fmaf(s[nf][3], EXPC, lc[1]);
                const int j = nf >> 1, odd = nf & 1;
                pfh[j][2*odd]   = ex2_h2(pack_h2(a0, a1));
                pfh[j][2*odd+1] = ex2_h2(pack_h2(a2, a3));
            }
        } else {
            #pragma unroll
            for (int nf = 0; nf < 8; nf++) {
                const int kk = jt*64 + nf*8 + tq2;
                float mk[4], aa[4];
                #pragma unroll
                for (int e = 0; e < 4; e++) {
                    const int qq = q0 + (e >> 1) * 8;
                    const int kc = kk + (e & 1);
                    const int rel = qq - kc;
                    float m = 0.f;
                    if (rel >= 0) {
                        float clip = fminf(fmaxf((c1 - (float)rel) * 0.03125f, 0.f), 1.f);
                        m = clip * (sw0 + (((rel & 1) == 0) ? sw1 : 0.f));
                    }
                    mk[e] = m;
                    aa[e] = s[nf][e] * EXPC;
                }
                const int j = nf >> 1, odd = nf & 1;
                pfh[j][2*odd]   = hmul2(ex2_h2(pack_h2(aa[0], aa[1])), pack_h2(mk[0], mk[1]));
                pfh[j][2*odd+1] = hmul2(ex2_h2(pack_h2(aa[2], aa[3])), pack_h2(mk[2], mk[3]));
            }
        }

        // ---- rowsum via ones-mma (every thread gets full row sums) ----
        #pragma unroll
        for (int ks = 0; ks < 4; ks++)
            mma_f32acc(rsacc, pfh[ks], ONES2, ONES2);

        // ---- Y += P V ----
        #pragma unroll
        for (int ks = 0; ks < 4; ks++) {
            #pragma unroll
            for (int dnp = 0; dnp < 4; dnp++) {
                uint32_t vh[4];
                ldsm_x4t(vh, smem_u32(Vh + (ks*16 + vb_row)*ASQ + dnp*16 + vb_coff));
                #pragma unroll
                for (int half = 0; half < 2; half++)
                    mma_f32acc(accy[dnp*2 + half], pfh[ks], vh[2*half], vh[2*half+1]);
            }
        }
    }

    const float inv0 = 1.f / rsacc[0], inv1 = 1.f / rsacc[2];

    const size_t row0 = (size_t)(b*TT + q0);
    #pragma unroll
    for (int df = 0; df < 8; df++) {
        const int col = h*THD + df*8 + tq2;
        #pragma unroll
        for (int rr = 0; rr < 2; rr++) {
            const float inv = rr ? inv1 : inv0;
            const size_t off = (row0 + 8*rr) * TC + col;
            *(uint32_t*)(yhi + off) =
                pack_h2(accy[df][2*rr] * inv, accy[df][2*rr+1] * inv);
        }
    }
}

extern "C" void kernel_launch(void* const* d_in, const int* in_sizes, int n_in,
                              void* d_out, int out_size)
{
    const float* x    = (const float*)d_in[0];
    const float* Wqkv = (const float*)d_in[1];
    const float* Wpr  = (const float*)d_in[2];
    const float* span = (const float*)d_in[3];
    const float* strd = (const float*)d_in[4];
    float* out = (float*)d_out;

    __half *qkvhi, *xhi, *wqh, *wph, *yhi;
    cudaGetSymbolAddress((void**)&qkvhi, g_qkvhi);
    cudaGetSymbolAddress((void**)&xhi, g_xhi);
    cudaGetSymbolAddress((void**)&wqh, g_wqkv_hi);
    cudaGetSymbolAddress((void**)&wph, g_wpr_hi);
    cudaGetSymbolAddress((void**)&yhi, g_yhi);

    static bool attr_set = false;
    if (!attr_set) {
        cudaFuncSetAttribute(gemm_mma, cudaFuncAttributeMaxDynamicSharedMemorySize, GEMM_SMEM);
        cudaFuncSetAttribute(attn_mma, cudaFuncAttributeMaxDynamicSharedMemorySize, ATTN_SMEM);
        attr_set = true;
    }

    // 0) fused prep: x -> fp16 hi, W transposes, span_loss scalar
    prep_kernel<<<NCONV + NTRX * (TC/32), 256>>>(
        (const float4*)x, (__half2*)xhi, Wqkv, wqh, Wpr, wph, span, out, out_size);

    // 1) qkv = x @ Wqkv -> fp16 hi
    gemm_mma<<<dim3(N3C/64, MR/128), 256, GEMM_SMEM>>>(xhi, wqh,
        nullptr, qkvhi, 1, MR, N3C, TC);

    // 2) tensor-core flash attention (Q-tile 128) -> yhi
    attn_mma<<<dim3(TT/128, TH, TB), 256, ATTN_SMEM>>>(qkvhi, span, strd, yhi);

    // 3) y = yatt @ Wproj -> d_out (fp32)
    gemm_mma<<<dim3(TC/64, MR/128), 256, GEMM_SMEM>>>(yhi, wph,
        out, nullptr, 0, MR, TC, TC);
}